// round 8
// baseline (speedup 1.0000x reference)
#include <cuda_runtime.h>
#include <math.h>
#include <stdint.h>

// ---------------- problem constants ----------------
#define B_    4
#define S_    256
#define BS_   1024          // B*S
#define NN    500           // nodes
#define NPAD  512
#define FF    32
#define DD    64
#define GDCOL 65536         // BS_*DD
#define I3D   192
#define KIN   32000
#define SPLITK 25
#define KCH_L  1280         // 32000/25

// ---------------- device scratch (static zero-init; pads never written) ----------------
__device__ __align__(16) float g_X[(size_t)NPAD * BS_ * DD];
__device__ __align__(16) float g_Y[(size_t)NPAD * BS_ * DD];
__device__ __align__(16) float g_flat[(size_t)BS_ * KIN];
__device__ __align__(16) float g_adjT[NPAD * NPAD];
__device__ __align__(16) float g_part_l[SPLITK * BS_ * I3D];
__device__ __align__(16) float g_part_m[SPLITK * 80 * I3D];
__device__ __align__(16) float g_part_s[SPLITK * 40 * I3D];
__device__ __align__(16) float g_xp_l[BS_ * I3D];
__device__ __align__(16) float g_xp_m[80 * I3D];
__device__ __align__(16) float g_xp_s[40 * I3D];
__device__ __align__(16) float g_hcat[4 * I3D];

__device__ __forceinline__ float gelu_f(float x) {
    return 0.5f * x * (1.0f + erff(x * 0.7071067811865476f));
}
__device__ __forceinline__ float sigm_f(float x) {
    return 1.0f / (1.0f + expf(-x));
}

// tf32 split helpers
__device__ __forceinline__ uint32_t to_tf32(float v) {
    uint32_t r;
    asm("cvt.rna.tf32.f32 %0, %1;" : "=r"(r) : "f"(v));
    return r;
}
__device__ __forceinline__ void split_tf32(float v, float& hi, float& lo) {
    uint32_t h = to_tf32(v);
    hi = __uint_as_float(h);
    lo = __uint_as_float(to_tf32(v - hi));
}
__device__ __forceinline__ void mma_tf32(float* c, const uint32_t* a, const uint32_t* b) {
    asm volatile(
        "mma.sync.aligned.m16n8k8.row.col.f32.tf32.tf32.f32 "
        "{%0,%1,%2,%3}, {%4,%5,%6,%7}, {%8,%9}, {%0,%1,%2,%3};"
        : "+f"(c[0]), "+f"(c[1]), "+f"(c[2]), "+f"(c[3])
        : "r"(a[0]), "r"(a[1]), "r"(a[2]), "r"(a[3]), "r"(b[0]), "r"(b[1]));
}

// =====================================================================
// 1) input projection: X[n][bs][d] = gelu(sum_f x[bs][n][f]*ipW[d][f] + b[d])
// =====================================================================
__global__ __launch_bounds__(256) void k_input_proj(
    const float* __restrict__ x, const float* __restrict__ ipW, const float* __restrict__ ipb)
{
    __shared__ float Wt[FF][DD];   // Wt[f][d]
    __shared__ float sb[DD];
    int tid = threadIdx.x;
    for (int q = tid; q < FF * DD; q += 256) {
        int d = q >> 5, f = q & 31;          // ipW row-major [d][f]
        Wt[f][d] = ipW[q];
    }
    if (tid < DD) sb[tid] = ipb[tid];
    __syncthreads();
    int warp = tid >> 5, lane = tid & 31;
    for (int it = 0; it < 16; it++) {
        int row = (blockIdx.x * 16 + it) * 8 + warp;   // row = bs*500+n, < 512000
        float xv = x[(size_t)row * FF + lane];
        float a0 = sb[lane], a1 = sb[lane + 32];
#pragma unroll
        for (int f = 0; f < FF; f++) {
            float xf = __shfl_sync(0xffffffffu, xv, f);
            a0 += xf * Wt[f][lane];
            a1 += xf * Wt[f][lane + 32];
        }
        int bs = row / NN, n = row - bs * NN;
        size_t base = ((size_t)n * BS_ + bs) * DD;
        g_X[base + lane]      = gelu_f(a0);
        g_X[base + lane + 32] = gelu_f(a1);
    }
}

// =====================================================================
// 2) adjacency: adjT[m][n] = softmax_over_m((from[n].to[m]) * 2)
// =====================================================================
__global__ __launch_bounds__(256) void k_adj(
    const float* __restrict__ fe, const float* __restrict__ te)
{
    __shared__ float fl[32];
    __shared__ float lg[NN];
    __shared__ float redm[8], reds[8];
    int n = blockIdx.x, tid = threadIdx.x;
    int lane = tid & 31, warp = tid >> 5;
    if (tid < 32) fl[tid] = fe[n * 32 + tid];
    __syncthreads();

    float lmax = -1e30f;
    for (int m = tid; m < NN; m += 256) {
        float s = 0.f;
#pragma unroll
        for (int f = 0; f < 32; f++) s += fl[f] * te[m * 32 + f];
        s *= 2.0f;
        lg[m] = s;
        lmax = fmaxf(lmax, s);
    }
#pragma unroll
    for (int o = 16; o; o >>= 1) lmax = fmaxf(lmax, __shfl_xor_sync(0xffffffffu, lmax, o));
    if (lane == 0) redm[warp] = lmax;
    __syncthreads();
    float mx = redm[0];
#pragma unroll
    for (int w = 1; w < 8; w++) mx = fmaxf(mx, redm[w]);

    float lsum = 0.f;
    for (int m = tid; m < NN; m += 256) {
        float e = expf(lg[m] - mx);
        lg[m] = e;
        lsum += e;
    }
#pragma unroll
    for (int o = 16; o; o >>= 1) lsum += __shfl_xor_sync(0xffffffffu, lsum, o);
    if (lane == 0) reds[warp] = lsum;
    __syncthreads();
    float tot = 0.f;
#pragma unroll
    for (int w = 0; w < 8; w++) tot += reds[w];
    float inv = 1.0f / tot;
    for (int m = tid; m < NPAD; m += 256)
        g_adjT[m * NPAD + n] = (m < NN) ? lg[m] * inv : 0.f;
}

// =====================================================================
// 3) FUSED layer kernel:
//    u = adjT @ src + src            (tf32 3-split mma mainloop)
//    out = LN(gelu(u @ W^T + b))*g+be  (epilogue, smem-staged, mma)
//    layer 0: src=g_X, dst=g_Y (rows<500); layer 1: src=g_Y, dst=g_flat scatter
//    CTA 128x128x16; grid (4, 512) m-fastest for L2 B-reuse.
//    dynamic smem: pool(8704f: mainloop Ah/Al/Bh/Bl, aliased by US[64][136])
//                  + WH(4160f) + WL(4160f) + sb/sg/sbe(192f) = 68864 B
// =====================================================================
__global__ __launch_bounds__(256) void k_agg_token_tc(
    const float* __restrict__ W, const float* __restrict__ bvec,
    const float* __restrict__ gvec, const float* __restrict__ bevec,
    int layer)
{
    extern __shared__ float sm[];
    float* pAh = sm;                 // [16][136]
    float* pAl = sm + 2176;
    float* pBh = sm + 4352;
    float* pBl = sm + 6528;
    float* US  = sm;                 // alias of pool, [64][136], used post-mainloop
    float* WH  = sm + 8704;          // [64][65]
    float* WL  = sm + 12864;
    float* sb  = sm + 17024;
    float* sg  = sm + 17088;
    float* sbe = sm + 17152;

    int tid = threadIdx.x;
    int m0 = blockIdx.x * 128, n0 = blockIdx.y * 128;
    int wid = tid >> 5, lane = tid & 31;
    int g = lane >> 2, tig = lane & 3;
    int wm = (wid & 1) * 64, wn = (wid >> 1) * 32;

    // load + split W (row-major [e][d] -> WH/WL[d][e]) and LN params
    for (int q = tid; q < 4096; q += 256) {
        int e = q >> 6, d = q & 63;
        float h, l;
        split_tf32(W[q], h, l);
        WH[d * 65 + e] = h; WL[d * 65 + e] = l;
    }
    if (tid < 64) { sb[tid] = bvec[tid]; sg[tid] = gvec[tid]; sbe[tid] = bevec[tid]; }

    int a_r = tid >> 1,  a_kc = (tid & 1) * 4;
    int b_k = tid >> 4,  b_c = (tid & 15) * 4;

    float acc[4][4][4];
#pragma unroll
    for (int mt = 0; mt < 4; mt++)
#pragma unroll
        for (int nt = 0; nt < 4; nt++)
#pragma unroll
            for (int r = 0; r < 4; r++) acc[mt][nt][r] = 0.f;

    const float* A  = g_adjT;
    const float* Bm = layer ? g_Y : g_X;

    float4 aR0 = *(const float4*)&A[(m0 + a_r) * NPAD + a_kc];
    float4 aR1 = *(const float4*)&A[(m0 + a_r) * NPAD + a_kc + 8];
    float4 bR0 = *(const float4*)&Bm[(size_t)b_k * GDCOL + n0 + b_c];
    float4 bR1 = *(const float4*)&Bm[(size_t)b_k * GDCOL + n0 + b_c + 64];

    __syncthreads();   // W/bias loads complete before pool-area writes? (pool disjoint from WH; barrier orders W for epilogue and pool stores below)

    for (int kt = 0; kt < 32; kt++) {
        {
            float av[8] = {aR0.x, aR0.y, aR0.z, aR0.w, aR1.x, aR1.y, aR1.z, aR1.w};
#pragma unroll
            for (int i = 0; i < 4; i++) {
                float h, l;
                split_tf32(av[i], h, l);
                pAh[(a_kc + i) * 136 + a_r] = h; pAl[(a_kc + i) * 136 + a_r] = l;
                split_tf32(av[4 + i], h, l);
                pAh[(a_kc + 8 + i) * 136 + a_r] = h; pAl[(a_kc + 8 + i) * 136 + a_r] = l;
            }
            float4 h4, l4;
            split_tf32(bR0.x, h4.x, l4.x); split_tf32(bR0.y, h4.y, l4.y);
            split_tf32(bR0.z, h4.z, l4.z); split_tf32(bR0.w, h4.w, l4.w);
            *(float4*)&pBh[b_k * 136 + b_c] = h4; *(float4*)&pBl[b_k * 136 + b_c] = l4;
            split_tf32(bR1.x, h4.x, l4.x); split_tf32(bR1.y, h4.y, l4.y);
            split_tf32(bR1.z, h4.z, l4.z); split_tf32(bR1.w, h4.w, l4.w);
            *(float4*)&pBh[b_k * 136 + b_c + 64] = h4; *(float4*)&pBl[b_k * 136 + b_c + 64] = l4;
        }
        __syncthreads();

        if (kt + 1 < 32) {
            int k0 = (kt + 1) * 16;
            aR0 = *(const float4*)&A[(m0 + a_r) * NPAD + k0 + a_kc];
            aR1 = *(const float4*)&A[(m0 + a_r) * NPAD + k0 + a_kc + 8];
            bR0 = *(const float4*)&Bm[(size_t)(k0 + b_k) * GDCOL + n0 + b_c];
            bR1 = *(const float4*)&Bm[(size_t)(k0 + b_k) * GDCOL + n0 + b_c + 64];
        }

#pragma unroll
        for (int s = 0; s < 2; s++) {
            int kk = s * 8;
            uint32_t ah[4][4], al[4][4];
#pragma unroll
            for (int mt = 0; mt < 4; mt++) {
                int mrow = wm + mt * 16 + g;
                ah[mt][0] = __float_as_uint(pAh[(kk + tig) * 136 + mrow]);
                ah[mt][1] = __float_as_uint(pAh[(kk + tig) * 136 + mrow + 8]);
                ah[mt][2] = __float_as_uint(pAh[(kk + tig + 4) * 136 + mrow]);
                ah[mt][3] = __float_as_uint(pAh[(kk + tig + 4) * 136 + mrow + 8]);
                al[mt][0] = __float_as_uint(pAl[(kk + tig) * 136 + mrow]);
                al[mt][1] = __float_as_uint(pAl[(kk + tig) * 136 + mrow + 8]);
                al[mt][2] = __float_as_uint(pAl[(kk + tig + 4) * 136 + mrow]);
                al[mt][3] = __float_as_uint(pAl[(kk + tig + 4) * 136 + mrow + 8]);
            }
            uint32_t bh[4][2], bl[4][2];
#pragma unroll
            for (int nt = 0; nt < 4; nt++) {
                int ncol = wn + nt * 8 + g;
                bh[nt][0] = __float_as_uint(pBh[(kk + tig) * 136 + ncol]);
                bh[nt][1] = __float_as_uint(pBh[(kk + tig + 4) * 136 + ncol]);
                bl[nt][0] = __float_as_uint(pBl[(kk + tig) * 136 + ncol]);
                bl[nt][1] = __float_as_uint(pBl[(kk + tig + 4) * 136 + ncol]);
            }
#pragma unroll
            for (int mt = 0; mt < 4; mt++)
#pragma unroll
                for (int nt = 0; nt < 4; nt++) {
                    mma_tf32(acc[mt][nt], ah[mt], bh[nt]);
                    mma_tf32(acc[mt][nt], ah[mt], bl[nt]);
                    mma_tf32(acc[mt][nt], al[mt], bh[nt]);
                }
        }
        __syncthreads();
    }

    // ------------- fused epilogue: two 64-row phases -------------
    for (int p = 0; p < 2; p++) {
        // stage u = agg + residual into US[64][136] (feature offset cg*68)
        if ((wid & 1) == p) {
#pragma unroll
            for (int mt = 0; mt < 4; mt++) {
#pragma unroll
                for (int nt = 0; nt < 4; nt++) {
                    int lr = mt * 16 + g;
                    int lcol = wn + nt * 8 + tig * 2;
                    int cg = lcol >> 6, d = lcol & 63;
                    int grow = m0 + p * 64 + lr;
                    size_t gi0 = (size_t)grow * GDCOL + n0 + lcol;
                    size_t gi1 = (size_t)(grow + 8) * GDCOL + n0 + lcol;
                    float2 x0 = *(const float2*)&Bm[gi0];
                    float2 x1 = *(const float2*)&Bm[gi1];
                    *(float2*)&US[lr * 136 + cg * 68 + d] =
                        make_float2(acc[mt][nt][0] + x0.x, acc[mt][nt][1] + x0.y);
                    *(float2*)&US[(lr + 8) * 136 + cg * 68 + d] =
                        make_float2(acc[mt][nt][2] + x1.x, acc[mt][nt][3] + x1.y);
                }
            }
        }
        __syncthreads();

        // transform: warp wid handles tokens wid*16 .. wid*16+15 of this phase
        // token i: lr = wid*8 + (i>>1), cg = i&1. mma A row i=g -> token g; i=g+8 -> token g+8.
        {
            int base0 = ((wid << 3) + (g >> 1)) * 136 + (g & 1) * 68;
            int base1 = base0 + 4 * 136;

            float araw[8][4];
#pragma unroll
            for (int kk = 0; kk < 8; kk++) {
                araw[kk][0] = US[base0 + kk * 8 + tig];
                araw[kk][1] = US[base1 + kk * 8 + tig];
                araw[kk][2] = US[base0 + kk * 8 + tig + 4];
                araw[kk][3] = US[base1 + kk * 8 + tig + 4];
            }

            float tacc[8][4];
#pragma unroll
            for (int nt = 0; nt < 8; nt++)
#pragma unroll
                for (int r = 0; r < 4; r++) tacc[nt][r] = 0.f;

#pragma unroll
            for (int kk = 0; kk < 8; kk++) {
                uint32_t ah[4], al[4];
#pragma unroll
                for (int r = 0; r < 4; r++) {
                    float h, l;
                    split_tf32(araw[kk][r], h, l);
                    ah[r] = __float_as_uint(h); al[r] = __float_as_uint(l);
                }
                int k0 = (kk * 8 + tig) * 65, k1 = (kk * 8 + tig + 4) * 65;
#pragma unroll
                for (int nt = 0; nt < 8; nt++) {
                    int e = nt * 8 + g;
                    uint32_t bh[2], bl[2];
                    bh[0] = __float_as_uint(WH[k0 + e]);
                    bh[1] = __float_as_uint(WH[k1 + e]);
                    bl[0] = __float_as_uint(WL[k0 + e]);
                    bl[1] = __float_as_uint(WL[k1 + e]);
                    mma_tf32(tacc[nt], ah, bh);
                    mma_tf32(tacc[nt], ah, bl);
                    mma_tf32(tacc[nt], al, bh);
                }
            }

            // bias + gelu
#pragma unroll
            for (int nt = 0; nt < 8; nt++) {
                float bbx = sb[nt * 8 + 2 * tig], bby = sb[nt * 8 + 2 * tig + 1];
                tacc[nt][0] = gelu_f(tacc[nt][0] + bbx);
                tacc[nt][1] = gelu_f(tacc[nt][1] + bby);
                tacc[nt][2] = gelu_f(tacc[nt][2] + bbx);
                tacc[nt][3] = gelu_f(tacc[nt][3] + bby);
            }

            // LN across quad lanes
            float s0 = 0.f, s1 = 0.f;
#pragma unroll
            for (int nt = 0; nt < 8; nt++) { s0 += tacc[nt][0] + tacc[nt][1]; s1 += tacc[nt][2] + tacc[nt][3]; }
            s0 += __shfl_xor_sync(0xffffffffu, s0, 1); s0 += __shfl_xor_sync(0xffffffffu, s0, 2);
            s1 += __shfl_xor_sync(0xffffffffu, s1, 1); s1 += __shfl_xor_sync(0xffffffffu, s1, 2);
            float mu0 = s0 * (1.0f / 64.0f), mu1 = s1 * (1.0f / 64.0f);
            float v0 = 0.f, v1 = 0.f;
#pragma unroll
            for (int nt = 0; nt < 8; nt++) {
                float d0 = tacc[nt][0] - mu0, d1 = tacc[nt][1] - mu0;
                float d2 = tacc[nt][2] - mu1, d3 = tacc[nt][3] - mu1;
                v0 += d0 * d0 + d1 * d1; v1 += d2 * d2 + d3 * d3;
            }
            v0 += __shfl_xor_sync(0xffffffffu, v0, 1); v0 += __shfl_xor_sync(0xffffffffu, v0, 2);
            v1 += __shfl_xor_sync(0xffffffffu, v1, 1); v1 += __shfl_xor_sync(0xffffffffu, v1, 2);
            float inv0 = rsqrtf(v0 * (1.0f / 64.0f) + 1e-5f);
            float inv1 = rsqrtf(v1 * (1.0f / 64.0f) + 1e-5f);

            int grow0 = m0 + p * 64 + (wid << 3) + (g >> 1);
            int grow1 = grow0 + 4;
            int bs = (n0 >> 6) + (g & 1);

            size_t ob0, ob1;
            float* dst;
            if (layer == 0) {
                dst = g_Y;
                ob0 = (size_t)grow0 * GDCOL + (size_t)bs * 64;
                ob1 = (size_t)grow1 * GDCOL + (size_t)bs * 64;
            } else {
                dst = g_flat;
                ob0 = (size_t)bs * KIN + (size_t)grow0 * 64;
                ob1 = (size_t)bs * KIN + (size_t)grow1 * 64;
            }
            if (grow0 < NN) {
#pragma unroll
                for (int nt = 0; nt < 8; nt++) {
                    int c = nt * 8 + 2 * tig;
                    *(float2*)&dst[ob0 + c] = make_float2(
                        (tacc[nt][0] - mu0) * inv0 * sg[c] + sbe[c],
                        (tacc[nt][1] - mu0) * inv0 * sg[c + 1] + sbe[c + 1]);
                }
            }
            if (grow1 < NN) {
#pragma unroll
                for (int nt = 0; nt < 8; nt++) {
                    int c = nt * 8 + 2 * tig;
                    *(float2*)&dst[ob1 + c] = make_float2(
                        (tacc[nt][2] - mu1) * inv1 * sg[c] + sbe[c],
                        (tacc[nt][3] - mu1) * inv1 * sg[c + 1] + sbe[c + 1]);
                }
            }
        }
        __syncthreads();   // US reads done before next phase overwrites
    }
}

// =====================================================================
// 5) GRU input projection (split-K FFMA GEMM) — unchanged
// =====================================================================
__global__ __launch_bounds__(256) void k_xp(
    const float* __restrict__ W, int T, int Mtot, int KCH, int sel)
{
    __shared__ float As[2][8][65];
    __shared__ float Bs[2][8][65];
    float* part = (sel == 0) ? g_part_l : (sel == 1) ? g_part_m : g_part_s;

    int tid = threadIdx.x;
    int m0 = blockIdx.x * 64;
    int n0 = blockIdx.y * 64;
    int z  = blockIdx.z;
    int kbase = z * KCH;

    int a_r = tid >> 2;
    int a_k = (tid & 3) * 2;
    int b_g = tid >> 2;
    int b_k = (tid & 3) * 2;
    int ty = tid >> 4, tx = tid & 15;

    int r = m0 + a_r;
    bool a_valid = (r < Mtot);
    const float* aptr = g_flat;
    if (a_valid) {
        int bb = r / T, tt = r - bb * T;
        int frow = bb * S_ + (S_ - T) + tt;
        aptr = g_flat + (size_t)frow * KIN;
    }
    const float* bptr = W + (size_t)(n0 + b_g) * KIN;

    float acc[4][4];
#pragma unroll
    for (int i = 0; i < 4; i++)
#pragma unroll
        for (int j = 0; j < 4; j++) acc[i][j] = 0.f;

    int NT = KCH / 8;
    float2 aReg = a_valid ? *(const float2*)(aptr + kbase + a_k) : make_float2(0.f, 0.f);
    float2 bReg = *(const float2*)(bptr + kbase + b_k);
    As[0][a_k][a_r] = aReg.x; As[0][a_k + 1][a_r] = aReg.y;
    Bs[0][b_k][b_g] = bReg.x; Bs[0][b_k + 1][b_g] = bReg.y;
    __syncthreads();

    for (int kt = 0; kt < NT; kt++) {
        int cur = kt & 1, nxt = cur ^ 1;
        if (kt + 1 < NT) {
            int k0 = kbase + (kt + 1) * 8;
            aReg = a_valid ? *(const float2*)(aptr + k0 + a_k) : make_float2(0.f, 0.f);
            bReg = *(const float2*)(bptr + k0 + b_k);
        }
#pragma unroll
        for (int k = 0; k < 8; k++) {
            float af[4], bf[4];
#pragma unroll
            for (int i = 0; i < 4; i++) af[i] = As[cur][k][ty * 4 + i];
#pragma unroll
            for (int j = 0; j < 4; j++) bf[j] = Bs[cur][k][tx * 4 + j];
#pragma unroll
            for (int i = 0; i < 4; i++)
#pragma unroll
                for (int j = 0; j < 4; j++)
                    acc[i][j] += af[i] * bf[j];
        }
        if (kt + 1 < NT) {
            As[nxt][a_k][a_r] = aReg.x; As[nxt][a_k + 1][a_r] = aReg.y;
            Bs[nxt][b_k][b_g] = bReg.x; Bs[nxt][b_k + 1][b_g] = bReg.y;
        }
        __syncthreads();
    }

#pragma unroll
    for (int i = 0; i < 4; i++) {
        int rr = m0 + ty * 4 + i;
        if (rr < Mtot) {
#pragma unroll
            for (int j = 0; j < 4; j++) {
                int gg = n0 + tx * 4 + j;
                part[((size_t)z * Mtot + rr) * I3D + gg] = acc[i][j];
            }
        }
    }
}

__global__ void k_xp_reduce(const float* __restrict__ bih, int Mtot, int sel)
{
    const float* part = (sel == 0) ? g_part_l : (sel == 1) ? g_part_m : g_part_s;
    float* out = (sel == 0) ? g_xp_l : (sel == 1) ? g_xp_m : g_xp_s;
    int i = blockIdx.x * 256 + threadIdx.x;
    int tot = Mtot * I3D;
    if (i >= tot) return;
    int g = i % I3D;
    float s = bih[g];
    for (int z = 0; z < SPLITK; z++) s += part[(size_t)z * tot + i];
    out[i] = s;
}

// =====================================================================
// 6) GRU recurrence — unchanged
// =====================================================================
__global__ __launch_bounds__(192) void k_gru(
    const float* __restrict__ Whh_s, const float* __restrict__ bhh_s,
    const float* __restrict__ Whh_m, const float* __restrict__ bhh_m,
    const float* __restrict__ Whh_l, const float* __restrict__ bhh_l)
{
    int blk = blockIdx.x;
    int gru = blk >> 2;
    int b = blk & 3;
    int T = (gru == 0) ? 10 : (gru == 1) ? 20 : 256;
    const float* xp  = (gru == 0) ? g_xp_s : (gru == 1) ? g_xp_m : g_xp_l;
    const float* Whh = (gru == 0) ? Whh_s : (gru == 1) ? Whh_m : Whh_l;
    const float* bhh = (gru == 0) ? bhh_s : (gru == 1) ? bhh_m : bhh_l;
    int g = threadIdx.x;

    float w[64];
#pragma unroll
    for (int d = 0; d < 64; d += 4) {
        float4 v = *(const float4*)&Whh[g * 64 + d];
        w[d] = v.x; w[d + 1] = v.y; w[d + 2] = v.z; w[d + 3] = v.w;
    }
    float bh = bhh[g];

    __shared__ float h_sh[64], r_sh[64], z_sh[64], n_sh[64];
    if (g < 64) h_sh[g] = 0.f;
    __syncthreads();

    const float* xpb = xp + (size_t)b * T * I3D;
    for (int t = 0; t < T; t++) {
        float a0 = 0.f, a1 = 0.f, a2 = 0.f, a3 = 0.f;
#pragma unroll
        for (int d = 0; d < 64; d += 4) {
            a0 += w[d]     * h_sh[d];
            a1 += w[d + 1] * h_sh[d + 1];
            a2 += w[d + 2] * h_sh[d + 2];
            a3 += w[d + 3] * h_sh[d + 3];
        }
        float gh = bh + ((a0 + a1) + (a2 + a3));
        float xv = xpb[t * I3D + g];
        if (g < 64) {
            r_sh[g] = sigm_f(xv + gh);
        } else if (g < 128) {
            z_sh[g - 64] = sigm_f(xv + gh);
        }
        __syncthreads();
        if (g >= 128) {
            n_sh[g - 128] = tanhf(xv + r_sh[g - 128] * gh);
        }
        __syncthreads();
        if (g < 64) {
            float zz = z_sh[g], nn = n_sh[g];
            h_sh[g] = (1.f - zz) * nn + zz * h_sh[g];
        }
        __syncthreads();
    }
    if (g < 64) g_hcat[b * I3D + gru * 64 + g] = h_sh[g];
}

// =====================================================================
// 7) head — unchanged
// =====================================================================
__global__ __launch_bounds__(256) void k_head(
    const float* __restrict__ W1, const float* __restrict__ b1,
    const float* __restrict__ W2, const float* __restrict__ b2,
    float* __restrict__ out)
{
    __shared__ float hc[4 * I3D];
    __shared__ float h1[4 * 64];
    int t = threadIdx.x;
    for (int i = t; i < 4 * I3D; i += 256) hc[i] = g_hcat[i];
    __syncthreads();
    {
        int b = t >> 6, e = t & 63;
        float a = b1[e];
#pragma unroll 8
        for (int gg = 0; gg < I3D; gg++) a += hc[b * I3D + gg] * W1[e * I3D + gg];
        h1[b * 64 + e] = gelu_f(a);
    }
    __syncthreads();
    for (int q = t; q < 4 * NN; q += 256) {
        int b = q / NN, n = q - b * NN;
        float a = b2[n];
#pragma unroll 8
        for (int e = 0; e < 64; e++) a += h1[b * 64 + e] * W2[n * 64 + e];
        out[b * NN + n] = a;
    }
}

// =====================================================================
// launcher
// =====================================================================
extern "C" void kernel_launch(void* const* d_in, const int* in_sizes, int n_in,
                              void* d_out, int out_size)
{
    const float* x     = (const float*)d_in[0];
    const float* ipW   = (const float*)d_in[1];
    const float* ipb   = (const float*)d_in[2];
    const float* fe    = (const float*)d_in[3];
    const float* te    = (const float*)d_in[4];
    const float* glW   = (const float*)d_in[5];
    const float* glb   = (const float*)d_in[6];
    const float* glg   = (const float*)d_in[7];
    const float* glbe  = (const float*)d_in[8];
    const float* Wih_s = (const float*)d_in[9];
    const float* Whh_s = (const float*)d_in[10];
    const float* bih_s = (const float*)d_in[11];
    const float* bhh_s = (const float*)d_in[12];
    const float* Wih_m = (const float*)d_in[13];
    const float* Whh_m = (const float*)d_in[14];
    const float* bih_m = (const float*)d_in[15];
    const float* bhh_m = (const float*)d_in[16];
    const float* Wih_l = (const float*)d_in[17];
    const float* Whh_l = (const float*)d_in[18];
    const float* bih_l = (const float*)d_in[19];
    const float* bhh_l = (const float*)d_in[20];
    const float* dhW1  = (const float*)d_in[21];
    const float* dhb1  = (const float*)d_in[22];
    const float* dhW2  = (const float*)d_in[23];
    const float* dhb2  = (const float*)d_in[24];
    float* out = (float*)d_out;

    const int FUSED_SMEM = 17216 * 4;   // 68864 bytes
    cudaFuncSetAttribute(k_agg_token_tc,
                         cudaFuncAttributeMaxDynamicSharedMemorySize, FUSED_SMEM);

    k_input_proj<<<4000, 256>>>(x, ipW, ipb);
    k_adj<<<NN, 256>>>(fe, te);

    // layer 0: src g_X -> dst g_Y
    k_agg_token_tc<<<dim3(4, GDCOL / 128), 256, FUSED_SMEM>>>(glW, glb, glg, glbe, 0);
    // layer 1: src g_Y -> dst g_flat (scatter)
    k_agg_token_tc<<<dim3(4, GDCOL / 128), 256, FUSED_SMEM>>>(glW + 4096, glb + 64, glg + 64, glbe + 64, 1);

    // GRU input projections (split-K)
    k_xp<<<dim3(16, 3, SPLITK), 256>>>(Wih_l, 256, 1024, KCH_L, 0);
    k_xp<<<dim3(2, 3, SPLITK), 256>>>(Wih_m, 20, 80, KCH_L, 1);
    k_xp<<<dim3(1, 3, SPLITK), 256>>>(Wih_s, 10, 40, KCH_L, 2);
    k_xp_reduce<<<(1024 * I3D + 255) / 256, 256>>>(bih_l, 1024, 0);
    k_xp_reduce<<<(80 * I3D + 255) / 256, 256>>>(bih_m, 80, 1);
    k_xp_reduce<<<(40 * I3D + 255) / 256, 256>>>(bih_s, 40, 2);

    k_gru<<<12, 192>>>(Whh_s, bhh_s, Whh_m, bhh_m, Whh_l, bhh_l);
    k_head<<<1, 256>>>(dhW1, dhb1, dhW2, dhb2, out);
}

// round 10
// speedup vs baseline: 1.1109x; 1.1109x over previous
#include <cuda_runtime.h>
#include <math.h>
#include <stdint.h>

// ---------------- problem constants ----------------
#define B_    4
#define S_    256
#define BS_   1024          // B*S
#define NN    500           // nodes
#define NPAD  512
#define FF    32
#define DD    64
#define GDCOL 65536         // BS_*DD
#define I3D   192
#define KIN   32000
#define SPLITK 25
#define KCH_L  1280         // 32000/25

// ---------------- device scratch (static zero-init; pads never written) ----------------
__device__ __align__(16) float g_X[(size_t)NPAD * BS_ * DD];
__device__ __align__(16) float g_Y[(size_t)NPAD * BS_ * DD];
__device__ __align__(16) float g_flat[(size_t)BS_ * KIN];
__device__ __align__(16) float g_adjT[NPAD * NPAD];
__device__ __align__(16) float g_part_l[SPLITK * BS_ * I3D];
__device__ __align__(16) float g_part_m[SPLITK * 80 * I3D];
__device__ __align__(16) float g_part_s[SPLITK * 40 * I3D];
__device__ __align__(16) float g_xp_l[BS_ * I3D];
__device__ __align__(16) float g_xp_m[80 * I3D];
__device__ __align__(16) float g_xp_s[40 * I3D];
__device__ __align__(16) float g_hcat[4 * I3D];

__device__ __forceinline__ float gelu_f(float x) {
    return 0.5f * x * (1.0f + erff(x * 0.7071067811865476f));
}
__device__ __forceinline__ float sigm_f(float x) {
    return 1.0f / (1.0f + expf(-x));
}

// tf32 split helpers
__device__ __forceinline__ uint32_t to_tf32(float v) {
    uint32_t r;
    asm("cvt.rna.tf32.f32 %0, %1;" : "=r"(r) : "f"(v));
    return r;
}
__device__ __forceinline__ void split_tf32(float v, float& hi, float& lo) {
    uint32_t h = to_tf32(v);
    hi = __uint_as_float(h);
    lo = __uint_as_float(to_tf32(v - hi));
}
__device__ __forceinline__ void mma_tf32(float* c, const uint32_t* a, const uint32_t* b) {
    asm volatile(
        "mma.sync.aligned.m16n8k8.row.col.f32.tf32.tf32.f32 "
        "{%0,%1,%2,%3}, {%4,%5,%6,%7}, {%8,%9}, {%0,%1,%2,%3};"
        : "+f"(c[0]), "+f"(c[1]), "+f"(c[2]), "+f"(c[3])
        : "r"(a[0]), "r"(a[1]), "r"(a[2]), "r"(a[3]), "r"(b[0]), "r"(b[1]));
}

// =====================================================================
// 1) input projection: X[n][bs][d] = gelu(sum_f x[bs][n][f]*ipW[d][f] + b[d])
// =====================================================================
__global__ __launch_bounds__(256) void k_input_proj(
    const float* __restrict__ x, const float* __restrict__ ipW, const float* __restrict__ ipb)
{
    __shared__ float Wt[FF][DD];   // Wt[f][d]
    __shared__ float sb[DD];
    int tid = threadIdx.x;
    for (int q = tid; q < FF * DD; q += 256) {
        int d = q >> 5, f = q & 31;          // ipW row-major [d][f]
        Wt[f][d] = ipW[q];
    }
    if (tid < DD) sb[tid] = ipb[tid];
    __syncthreads();
    int warp = tid >> 5, lane = tid & 31;
    for (int it = 0; it < 16; it++) {
        int row = (blockIdx.x * 16 + it) * 8 + warp;   // row = bs*500+n, < 512000
        float xv = x[(size_t)row * FF + lane];
        float a0 = sb[lane], a1 = sb[lane + 32];
#pragma unroll
        for (int f = 0; f < FF; f++) {
            float xf = __shfl_sync(0xffffffffu, xv, f);
            a0 += xf * Wt[f][lane];
            a1 += xf * Wt[f][lane + 32];
        }
        int bs = row / NN, n = row - bs * NN;
        size_t base = ((size_t)n * BS_ + bs) * DD;
        g_X[base + lane]      = gelu_f(a0);
        g_X[base + lane + 32] = gelu_f(a1);
    }
}

// =====================================================================
// 2) adjacency: adjT[m][n] = softmax_over_m((from[n].to[m]) * 2)
// =====================================================================
__global__ __launch_bounds__(256) void k_adj(
    const float* __restrict__ fe, const float* __restrict__ te)
{
    __shared__ float fl[32];
    __shared__ float lg[NN];
    __shared__ float redm[8], reds[8];
    int n = blockIdx.x, tid = threadIdx.x;
    int lane = tid & 31, warp = tid >> 5;
    if (tid < 32) fl[tid] = fe[n * 32 + tid];
    __syncthreads();

    float lmax = -1e30f;
    for (int m = tid; m < NN; m += 256) {
        float s = 0.f;
#pragma unroll
        for (int f = 0; f < 32; f++) s += fl[f] * te[m * 32 + f];
        s *= 2.0f;
        lg[m] = s;
        lmax = fmaxf(lmax, s);
    }
#pragma unroll
    for (int o = 16; o; o >>= 1) lmax = fmaxf(lmax, __shfl_xor_sync(0xffffffffu, lmax, o));
    if (lane == 0) redm[warp] = lmax;
    __syncthreads();
    float mx = redm[0];
#pragma unroll
    for (int w = 1; w < 8; w++) mx = fmaxf(mx, redm[w]);

    float lsum = 0.f;
    for (int m = tid; m < NN; m += 256) {
        float e = expf(lg[m] - mx);
        lg[m] = e;
        lsum += e;
    }
#pragma unroll
    for (int o = 16; o; o >>= 1) lsum += __shfl_xor_sync(0xffffffffu, lsum, o);
    if (lane == 0) reds[warp] = lsum;
    __syncthreads();
    float tot = 0.f;
#pragma unroll
    for (int w = 0; w < 8; w++) tot += reds[w];
    float inv = 1.0f / tot;
    for (int m = tid; m < NPAD; m += 256)
        g_adjT[m * NPAD + n] = (m < NN) ? lg[m] * inv : 0.f;
}

// =====================================================================
// 3) FUSED layer kernel (unchanged from R8)
// =====================================================================
__global__ __launch_bounds__(256) void k_agg_token_tc(
    const float* __restrict__ W, const float* __restrict__ bvec,
    const float* __restrict__ gvec, const float* __restrict__ bevec,
    int layer)
{
    extern __shared__ float sm[];
    float* pAh = sm;                 // [16][136]
    float* pAl = sm + 2176;
    float* pBh = sm + 4352;
    float* pBl = sm + 6528;
    float* US  = sm;                 // alias of pool, [64][136], used post-mainloop
    float* WH  = sm + 8704;          // [64][65]
    float* WL  = sm + 12864;
    float* sb  = sm + 17024;
    float* sg  = sm + 17088;
    float* sbe = sm + 17152;

    int tid = threadIdx.x;
    int m0 = blockIdx.x * 128, n0 = blockIdx.y * 128;
    int wid = tid >> 5, lane = tid & 31;
    int g = lane >> 2, tig = lane & 3;
    int wm = (wid & 1) * 64, wn = (wid >> 1) * 32;

    for (int q = tid; q < 4096; q += 256) {
        int e = q >> 6, d = q & 63;
        float h, l;
        split_tf32(W[q], h, l);
        WH[d * 65 + e] = h; WL[d * 65 + e] = l;
    }
    if (tid < 64) { sb[tid] = bvec[tid]; sg[tid] = gvec[tid]; sbe[tid] = bevec[tid]; }

    int a_r = tid >> 1,  a_kc = (tid & 1) * 4;
    int b_k = tid >> 4,  b_c = (tid & 15) * 4;

    float acc[4][4][4];
#pragma unroll
    for (int mt = 0; mt < 4; mt++)
#pragma unroll
        for (int nt = 0; nt < 4; nt++)
#pragma unroll
            for (int r = 0; r < 4; r++) acc[mt][nt][r] = 0.f;

    const float* A  = g_adjT;
    const float* Bm = layer ? g_Y : g_X;

    float4 aR0 = *(const float4*)&A[(m0 + a_r) * NPAD + a_kc];
    float4 aR1 = *(const float4*)&A[(m0 + a_r) * NPAD + a_kc + 8];
    float4 bR0 = *(const float4*)&Bm[(size_t)b_k * GDCOL + n0 + b_c];
    float4 bR1 = *(const float4*)&Bm[(size_t)b_k * GDCOL + n0 + b_c + 64];

    __syncthreads();

    for (int kt = 0; kt < 32; kt++) {
        {
            float av[8] = {aR0.x, aR0.y, aR0.z, aR0.w, aR1.x, aR1.y, aR1.z, aR1.w};
#pragma unroll
            for (int i = 0; i < 4; i++) {
                float h, l;
                split_tf32(av[i], h, l);
                pAh[(a_kc + i) * 136 + a_r] = h; pAl[(a_kc + i) * 136 + a_r] = l;
                split_tf32(av[4 + i], h, l);
                pAh[(a_kc + 8 + i) * 136 + a_r] = h; pAl[(a_kc + 8 + i) * 136 + a_r] = l;
            }
            float4 h4, l4;
            split_tf32(bR0.x, h4.x, l4.x); split_tf32(bR0.y, h4.y, l4.y);
            split_tf32(bR0.z, h4.z, l4.z); split_tf32(bR0.w, h4.w, l4.w);
            *(float4*)&pBh[b_k * 136 + b_c] = h4; *(float4*)&pBl[b_k * 136 + b_c] = l4;
            split_tf32(bR1.x, h4.x, l4.x); split_tf32(bR1.y, h4.y, l4.y);
            split_tf32(bR1.z, h4.z, l4.z); split_tf32(bR1.w, h4.w, l4.w);
            *(float4*)&pBh[b_k * 136 + b_c + 64] = h4; *(float4*)&pBl[b_k * 136 + b_c + 64] = l4;
        }
        __syncthreads();

        if (kt + 1 < 32) {
            int k0 = (kt + 1) * 16;
            aR0 = *(const float4*)&A[(m0 + a_r) * NPAD + k0 + a_kc];
            aR1 = *(const float4*)&A[(m0 + a_r) * NPAD + k0 + a_kc + 8];
            bR0 = *(const float4*)&Bm[(size_t)(k0 + b_k) * GDCOL + n0 + b_c];
            bR1 = *(const float4*)&Bm[(size_t)(k0 + b_k) * GDCOL + n0 + b_c + 64];
        }

#pragma unroll
        for (int s = 0; s < 2; s++) {
            int kk = s * 8;
            uint32_t ah[4][4], al[4][4];
#pragma unroll
            for (int mt = 0; mt < 4; mt++) {
                int mrow = wm + mt * 16 + g;
                ah[mt][0] = __float_as_uint(pAh[(kk + tig) * 136 + mrow]);
                ah[mt][1] = __float_as_uint(pAh[(kk + tig) * 136 + mrow + 8]);
                ah[mt][2] = __float_as_uint(pAh[(kk + tig + 4) * 136 + mrow]);
                ah[mt][3] = __float_as_uint(pAh[(kk + tig + 4) * 136 + mrow + 8]);
                al[mt][0] = __float_as_uint(pAl[(kk + tig) * 136 + mrow]);
                al[mt][1] = __float_as_uint(pAl[(kk + tig) * 136 + mrow + 8]);
                al[mt][2] = __float_as_uint(pAl[(kk + tig + 4) * 136 + mrow]);
                al[mt][3] = __float_as_uint(pAl[(kk + tig + 4) * 136 + mrow + 8]);
            }
            uint32_t bh[4][2], bl[4][2];
#pragma unroll
            for (int nt = 0; nt < 4; nt++) {
                int ncol = wn + nt * 8 + g;
                bh[nt][0] = __float_as_uint(pBh[(kk + tig) * 136 + ncol]);
                bh[nt][1] = __float_as_uint(pBh[(kk + tig + 4) * 136 + ncol]);
                bl[nt][0] = __float_as_uint(pBl[(kk + tig) * 136 + ncol]);
                bl[nt][1] = __float_as_uint(pBl[(kk + tig + 4) * 136 + ncol]);
            }
#pragma unroll
            for (int mt = 0; mt < 4; mt++)
#pragma unroll
                for (int nt = 0; nt < 4; nt++) {
                    mma_tf32(acc[mt][nt], ah[mt], bh[nt]);
                    mma_tf32(acc[mt][nt], ah[mt], bl[nt]);
                    mma_tf32(acc[mt][nt], al[mt], bh[nt]);
                }
        }
        __syncthreads();
    }

    // ------------- fused epilogue: two 64-row phases -------------
    for (int p = 0; p < 2; p++) {
        if ((wid & 1) == p) {
#pragma unroll
            for (int mt = 0; mt < 4; mt++) {
#pragma unroll
                for (int nt = 0; nt < 4; nt++) {
                    int lr = mt * 16 + g;
                    int lcol = wn + nt * 8 + tig * 2;
                    int cg = lcol >> 6, d = lcol & 63;
                    int grow = m0 + p * 64 + lr;
                    size_t gi0 = (size_t)grow * GDCOL + n0 + lcol;
                    size_t gi1 = (size_t)(grow + 8) * GDCOL + n0 + lcol;
                    float2 x0 = *(const float2*)&Bm[gi0];
                    float2 x1 = *(const float2*)&Bm[gi1];
                    *(float2*)&US[lr * 136 + cg * 68 + d] =
                        make_float2(acc[mt][nt][0] + x0.x, acc[mt][nt][1] + x0.y);
                    *(float2*)&US[(lr + 8) * 136 + cg * 68 + d] =
                        make_float2(acc[mt][nt][2] + x1.x, acc[mt][nt][3] + x1.y);
                }
            }
        }
        __syncthreads();

        {
            int base0 = ((wid << 3) + (g >> 1)) * 136 + (g & 1) * 68;
            int base1 = base0 + 4 * 136;

            float araw[8][4];
#pragma unroll
            for (int kk = 0; kk < 8; kk++) {
                araw[kk][0] = US[base0 + kk * 8 + tig];
                araw[kk][1] = US[base1 + kk * 8 + tig];
                araw[kk][2] = US[base0 + kk * 8 + tig + 4];
                araw[kk][3] = US[base1 + kk * 8 + tig + 4];
            }

            float tacc[8][4];
#pragma unroll
            for (int nt = 0; nt < 8; nt++)
#pragma unroll
                for (int r = 0; r < 4; r++) tacc[nt][r] = 0.f;

#pragma unroll
            for (int kk = 0; kk < 8; kk++) {
                uint32_t ah[4], al[4];
#pragma unroll
                for (int r = 0; r < 4; r++) {
                    float h, l;
                    split_tf32(araw[kk][r], h, l);
                    ah[r] = __float_as_uint(h); al[r] = __float_as_uint(l);
                }
                int k0 = (kk * 8 + tig) * 65, k1 = (kk * 8 + tig + 4) * 65;
#pragma unroll
                for (int nt = 0; nt < 8; nt++) {
                    int e = nt * 8 + g;
                    uint32_t bh[2], bl[2];
                    bh[0] = __float_as_uint(WH[k0 + e]);
                    bh[1] = __float_as_uint(WH[k1 + e]);
                    bl[0] = __float_as_uint(WL[k0 + e]);
                    bl[1] = __float_as_uint(WL[k1 + e]);
                    mma_tf32(tacc[nt], ah, bh);
                    mma_tf32(tacc[nt], ah, bl);
                    mma_tf32(tacc[nt], al, bh);
                }
            }

#pragma unroll
            for (int nt = 0; nt < 8; nt++) {
                float bbx = sb[nt * 8 + 2 * tig], bby = sb[nt * 8 + 2 * tig + 1];
                tacc[nt][0] = gelu_f(tacc[nt][0] + bbx);
                tacc[nt][1] = gelu_f(tacc[nt][1] + bby);
                tacc[nt][2] = gelu_f(tacc[nt][2] + bbx);
                tacc[nt][3] = gelu_f(tacc[nt][3] + bby);
            }

            float s0 = 0.f, s1 = 0.f;
#pragma unroll
            for (int nt = 0; nt < 8; nt++) { s0 += tacc[nt][0] + tacc[nt][1]; s1 += tacc[nt][2] + tacc[nt][3]; }
            s0 += __shfl_xor_sync(0xffffffffu, s0, 1); s0 += __shfl_xor_sync(0xffffffffu, s0, 2);
            s1 += __shfl_xor_sync(0xffffffffu, s1, 1); s1 += __shfl_xor_sync(0xffffffffu, s1, 2);
            float mu0 = s0 * (1.0f / 64.0f), mu1 = s1 * (1.0f / 64.0f);
            float v0 = 0.f, v1 = 0.f;
#pragma unroll
            for (int nt = 0; nt < 8; nt++) {
                float d0 = tacc[nt][0] - mu0, d1 = tacc[nt][1] - mu0;
                float d2 = tacc[nt][2] - mu1, d3 = tacc[nt][3] - mu1;
                v0 += d0 * d0 + d1 * d1; v1 += d2 * d2 + d3 * d3;
            }
            v0 += __shfl_xor_sync(0xffffffffu, v0, 1); v0 += __shfl_xor_sync(0xffffffffu, v0, 2);
            v1 += __shfl_xor_sync(0xffffffffu, v1, 1); v1 += __shfl_xor_sync(0xffffffffu, v1, 2);
            float inv0 = rsqrtf(v0 * (1.0f / 64.0f) + 1e-5f);
            float inv1 = rsqrtf(v1 * (1.0f / 64.0f) + 1e-5f);

            int grow0 = m0 + p * 64 + (wid << 3) + (g >> 1);
            int grow1 = grow0 + 4;
            int bs = (n0 >> 6) + (g & 1);

            size_t ob0, ob1;
            float* dst;
            if (layer == 0) {
                dst = g_Y;
                ob0 = (size_t)grow0 * GDCOL + (size_t)bs * 64;
                ob1 = (size_t)grow1 * GDCOL + (size_t)bs * 64;
            } else {
                dst = g_flat;
                ob0 = (size_t)bs * KIN + (size_t)grow0 * 64;
                ob1 = (size_t)bs * KIN + (size_t)grow1 * 64;
            }
            if (grow0 < NN) {
#pragma unroll
                for (int nt = 0; nt < 8; nt++) {
                    int c = nt * 8 + 2 * tig;
                    *(float2*)&dst[ob0 + c] = make_float2(
                        (tacc[nt][0] - mu0) * inv0 * sg[c] + sbe[c],
                        (tacc[nt][1] - mu0) * inv0 * sg[c + 1] + sbe[c + 1]);
                }
            }
            if (grow1 < NN) {
#pragma unroll
                for (int nt = 0; nt < 8; nt++) {
                    int c = nt * 8 + 2 * tig;
                    *(float2*)&dst[ob1 + c] = make_float2(
                        (tacc[nt][2] - mu1) * inv1 * sg[c] + sbe[c],
                        (tacc[nt][3] - mu1) * inv1 * sg[c + 1] + sbe[c + 1]);
                }
            }
        }
        __syncthreads();
    }
}

// =====================================================================
// 5) GRU input projection — tf32 3-split tensor-core GEMM, split-K.
//    part[z][r][gate] = sum_{k in chunk z} x_flat[row(r)][k] * Wih[gate][k]
//    CTA 64x64x16; 8 warps = 4 m x 2 n, warp tile 16x32.
//    Loader: 4 threads/row x float4 = full k 0..15 per tile (NO second-half load).
// =====================================================================
__global__ __launch_bounds__(256) void k_xp_tc(
    const float* __restrict__ W, int T, int Mtot, int sel)
{
    __shared__ float Ah[16][72], Al[16][72];
    __shared__ float Bh[16][72], Bl[16][72];
    float* part = (sel == 0) ? g_part_l : (sel == 1) ? g_part_m : g_part_s;

    int tid = threadIdx.x;
    int m0 = blockIdx.x * 64;
    int n0 = blockIdx.y * 64;
    int z  = blockIdx.z;
    int kbase = z * KCH_L;

    int wid = tid >> 5, lane = tid & 31;
    int g = lane >> 2, tig = lane & 3;
    int wm = (wid & 3) * 16, wn = (wid >> 2) * 32;

    int a_r = tid >> 2, a_k = (tid & 3) * 4;     // covers k 0..15 across tid&3
    int b_g = tid >> 2, b_k = (tid & 3) * 4;

    int r = m0 + a_r;
    bool a_valid = (r < Mtot);
    const float* aptr = g_flat;                   // only dereferenced if a_valid
    if (a_valid) {
        int bb = r / T, tt = r - bb * T;
        int frow = bb * S_ + (S_ - T) + tt;
        aptr = g_flat + (size_t)frow * KIN;
    }
    const float* bptr = W + (size_t)(n0 + b_g) * KIN;

    float acc[4][4];
#pragma unroll
    for (int nt = 0; nt < 4; nt++)
#pragma unroll
        for (int c = 0; c < 4; c++) acc[nt][c] = 0.f;

    const int NT = KCH_L / 16;    // 80
    float4 aReg = a_valid ? *(const float4*)(aptr + kbase + a_k) : make_float4(0.f, 0.f, 0.f, 0.f);
    float4 bReg = *(const float4*)(bptr + kbase + b_k);

    for (int kt = 0; kt < NT; kt++) {
        // split current tile into smem (full 16-k coverage from aReg/bReg alone)
        {
            float h, l;
            split_tf32(aReg.x, h, l); Ah[a_k + 0][a_r] = h; Al[a_k + 0][a_r] = l;
            split_tf32(aReg.y, h, l); Ah[a_k + 1][a_r] = h; Al[a_k + 1][a_r] = l;
            split_tf32(aReg.z, h, l); Ah[a_k + 2][a_r] = h; Al[a_k + 2][a_r] = l;
            split_tf32(aReg.w, h, l); Ah[a_k + 3][a_r] = h; Al[a_k + 3][a_r] = l;
            split_tf32(bReg.x, h, l); Bh[b_k + 0][b_g] = h; Bl[b_k + 0][b_g] = l;
            split_tf32(bReg.y, h, l); Bh[b_k + 1][b_g] = h; Bl[b_k + 1][b_g] = l;
            split_tf32(bReg.z, h, l); Bh[b_k + 2][b_g] = h; Bl[b_k + 2][b_g] = l;
            split_tf32(bReg.w, h, l); Bh[b_k + 3][b_g] = h; Bl[b_k + 3][b_g] = l;
        }
        __syncthreads();

        if (kt + 1 < NT) {
            int k0 = kbase + (kt + 1) * 16;
            aReg = a_valid ? *(const float4*)(aptr + k0 + a_k) : make_float4(0.f, 0.f, 0.f, 0.f);
            bReg = *(const float4*)(bptr + k0 + b_k);
        }

#pragma unroll
        for (int s = 0; s < 2; s++) {
            int kk = s * 8;
            uint32_t ah[4], al[4];
            int mrow = wm + g;
            ah[0] = __float_as_uint(Ah[kk + tig][mrow]);
            ah[1] = __float_as_uint(Ah[kk + tig][mrow + 8]);
            ah[2] = __float_as_uint(Ah[kk + tig + 4][mrow]);
            ah[3] = __float_as_uint(Ah[kk + tig + 4][mrow + 8]);
            al[0] = __float_as_uint(Al[kk + tig][mrow]);
            al[1] = __float_as_uint(Al[kk + tig][mrow + 8]);
            al[2] = __float_as_uint(Al[kk + tig + 4][mrow]);
            al[3] = __float_as_uint(Al[kk + tig + 4][mrow + 8]);
#pragma unroll
            for (int nt = 0; nt < 4; nt++) {
                int ncol = wn + nt * 8 + g;
                uint32_t bh[2], bl[2];
                bh[0] = __float_as_uint(Bh[kk + tig][ncol]);
                bh[1] = __float_as_uint(Bh[kk + tig + 4][ncol]);
                bl[0] = __float_as_uint(Bl[kk + tig][ncol]);
                bl[1] = __float_as_uint(Bl[kk + tig + 4][ncol]);
                mma_tf32(acc[nt], ah, bh);
                mma_tf32(acc[nt], ah, bl);
                mma_tf32(acc[nt], al, bh);
            }
        }
        __syncthreads();
    }

    // store partials: c0,c1 -> row wm+g, cols 2tig,2tig+1; c2,c3 -> row wm+g+8
    int row0 = m0 + wm + g, row1 = row0 + 8;
#pragma unroll
    for (int nt = 0; nt < 4; nt++) {
        int gate = n0 + wn + nt * 8 + 2 * tig;
        if (row0 < Mtot)
            *(float2*)&part[((size_t)z * Mtot + row0) * I3D + gate] =
                make_float2(acc[nt][0], acc[nt][1]);
        if (row1 < Mtot)
            *(float2*)&part[((size_t)z * Mtot + row1) * I3D + gate] =
                make_float2(acc[nt][2], acc[nt][3]);
    }
}

__global__ void k_xp_reduce(const float* __restrict__ bih, int Mtot, int sel)
{
    const float* part = (sel == 0) ? g_part_l : (sel == 1) ? g_part_m : g_part_s;
    float* out = (sel == 0) ? g_xp_l : (sel == 1) ? g_xp_m : g_xp_s;
    int i = blockIdx.x * 256 + threadIdx.x;
    int tot = Mtot * I3D;
    if (i >= tot) return;
    int g = i % I3D;
    float s = bih[g];
    for (int z = 0; z < SPLITK; z++) s += part[(size_t)z * tot + i];
    out[i] = s;
}

// =====================================================================
// 6) GRU recurrence — unchanged
// =====================================================================
__global__ __launch_bounds__(192) void k_gru(
    const float* __restrict__ Whh_s, const float* __restrict__ bhh_s,
    const float* __restrict__ Whh_m, const float* __restrict__ bhh_m,
    const float* __restrict__ Whh_l, const float* __restrict__ bhh_l)
{
    int blk = blockIdx.x;
    int gru = blk >> 2;
    int b = blk & 3;
    int T = (gru == 0) ? 10 : (gru == 1) ? 20 : 256;
    const float* xp  = (gru == 0) ? g_xp_s : (gru == 1) ? g_xp_m : g_xp_l;
    const float* Whh = (gru == 0) ? Whh_s : (gru == 1) ? Whh_m : Whh_l;
    const float* bhh = (gru == 0) ? bhh_s : (gru == 1) ? bhh_m : bhh_l;
    int g = threadIdx.x;

    float w[64];
#pragma unroll
    for (int d = 0; d < 64; d += 4) {
        float4 v = *(const float4*)&Whh[g * 64 + d];
        w[d] = v.x; w[d + 1] = v.y; w[d + 2] = v.z; w[d + 3] = v.w;
    }
    float bh = bhh[g];

    __shared__ float h_sh[64], r_sh[64], z_sh[64], n_sh[64];
    if (g < 64) h_sh[g] = 0.f;
    __syncthreads();

    const float* xpb = xp + (size_t)b * T * I3D;
    for (int t = 0; t < T; t++) {
        float a0 = 0.f, a1 = 0.f, a2 = 0.f, a3 = 0.f;
#pragma unroll
        for (int d = 0; d < 64; d += 4) {
            a0 += w[d]     * h_sh[d];
            a1 += w[d + 1] * h_sh[d + 1];
            a2 += w[d + 2] * h_sh[d + 2];
            a3 += w[d + 3] * h_sh[d + 3];
        }
        float gh = bh + ((a0 + a1) + (a2 + a3));
        float xv = xpb[t * I3D + g];
        if (g < 64) {
            r_sh[g] = sigm_f(xv + gh);
        } else if (g < 128) {
            z_sh[g - 64] = sigm_f(xv + gh);
        }
        __syncthreads();
        if (g >= 128) {
            n_sh[g - 128] = tanhf(xv + r_sh[g - 128] * gh);
        }
        __syncthreads();
        if (g < 64) {
            float zz = z_sh[g], nn = n_sh[g];
            h_sh[g] = (1.f - zz) * nn + zz * h_sh[g];
        }
        __syncthreads();
    }
    if (g < 64) g_hcat[b * I3D + gru * 64 + g] = h_sh[g];
}

// =====================================================================
// 7) head — unchanged
// =====================================================================
__global__ __launch_bounds__(256) void k_head(
    const float* __restrict__ W1, const float* __restrict__ b1,
    const float* __restrict__ W2, const float* __restrict__ b2,
    float* __restrict__ out)
{
    __shared__ float hc[4 * I3D];
    __shared__ float h1[4 * 64];
    int t = threadIdx.x;
    for (int i = t; i < 4 * I3D; i += 256) hc[i] = g_hcat[i];
    __syncthreads();
    {
        int b = t >> 6, e = t & 63;
        float a = b1[e];
#pragma unroll 8
        for (int gg = 0; gg < I3D; gg++) a += hc[b * I3D + gg] * W1[e * I3D + gg];
        h1[b * 64 + e] = gelu_f(a);
    }
    __syncthreads();
    for (int q = t; q < 4 * NN; q += 256) {
        int b = q / NN, n = q - b * NN;
        float a = b2[n];
#pragma unroll 8
        for (int e = 0; e < 64; e++) a += h1[b * 64 + e] * W2[n * 64 + e];
        out[b * NN + n] = a;
    }
}

// =====================================================================
// launcher
// =====================================================================
extern "C" void kernel_launch(void* const* d_in, const int* in_sizes, int n_in,
                              void* d_out, int out_size)
{
    const float* x     = (const float*)d_in[0];
    const float* ipW   = (const float*)d_in[1];
    const float* ipb   = (const float*)d_in[2];
    const float* fe    = (const float*)d_in[3];
    const float* te    = (const float*)d_in[4];
    const float* glW   = (const float*)d_in[5];
    const float* glb   = (const float*)d_in[6];
    const float* glg   = (const float*)d_in[7];
    const float* glbe  = (const float*)d_in[8];
    const float* Wih_s = (const float*)d_in[9];
    const float* Whh_s = (const float*)d_in[10];
    const float* bih_s = (const float*)d_in[11];
    const float* bhh_s = (const float*)d_in[12];
    const float* Wih_m = (const float*)d_in[13];
    const float* Whh_m = (const float*)d_in[14];
    const float* bih_m = (const float*)d_in[15];
    const float* bhh_m = (const float*)d_in[16];
    const float* Wih_l = (const float*)d_in[17];
    const float* Whh_l = (const float*)d_in[18];
    const float* bih_l = (const float*)d_in[19];
    const float* bhh_l = (const float*)d_in[20];
    const float* dhW1  = (const float*)d_in[21];
    const float* dhb1  = (const float*)d_in[22];
    const float* dhW2  = (const float*)d_in[23];
    const float* dhb2  = (const float*)d_in[24];
    float* out = (float*)d_out;

    const int FUSED_SMEM = 17216 * 4;   // 68864 bytes
    cudaFuncSetAttribute(k_agg_token_tc,
                         cudaFuncAttributeMaxDynamicSharedMemorySize, FUSED_SMEM);

    k_input_proj<<<4000, 256>>>(x, ipW, ipb);
    k_adj<<<NN, 256>>>(fe, te);

    // layer 0: src g_X -> dst g_Y
    k_agg_token_tc<<<dim3(4, GDCOL / 128), 256, FUSED_SMEM>>>(glW, glb, glg, glbe, 0);
    // layer 1: src g_Y -> dst g_flat (scatter)
    k_agg_token_tc<<<dim3(4, GDCOL / 128), 256, FUSED_SMEM>>>(glW + 4096, glb + 64, glg + 64, glbe + 64, 1);

    // GRU input projections (split-K, tensor cores)
    k_xp_tc<<<dim3(16, 3, SPLITK), 256>>>(Wih_l, 256, 1024, 0);
    k_xp_tc<<<dim3(2, 3, SPLITK), 256>>>(Wih_m, 20, 80, 1);
    k_xp_tc<<<dim3(1, 3, SPLITK), 256>>>(Wih_s, 10, 40, 2);
    k_xp_reduce<<<(1024 * I3D + 255) / 256, 256>>>(bih_l, 1024, 0);
    k_xp_reduce<<<(80 * I3D + 255) / 256, 256>>>(bih_m, 80, 1);
    k_xp_reduce<<<(40 * I3D + 255) / 256, 256>>>(bih_s, 40, 2);

    k_gru<<<12, 192>>>(Whh_s, bhh_s, Whh_m, bhh_m, Whh_l, bhh_l);
    k_head<<<1, 256>>>(dhW1, dhb1, dhW2, dhb2, out);
}

// round 11
// speedup vs baseline: 1.3875x; 1.2490x over previous
#include <cuda_runtime.h>
#include <cuda_bf16.h>
#include <math.h>
#include <stdint.h>

// ---------------- problem constants ----------------
#define B_    4
#define S_    256
#define BS_   1024          // B*S
#define NN    500           // nodes
#define NPAD  512
#define FF    32
#define DD    64
#define GDCOL 65536         // BS_*DD
#define I3D   192
#define KIN   32000
#define SPLITK 25
#define KCH_L  1280         // 32000/25

// ---------------- device scratch (static zero-init; pads never written) ----------------
__device__ __align__(16) float g_X[(size_t)NPAD * BS_ * DD];
__device__ __align__(16) float g_Y[(size_t)NPAD * BS_ * DD];
__device__ __align__(16) float g_flat[(size_t)BS_ * KIN];
__device__ __align__(16) float g_adjT[NPAD * NPAD];
__device__ __align__(16) float g_part_l[SPLITK * BS_ * I3D];
__device__ __align__(16) float g_part_m[SPLITK * 80 * I3D];
__device__ __align__(16) float g_part_s[SPLITK * 40 * I3D];
__device__ __align__(16) float g_xp_l[BS_ * I3D];
__device__ __align__(16) float g_xp_m[80 * I3D];
__device__ __align__(16) float g_xp_s[40 * I3D];
__device__ __align__(16) float g_hcat[4 * I3D];

__device__ __forceinline__ float gelu_f(float x) {
    return 0.5f * x * (1.0f + erff(x * 0.7071067811865476f));
}
__device__ __forceinline__ float sigm_f(float x) {
    return 1.0f / (1.0f + expf(-x));
}

// ---- tf32 helpers (epilogue token transform keeps tf32 path) ----
__device__ __forceinline__ uint32_t to_tf32(float v) {
    uint32_t r;
    asm("cvt.rna.tf32.f32 %0, %1;" : "=r"(r) : "f"(v));
    return r;
}
__device__ __forceinline__ void split_tf32(float v, float& hi, float& lo) {
    uint32_t h = to_tf32(v);
    hi = __uint_as_float(h);
    lo = __uint_as_float(to_tf32(v - hi));
}
__device__ __forceinline__ void mma_tf32(float* c, const uint32_t* a, const uint32_t* b) {
    asm volatile(
        "mma.sync.aligned.m16n8k8.row.col.f32.tf32.tf32.f32 "
        "{%0,%1,%2,%3}, {%4,%5,%6,%7}, {%8,%9}, {%0,%1,%2,%3};"
        : "+f"(c[0]), "+f"(c[1]), "+f"(c[2]), "+f"(c[3])
        : "r"(a[0]), "r"(a[1]), "r"(a[2]), "r"(a[3]), "r"(b[0]), "r"(b[1]));
}

// ---- bf16 3-split helpers (mainloops) ----
__device__ __forceinline__ void mma_bf16(float* c, const uint32_t* a, const uint32_t* b) {
    asm volatile(
        "mma.sync.aligned.m16n8k16.row.col.f32.bf16.bf16.f32 "
        "{%0,%1,%2,%3}, {%4,%5,%6,%7}, {%8,%9}, {%0,%1,%2,%3};"
        : "+f"(c[0]), "+f"(c[1]), "+f"(c[2]), "+f"(c[3])
        : "r"(a[0]), "r"(a[1]), "r"(a[2]), "r"(a[3]), "r"(b[0]), "r"(b[1]));
}
// pack (v0 -> low 16, v1 -> high 16) as bf16 hi parts + bf16 residuals
__device__ __forceinline__ void split2_bf16(float v0, float v1, uint32_t& ph, uint32_t& pl) {
    __nv_bfloat16 h0 = __float2bfloat16(v0), h1 = __float2bfloat16(v1);
    ph = ((uint32_t)__bfloat16_as_ushort(h1) << 16) | (uint32_t)__bfloat16_as_ushort(h0);
    float f0 = __bfloat162float(h0), f1 = __bfloat162float(h1);
    __nv_bfloat16 l0 = __float2bfloat16(v0 - f0), l1 = __float2bfloat16(v1 - f1);
    pl = ((uint32_t)__bfloat16_as_ushort(l1) << 16) | (uint32_t)__bfloat16_as_ushort(l0);
}

// =====================================================================
// 1) input projection: X[n][bs][d] = gelu(sum_f x[bs][n][f]*ipW[d][f] + b[d])
// =====================================================================
__global__ __launch_bounds__(256) void k_input_proj(
    const float* __restrict__ x, const float* __restrict__ ipW, const float* __restrict__ ipb)
{
    __shared__ float Wt[FF][DD];   // Wt[f][d]
    __shared__ float sb[DD];
    int tid = threadIdx.x;
    for (int q = tid; q < FF * DD; q += 256) {
        int d = q >> 5, f = q & 31;          // ipW row-major [d][f]
        Wt[f][d] = ipW[q];
    }
    if (tid < DD) sb[tid] = ipb[tid];
    __syncthreads();
    int warp = tid >> 5, lane = tid & 31;
    for (int it = 0; it < 16; it++) {
        int row = (blockIdx.x * 16 + it) * 8 + warp;   // row = bs*500+n, < 512000
        float xv = x[(size_t)row * FF + lane];
        float a0 = sb[lane], a1 = sb[lane + 32];
#pragma unroll
        for (int f = 0; f < FF; f++) {
            float xf = __shfl_sync(0xffffffffu, xv, f);
            a0 += xf * Wt[f][lane];
            a1 += xf * Wt[f][lane + 32];
        }
        int bs = row / NN, n = row - bs * NN;
        size_t base = ((size_t)n * BS_ + bs) * DD;
        g_X[base + lane]      = gelu_f(a0);
        g_X[base + lane + 32] = gelu_f(a1);
    }
}

// =====================================================================
// 2) adjacency: adjT[m][n] = softmax_over_m((from[n].to[m]) * 2)
// =====================================================================
__global__ __launch_bounds__(256) void k_adj(
    const float* __restrict__ fe, const float* __restrict__ te)
{
    __shared__ float fl[32];
    __shared__ float lg[NN];
    __shared__ float redm[8], reds[8];
    int n = blockIdx.x, tid = threadIdx.x;
    int lane = tid & 31, warp = tid >> 5;
    if (tid < 32) fl[tid] = fe[n * 32 + tid];
    __syncthreads();

    float lmax = -1e30f;
    for (int m = tid; m < NN; m += 256) {
        float s = 0.f;
#pragma unroll
        for (int f = 0; f < 32; f++) s += fl[f] * te[m * 32 + f];
        s *= 2.0f;
        lg[m] = s;
        lmax = fmaxf(lmax, s);
    }
#pragma unroll
    for (int o = 16; o; o >>= 1) lmax = fmaxf(lmax, __shfl_xor_sync(0xffffffffu, lmax, o));
    if (lane == 0) redm[warp] = lmax;
    __syncthreads();
    float mx = redm[0];
#pragma unroll
    for (int w = 1; w < 8; w++) mx = fmaxf(mx, redm[w]);

    float lsum = 0.f;
    for (int m = tid; m < NN; m += 256) {
        float e = expf(lg[m] - mx);
        lg[m] = e;
        lsum += e;
    }
#pragma unroll
    for (int o = 16; o; o >>= 1) lsum += __shfl_xor_sync(0xffffffffu, lsum, o);
    if (lane == 0) reds[warp] = lsum;
    __syncthreads();
    float tot = 0.f;
#pragma unroll
    for (int w = 0; w < 8; w++) tot += reds[w];
    float inv = 1.0f / tot;
    for (int m = tid; m < NPAD; m += 256)
        g_adjT[m * NPAD + n] = (m < NN) ? lg[m] * inv : 0.f;
}

// =====================================================================
// 3) FUSED layer kernel — bf16 3-split mainloop (m16n8k16), tf32 epilogue.
//    u = adjT @ src + src; out = LN(gelu(u @ W^T + b))*g+be
//    layer 0: src=g_X, dst=g_Y; layer 1: src=g_Y, dst=g_flat scatter.
//    CTA 128x128x16; grid (4, 512) m-fastest for L2 B-reuse.
//    smem: pool [0,8704) floats (packed bf16 operands alias US[64][136])
//          + WH/WL (tf32 split W) + LN params = 68864 B total.
// =====================================================================
__global__ __launch_bounds__(256) void k_agg_token_tc(
    const float* __restrict__ W, const float* __restrict__ bvec,
    const float* __restrict__ gvec, const float* __restrict__ bevec,
    int layer)
{
    extern __shared__ float sm[];
    uint32_t* PAh = (uint32_t*)sm;          // [8][136] packed bf16x2 (k-pairs)
    uint32_t* PAl = (uint32_t*)sm + 1088;
    uint32_t* PBh = (uint32_t*)sm + 2176;
    uint32_t* PBl = (uint32_t*)sm + 3264;   // ends 4352 < 8704 pool
    float* US  = sm;                        // [64][136], post-mainloop alias
    float* WH  = sm + 8704;                 // [64][65]
    float* WL  = sm + 12864;
    float* sb  = sm + 17024;
    float* sg  = sm + 17088;
    float* sbe = sm + 17152;

    int tid = threadIdx.x;
    int m0 = blockIdx.x * 128, n0 = blockIdx.y * 128;
    int wid = tid >> 5, lane = tid & 31;
    int g = lane >> 2, tig = lane & 3;
    int wm = (wid & 1) * 64, wn = (wid >> 1) * 32;

    // load + split W (tf32, for epilogue) and LN params
    for (int q = tid; q < 4096; q += 256) {
        int e = q >> 6, d = q & 63;
        float h, l;
        split_tf32(W[q], h, l);
        WH[d * 65 + e] = h; WL[d * 65 + e] = l;
    }
    if (tid < 64) { sb[tid] = bvec[tid]; sg[tid] = gvec[tid]; sbe[tid] = bevec[tid]; }

    // loaders: A: row a_r, k a_kc..a_kc+7.  B: k rows 2*b_k2, 2*b_k2+1, cols b_c..b_c+3.
    int a_r = tid >> 1,  a_kc = (tid & 1) * 8;
    int b_k2 = tid >> 5;                 // 0..7
    int b_c  = (tid & 31) * 4;           // 0..124

    float acc[4][4][4];
#pragma unroll
    for (int mt = 0; mt < 4; mt++)
#pragma unroll
        for (int nt = 0; nt < 4; nt++)
#pragma unroll
            for (int r = 0; r < 4; r++) acc[mt][nt][r] = 0.f;

    const float* A  = g_adjT;
    const float* Bm = layer ? g_Y : g_X;

    float4 aR0 = *(const float4*)&A[(m0 + a_r) * NPAD + a_kc];
    float4 aR1 = *(const float4*)&A[(m0 + a_r) * NPAD + a_kc + 4];
    float4 bR0 = *(const float4*)&Bm[(size_t)(2 * b_k2) * GDCOL + n0 + b_c];
    float4 bR1 = *(const float4*)&Bm[(size_t)(2 * b_k2 + 1) * GDCOL + n0 + b_c];

    __syncthreads();   // W/LN loads complete (pool area written below)

    for (int kt = 0; kt < 32; kt++) {
        // pack current tile into smem as bf16 hi/lo pairs along k
        {
            uint32_t ph, pl;
            int ab = (a_kc >> 1);
            split2_bf16(aR0.x, aR0.y, ph, pl); PAh[(ab + 0) * 136 + a_r] = ph; PAl[(ab + 0) * 136 + a_r] = pl;
            split2_bf16(aR0.z, aR0.w, ph, pl); PAh[(ab + 1) * 136 + a_r] = ph; PAl[(ab + 1) * 136 + a_r] = pl;
            split2_bf16(aR1.x, aR1.y, ph, pl); PAh[(ab + 2) * 136 + a_r] = ph; PAl[(ab + 2) * 136 + a_r] = pl;
            split2_bf16(aR1.z, aR1.w, ph, pl); PAh[(ab + 3) * 136 + a_r] = ph; PAl[(ab + 3) * 136 + a_r] = pl;
            split2_bf16(bR0.x, bR1.x, ph, pl); PBh[b_k2 * 136 + b_c + 0] = ph; PBl[b_k2 * 136 + b_c + 0] = pl;
            split2_bf16(bR0.y, bR1.y, ph, pl); PBh[b_k2 * 136 + b_c + 1] = ph; PBl[b_k2 * 136 + b_c + 1] = pl;
            split2_bf16(bR0.z, bR1.z, ph, pl); PBh[b_k2 * 136 + b_c + 2] = ph; PBl[b_k2 * 136 + b_c + 2] = pl;
            split2_bf16(bR0.w, bR1.w, ph, pl); PBh[b_k2 * 136 + b_c + 3] = ph; PBl[b_k2 * 136 + b_c + 3] = pl;
        }
        __syncthreads();

        if (kt + 1 < 32) {
            int k0 = (kt + 1) * 16;
            aR0 = *(const float4*)&A[(m0 + a_r) * NPAD + k0 + a_kc];
            aR1 = *(const float4*)&A[(m0 + a_r) * NPAD + k0 + a_kc + 4];
            bR0 = *(const float4*)&Bm[(size_t)(k0 + 2 * b_k2) * GDCOL + n0 + b_c];
            bR1 = *(const float4*)&Bm[(size_t)(k0 + 2 * b_k2 + 1) * GDCOL + n0 + b_c];
        }

        // one m16n8k16 pass covers full 16-k tile
        {
            uint32_t ah[4][4], al[4][4];
#pragma unroll
            for (int mt = 0; mt < 4; mt++) {
                int mrow = wm + mt * 16 + g;
                ah[mt][0] = PAh[tig * 136 + mrow];
                ah[mt][1] = PAh[tig * 136 + mrow + 8];
                ah[mt][2] = PAh[(tig + 4) * 136 + mrow];
                ah[mt][3] = PAh[(tig + 4) * 136 + mrow + 8];
                al[mt][0] = PAl[tig * 136 + mrow];
                al[mt][1] = PAl[tig * 136 + mrow + 8];
                al[mt][2] = PAl[(tig + 4) * 136 + mrow];
                al[mt][3] = PAl[(tig + 4) * 136 + mrow + 8];
            }
            uint32_t bh[4][2], bl[4][2];
#pragma unroll
            for (int nt = 0; nt < 4; nt++) {
                int ncol = wn + nt * 8 + g;
                bh[nt][0] = PBh[tig * 136 + ncol];
                bh[nt][1] = PBh[(tig + 4) * 136 + ncol];
                bl[nt][0] = PBl[tig * 136 + ncol];
                bl[nt][1] = PBl[(tig + 4) * 136 + ncol];
            }
#pragma unroll
            for (int mt = 0; mt < 4; mt++)
#pragma unroll
                for (int nt = 0; nt < 4; nt++) {
                    mma_bf16(acc[mt][nt], ah[mt], bh[nt]);
                    mma_bf16(acc[mt][nt], ah[mt], bl[nt]);
                    mma_bf16(acc[mt][nt], al[mt], bh[nt]);
                }
        }
        __syncthreads();
    }

    // ------------- fused epilogue: two 64-row phases (unchanged) -------------
    for (int p = 0; p < 2; p++) {
        if ((wid & 1) == p) {
#pragma unroll
            for (int mt = 0; mt < 4; mt++) {
#pragma unroll
                for (int nt = 0; nt < 4; nt++) {
                    int lr = mt * 16 + g;
                    int lcol = wn + nt * 8 + tig * 2;
                    int cg = lcol >> 6, d = lcol & 63;
                    int grow = m0 + p * 64 + lr;
                    size_t gi0 = (size_t)grow * GDCOL + n0 + lcol;
                    size_t gi1 = (size_t)(grow + 8) * GDCOL + n0 + lcol;
                    float2 x0 = *(const float2*)&Bm[gi0];
                    float2 x1 = *(const float2*)&Bm[gi1];
                    *(float2*)&US[lr * 136 + cg * 68 + d] =
                        make_float2(acc[mt][nt][0] + x0.x, acc[mt][nt][1] + x0.y);
                    *(float2*)&US[(lr + 8) * 136 + cg * 68 + d] =
                        make_float2(acc[mt][nt][2] + x1.x, acc[mt][nt][3] + x1.y);
                }
            }
        }
        __syncthreads();

        {
            int base0 = ((wid << 3) + (g >> 1)) * 136 + (g & 1) * 68;
            int base1 = base0 + 4 * 136;

            float araw[8][4];
#pragma unroll
            for (int kk = 0; kk < 8; kk++) {
                araw[kk][0] = US[base0 + kk * 8 + tig];
                araw[kk][1] = US[base1 + kk * 8 + tig];
                araw[kk][2] = US[base0 + kk * 8 + tig + 4];
                araw[kk][3] = US[base1 + kk * 8 + tig + 4];
            }

            float tacc[8][4];
#pragma unroll
            for (int nt = 0; nt < 8; nt++)
#pragma unroll
                for (int r = 0; r < 4; r++) tacc[nt][r] = 0.f;

#pragma unroll
            for (int kk = 0; kk < 8; kk++) {
                uint32_t ah[4], al[4];
#pragma unroll
                for (int r = 0; r < 4; r++) {
                    float h, l;
                    split_tf32(araw[kk][r], h, l);
                    ah[r] = __float_as_uint(h); al[r] = __float_as_uint(l);
                }
                int k0 = (kk * 8 + tig) * 65, k1 = (kk * 8 + tig + 4) * 65;
#pragma unroll
                for (int nt = 0; nt < 8; nt++) {
                    int e = nt * 8 + g;
                    uint32_t bh[2], bl[2];
                    bh[0] = __float_as_uint(WH[k0 + e]);
                    bh[1] = __float_as_uint(WH[k1 + e]);
                    bl[0] = __float_as_uint(WL[k0 + e]);
                    bl[1] = __float_as_uint(WL[k1 + e]);
                    mma_tf32(tacc[nt], ah, bh);
                    mma_tf32(tacc[nt], ah, bl);
                    mma_tf32(tacc[nt], al, bh);
                }
            }

#pragma unroll
            for (int nt = 0; nt < 8; nt++) {
                float bbx = sb[nt * 8 + 2 * tig], bby = sb[nt * 8 + 2 * tig + 1];
                tacc[nt][0] = gelu_f(tacc[nt][0] + bbx);
                tacc[nt][1] = gelu_f(tacc[nt][1] + bby);
                tacc[nt][2] = gelu_f(tacc[nt][2] + bbx);
                tacc[nt][3] = gelu_f(tacc[nt][3] + bby);
            }

            float s0 = 0.f, s1 = 0.f;
#pragma unroll
            for (int nt = 0; nt < 8; nt++) { s0 += tacc[nt][0] + tacc[nt][1]; s1 += tacc[nt][2] + tacc[nt][3]; }
            s0 += __shfl_xor_sync(0xffffffffu, s0, 1); s0 += __shfl_xor_sync(0xffffffffu, s0, 2);
            s1 += __shfl_xor_sync(0xffffffffu, s1, 1); s1 += __shfl_xor_sync(0xffffffffu, s1, 2);
            float mu0 = s0 * (1.0f / 64.0f), mu1 = s1 * (1.0f / 64.0f);
            float v0 = 0.f, v1 = 0.f;
#pragma unroll
            for (int nt = 0; nt < 8; nt++) {
                float d0 = tacc[nt][0] - mu0, d1 = tacc[nt][1] - mu0;
                float d2 = tacc[nt][2] - mu1, d3 = tacc[nt][3] - mu1;
                v0 += d0 * d0 + d1 * d1; v1 += d2 * d2 + d3 * d3;
            }
            v0 += __shfl_xor_sync(0xffffffffu, v0, 1); v0 += __shfl_xor_sync(0xffffffffu, v0, 2);
            v1 += __shfl_xor_sync(0xffffffffu, v1, 1); v1 += __shfl_xor_sync(0xffffffffu, v1, 2);
            float inv0 = rsqrtf(v0 * (1.0f / 64.0f) + 1e-5f);
            float inv1 = rsqrtf(v1 * (1.0f / 64.0f) + 1e-5f);

            int grow0 = m0 + p * 64 + (wid << 3) + (g >> 1);
            int grow1 = grow0 + 4;
            int bs = (n0 >> 6) + (g & 1);

            size_t ob0, ob1;
            float* dst;
            if (layer == 0) {
                dst = g_Y;
                ob0 = (size_t)grow0 * GDCOL + (size_t)bs * 64;
                ob1 = (size_t)grow1 * GDCOL + (size_t)bs * 64;
            } else {
                dst = g_flat;
                ob0 = (size_t)bs * KIN + (size_t)grow0 * 64;
                ob1 = (size_t)bs * KIN + (size_t)grow1 * 64;
            }
            if (grow0 < NN) {
#pragma unroll
                for (int nt = 0; nt < 8; nt++) {
                    int c = nt * 8 + 2 * tig;
                    *(float2*)&dst[ob0 + c] = make_float2(
                        (tacc[nt][0] - mu0) * inv0 * sg[c] + sbe[c],
                        (tacc[nt][1] - mu0) * inv0 * sg[c + 1] + sbe[c + 1]);
                }
            }
            if (grow1 < NN) {
#pragma unroll
                for (int nt = 0; nt < 8; nt++) {
                    int c = nt * 8 + 2 * tig;
                    *(float2*)&dst[ob1 + c] = make_float2(
                        (tacc[nt][2] - mu1) * inv1 * sg[c] + sbe[c],
                        (tacc[nt][3] - mu1) * inv1 * sg[c + 1] + sbe[c + 1]);
                }
            }
        }
        __syncthreads();
    }
}

// =====================================================================
// 5) GRU input projection — bf16 3-split m16n8k16 GEMM, split-K.
//    CTA 64x64x16; 8 warps = 4 m x 2 n, warp tile 16x32.
// =====================================================================
__global__ __launch_bounds__(256) void k_xp_tc(
    const float* __restrict__ W, int T, int Mtot, int sel)
{
    __shared__ uint32_t PAh[8][72], PAl[8][72];
    __shared__ uint32_t PBh[8][72], PBl[8][72];
    float* part = (sel == 0) ? g_part_l : (sel == 1) ? g_part_m : g_part_s;

    int tid = threadIdx.x;
    int m0 = blockIdx.x * 64;
    int n0 = blockIdx.y * 64;
    int z  = blockIdx.z;
    int kbase = z * KCH_L;

    int wid = tid >> 5, lane = tid & 31;
    int g = lane >> 2, tig = lane & 3;
    int wm = (wid & 3) * 16, wn = (wid >> 2) * 32;

    int a_r = tid >> 2, a_k = (tid & 3) * 4;     // k a_k..a_k+3 (covers 0..15)
    int b_g = tid >> 2, b_k = (tid & 3) * 4;

    int r = m0 + a_r;
    bool a_valid = (r < Mtot);
    const float* aptr = g_flat;                   // only dereferenced if a_valid
    if (a_valid) {
        int bb = r / T, tt = r - bb * T;
        int frow = bb * S_ + (S_ - T) + tt;
        aptr = g_flat + (size_t)frow * KIN;
    }
    const float* bptr = W + (size_t)(n0 + b_g) * KIN;

    float acc[4][4];
#pragma unroll
    for (int nt = 0; nt < 4; nt++)
#pragma unroll
        for (int c = 0; c < 4; c++) acc[nt][c] = 0.f;

    const int NT = KCH_L / 16;    // 80
    float4 aReg = a_valid ? *(const float4*)(aptr + kbase + a_k) : make_float4(0.f, 0.f, 0.f, 0.f);
    float4 bReg = *(const float4*)(bptr + kbase + b_k);

    for (int kt = 0; kt < NT; kt++) {
        {
            uint32_t ph, pl;
            int ak2 = a_k >> 1, bk2 = b_k >> 1;
            split2_bf16(aReg.x, aReg.y, ph, pl); PAh[ak2 + 0][a_r] = ph; PAl[ak2 + 0][a_r] = pl;
            split2_bf16(aReg.z, aReg.w, ph, pl); PAh[ak2 + 1][a_r] = ph; PAl[ak2 + 1][a_r] = pl;
            split2_bf16(bReg.x, bReg.y, ph, pl); PBh[bk2 + 0][b_g] = ph; PBl[bk2 + 0][b_g] = pl;
            split2_bf16(bReg.z, bReg.w, ph, pl); PBh[bk2 + 1][b_g] = ph; PBl[bk2 + 1][b_g] = pl;
        }
        __syncthreads();

        if (kt + 1 < NT) {
            int k0 = kbase + (kt + 1) * 16;
            aReg = a_valid ? *(const float4*)(aptr + k0 + a_k) : make_float4(0.f, 0.f, 0.f, 0.f);
            bReg = *(const float4*)(bptr + k0 + b_k);
        }

        {
            uint32_t ah[4], al[4];
            int mrow = wm + g;
            ah[0] = PAh[tig][mrow];     ah[1] = PAh[tig][mrow + 8];
            ah[2] = PAh[tig + 4][mrow]; ah[3] = PAh[tig + 4][mrow + 8];
            al[0] = PAl[tig][mrow];     al[1] = PAl[tig][mrow + 8];
            al[2] = PAl[tig + 4][mrow]; al[3] = PAl[tig + 4][mrow + 8];
#pragma unroll
            for (int nt = 0; nt < 4; nt++) {
                int ncol = wn + nt * 8 + g;
                uint32_t bh[2], bl[2];
                bh[0] = PBh[tig][ncol]; bh[1] = PBh[tig + 4][ncol];
                bl[0] = PBl[tig][ncol]; bl[1] = PBl[tig + 4][ncol];
                mma_bf16(acc[nt], ah, bh);
                mma_bf16(acc[nt], ah, bl);
                mma_bf16(acc[nt], al, bh);
            }
        }
        __syncthreads();
    }

    int row0 = m0 + wm + g, row1 = row0 + 8;
#pragma unroll
    for (int nt = 0; nt < 4; nt++) {
        int gate = n0 + wn + nt * 8 + 2 * tig;
        if (row0 < Mtot)
            *(float2*)&part[((size_t)z * Mtot + row0) * I3D + gate] =
                make_float2(acc[nt][0], acc[nt][1]);
        if (row1 < Mtot)
            *(float2*)&part[((size_t)z * Mtot + row1) * I3D + gate] =
                make_float2(acc[nt][2], acc[nt][3]);
    }
}

__global__ void k_xp_reduce(const float* __restrict__ bih, int Mtot, int sel)
{
    const float* part = (sel == 0) ? g_part_l : (sel == 1) ? g_part_m : g_part_s;
    float* out = (sel == 0) ? g_xp_l : (sel == 1) ? g_xp_m : g_xp_s;
    int i = blockIdx.x * 256 + threadIdx.x;
    int tot = Mtot * I3D;
    if (i >= tot) return;
    int g = i % I3D;
    float s = bih[g];
    for (int z = 0; z < SPLITK; z++) s += part[(size_t)z * tot + i];
    out[i] = s;
}

// =====================================================================
// 6) GRU recurrence — unchanged
// =====================================================================
__global__ __launch_bounds__(192) void k_gru(
    const float* __restrict__ Whh_s, const float* __restrict__ bhh_s,
    const float* __restrict__ Whh_m, const float* __restrict__ bhh_m,
    const float* __restrict__ Whh_l, const float* __restrict__ bhh_l)
{
    int blk = blockIdx.x;
    int gru = blk >> 2;
    int b = blk & 3;
    int T = (gru == 0) ? 10 : (gru == 1) ? 20 : 256;
    const float* xp  = (gru == 0) ? g_xp_s : (gru == 1) ? g_xp_m : g_xp_l;
    const float* Whh = (gru == 0) ? Whh_s : (gru == 1) ? Whh_m : Whh_l;
    const float* bhh = (gru == 0) ? bhh_s : (gru == 1) ? bhh_m : bhh_l;
    int g = threadIdx.x;

    float w[64];
#pragma unroll
    for (int d = 0; d < 64; d += 4) {
        float4 v = *(const float4*)&Whh[g * 64 + d];
        w[d] = v.x; w[d + 1] = v.y; w[d + 2] = v.z; w[d + 3] = v.w;
    }
    float bh = bhh[g];

    __shared__ float h_sh[64], r_sh[64], z_sh[64], n_sh[64];
    if (g < 64) h_sh[g] = 0.f;
    __syncthreads();

    const float* xpb = xp + (size_t)b * T * I3D;
    for (int t = 0; t < T; t++) {
        float a0 = 0.f, a1 = 0.f, a2 = 0.f, a3 = 0.f;
#pragma unroll
        for (int d = 0; d < 64; d += 4) {
            a0 += w[d]     * h_sh[d];
            a1 += w[d + 1] * h_sh[d + 1];
            a2 += w[d + 2] * h_sh[d + 2];
            a3 += w[d + 3] * h_sh[d + 3];
        }
        float gh = bh + ((a0 + a1) + (a2 + a3));
        float xv = xpb[t * I3D + g];
        if (g < 64) {
            r_sh[g] = sigm_f(xv + gh);
        } else if (g < 128) {
            z_sh[g - 64] = sigm_f(xv + gh);
        }
        __syncthreads();
        if (g >= 128) {
            n_sh[g - 128] = tanhf(xv + r_sh[g - 128] * gh);
        }
        __syncthreads();
        if (g < 64) {
            float zz = z_sh[g], nn = n_sh[g];
            h_sh[g] = (1.f - zz) * nn + zz * h_sh[g];
        }
        __syncthreads();
    }
    if (g < 64) g_hcat[b * I3D + gru * 64 + g] = h_sh[g];
}

// =====================================================================
// 7) head — unchanged
// =====================================================================
__global__ __launch_bounds__(256) void k_head(
    const float* __restrict__ W1, const float* __restrict__ b1,
    const float* __restrict__ W2, const float* __restrict__ b2,
    float* __restrict__ out)
{
    __shared__ float hc[4 * I3D];
    __shared__ float h1[4 * 64];
    int t = threadIdx.x;
    for (int i = t; i < 4 * I3D; i += 256) hc[i] = g_hcat[i];
    __syncthreads();
    {
        int b = t >> 6, e = t & 63;
        float a = b1[e];
#pragma unroll 8
        for (int gg = 0; gg < I3D; gg++) a += hc[b * I3D + gg] * W1[e * I3D + gg];
        h1[b * 64 + e] = gelu_f(a);
    }
    __syncthreads();
    for (int q = t; q < 4 * NN; q += 256) {
        int b = q / NN, n = q - b * NN;
        float a = b2[n];
#pragma unroll 8
        for (int e = 0; e < 64; e++) a += h1[b * 64 + e] * W2[n * 64 + e];
        out[b * NN + n] = a;
    }
}

// =====================================================================
// launcher
// =====================================================================
extern "C" void kernel_launch(void* const* d_in, const int* in_sizes, int n_in,
                              void* d_out, int out_size)
{
    const float* x     = (const float*)d_in[0];
    const float* ipW   = (const float*)d_in[1];
    const float* ipb   = (const float*)d_in[2];
    const float* fe    = (const float*)d_in[3];
    const float* te    = (const float*)d_in[4];
    const float* glW   = (const float*)d_in[5];
    const float* glb   = (const float*)d_in[6];
    const float* glg   = (const float*)d_in[7];
    const float* glbe  = (const float*)d_in[8];
    const float* Wih_s = (const float*)d_in[9];
    const float* Whh_s = (const float*)d_in[10];
    const float* bih_s = (const float*)d_in[11];
    const float* bhh_s = (const float*)d_in[12];
    const float* Wih_m = (const float*)d_in[13];
    const float* Whh_m = (const float*)d_in[14];
    const float* bih_m = (const float*)d_in[15];
    const float* bhh_m = (const float*)d_in[16];
    const float* Wih_l = (const float*)d_in[17];
    const float* Whh_l = (const float*)d_in[18];
    const float* bih_l = (const float*)d_in[19];
    const float* bhh_l = (const float*)d_in[20];
    const float* dhW1  = (const float*)d_in[21];
    const float* dhb1  = (const float*)d_in[22];
    const float* dhW2  = (const float*)d_in[23];
    const float* dhb2  = (const float*)d_in[24];
    float* out = (float*)d_out;

    const int FUSED_SMEM = 17216 * 4;   // 68864 bytes
    cudaFuncSetAttribute(k_agg_token_tc,
                         cudaFuncAttributeMaxDynamicSharedMemorySize, FUSED_SMEM);

    k_input_proj<<<4000, 256>>>(x, ipW, ipb);
    k_adj<<<NN, 256>>>(fe, te);

    // layer 0: src g_X -> dst g_Y
    k_agg_token_tc<<<dim3(4, GDCOL / 128), 256, FUSED_SMEM>>>(glW, glb, glg, glbe, 0);
    // layer 1: src g_Y -> dst g_flat (scatter)
    k_agg_token_tc<<<dim3(4, GDCOL / 128), 256, FUSED_SMEM>>>(glW + 4096, glb + 64, glg + 64, glbe + 64, 1);

    // GRU input projections (split-K, bf16 tensor cores)
    k_xp_tc<<<dim3(16, 3, SPLITK), 256>>>(Wih_l, 256, 1024, 0);
    k_xp_tc<<<dim3(2, 3, SPLITK), 256>>>(Wih_m, 20, 80, 1);
    k_xp_tc<<<dim3(1, 3, SPLITK), 256>>>(Wih_s, 10, 40, 2);
    k_xp_reduce<<<(1024 * I3D + 255) / 256, 256>>>(bih_l, 1024, 0);
    k_xp_reduce<<<(80 * I3D + 255) / 256, 256>>>(bih_m, 80, 1);
    k_xp_reduce<<<(40 * I3D + 255) / 256, 256>>>(bih_s, 40, 2);

    k_gru<<<12, 192>>>(Whh_s, bhh_s, Whh_m, bhh_m, Whh_l, bhh_l);
    k_head<<<1, 256>>>(dhW1, dhb1, dhW2, dhb2, out);
}

// round 14
// speedup vs baseline: 1.4156x; 1.0203x over previous
#include <cuda_runtime.h>
#include <cuda_bf16.h>
#include <math.h>
#include <stdint.h>

// ---------------- problem constants ----------------
#define B_    4
#define S_    256
#define BS_   1024          // B*S
#define NN    500           // nodes
#define NPAD  512
#define FF    32
#define DD    64
#define GDCOL 65536         // BS_*DD
#define I3D   192
#define KIN   32000
#define SPLITK 25
#define KCH_L  1280         // 32000/25

// ---------------- device scratch (static zero-init; pads never written) ----------------
__device__ __align__(16) float g_X[(size_t)NPAD * BS_ * DD];
__device__ __align__(16) float g_Y[(size_t)NPAD * BS_ * DD];
__device__ __align__(16) float g_flat[(size_t)BS_ * KIN];
__device__ __align__(16) float g_adjT[NPAD * NPAD];
__device__ __align__(16) float g_part_l[SPLITK * BS_ * I3D];
__device__ __align__(16) float g_part_m[SPLITK * 80 * I3D];
__device__ __align__(16) float g_part_s[SPLITK * 40 * I3D];
__device__ __align__(16) float g_xp_l[BS_ * I3D];
__device__ __align__(16) float g_xp_m[80 * I3D];
__device__ __align__(16) float g_xp_s[40 * I3D];
__device__ __align__(16) float g_hcat[4 * I3D];

__device__ __forceinline__ float gelu_f(float x) {
    return 0.5f * x * (1.0f + erff(x * 0.7071067811865476f));
}
__device__ __forceinline__ float sigm_f(float x) {
    return 1.0f / (1.0f + expf(-x));
}

// ---- tf32 helpers (epilogue token transform) ----
__device__ __forceinline__ uint32_t to_tf32(float v) {
    uint32_t r;
    asm("cvt.rna.tf32.f32 %0, %1;" : "=r"(r) : "f"(v));
    return r;
}
__device__ __forceinline__ void split_tf32(float v, float& hi, float& lo) {
    uint32_t h = to_tf32(v);
    hi = __uint_as_float(h);
    lo = __uint_as_float(to_tf32(v - hi));
}
__device__ __forceinline__ void mma_tf32(float* c, const uint32_t* a, const uint32_t* b) {
    asm volatile(
        "mma.sync.aligned.m16n8k8.row.col.f32.tf32.tf32.f32 "
        "{%0,%1,%2,%3}, {%4,%5,%6,%7}, {%8,%9}, {%0,%1,%2,%3};"
        : "+f"(c[0]), "+f"(c[1]), "+f"(c[2]), "+f"(c[3])
        : "r"(a[0]), "r"(a[1]), "r"(a[2]), "r"(a[3]), "r"(b[0]), "r"(b[1]));
}

// ---- bf16 3-split helpers (mainloops) ----
__device__ __forceinline__ void mma_bf16(float* c, const uint32_t* a, const uint32_t* b) {
    asm volatile(
        "mma.sync.aligned.m16n8k16.row.col.f32.bf16.bf16.f32 "
        "{%0,%1,%2,%3}, {%4,%5,%6,%7}, {%8,%9}, {%0,%1,%2,%3};"
        : "+f"(c[0]), "+f"(c[1]), "+f"(c[2]), "+f"(c[3])
        : "r"(a[0]), "r"(a[1]), "r"(a[2]), "r"(a[3]), "r"(b[0]), "r"(b[1]));
}
__device__ __forceinline__ void split2_bf16(float v0, float v1, uint32_t& ph, uint32_t& pl) {
    __nv_bfloat16 h0 = __float2bfloat16(v0), h1 = __float2bfloat16(v1);
    ph = ((uint32_t)__bfloat16_as_ushort(h1) << 16) | (uint32_t)__bfloat16_as_ushort(h0);
    float f0 = __bfloat162float(h0), f1 = __bfloat162float(h1);
    __nv_bfloat16 l0 = __float2bfloat16(v0 - f0), l1 = __float2bfloat16(v1 - f1);
    pl = ((uint32_t)__bfloat16_as_ushort(l1) << 16) | (uint32_t)__bfloat16_as_ushort(l0);
}

// =====================================================================
// 1) input projection
// =====================================================================
__global__ __launch_bounds__(256) void k_input_proj(
    const float* __restrict__ x, const float* __restrict__ ipW, const float* __restrict__ ipb)
{
    __shared__ float Wt[FF][DD];
    __shared__ float sb[DD];
    int tid = threadIdx.x;
    for (int q = tid; q < FF * DD; q += 256) {
        int d = q >> 5, f = q & 31;
        Wt[f][d] = ipW[q];
    }
    if (tid < DD) sb[tid] = ipb[tid];
    __syncthreads();
    int warp = tid >> 5, lane = tid & 31;
    for (int it = 0; it < 16; it++) {
        int row = (blockIdx.x * 16 + it) * 8 + warp;
        float xv = x[(size_t)row * FF + lane];
        float a0 = sb[lane], a1 = sb[lane + 32];
#pragma unroll
        for (int f = 0; f < FF; f++) {
            float xf = __shfl_sync(0xffffffffu, xv, f);
            a0 += xf * Wt[f][lane];
            a1 += xf * Wt[f][lane + 32];
        }
        int bs = row / NN, n = row - bs * NN;
        size_t base = ((size_t)n * BS_ + bs) * DD;
        g_X[base + lane]      = gelu_f(a0);
        g_X[base + lane + 32] = gelu_f(a1);
    }
}

// =====================================================================
// 2) adjacency
// =====================================================================
__global__ __launch_bounds__(256) void k_adj(
    const float* __restrict__ fe, const float* __restrict__ te)
{
    __shared__ float fl[32];
    __shared__ float lg[NN];
    __shared__ float redm[8], reds[8];
    int n = blockIdx.x, tid = threadIdx.x;
    int lane = tid & 31, warp = tid >> 5;
    if (tid < 32) fl[tid] = fe[n * 32 + tid];
    __syncthreads();

    float lmax = -1e30f;
    for (int m = tid; m < NN; m += 256) {
        float s = 0.f;
#pragma unroll
        for (int f = 0; f < 32; f++) s += fl[f] * te[m * 32 + f];
        s *= 2.0f;
        lg[m] = s;
        lmax = fmaxf(lmax, s);
    }
#pragma unroll
    for (int o = 16; o; o >>= 1) lmax = fmaxf(lmax, __shfl_xor_sync(0xffffffffu, lmax, o));
    if (lane == 0) redm[warp] = lmax;
    __syncthreads();
    float mx = redm[0];
#pragma unroll
    for (int w = 1; w < 8; w++) mx = fmaxf(mx, redm[w]);

    float lsum = 0.f;
    for (int m = tid; m < NN; m += 256) {
        float e = expf(lg[m] - mx);
        lg[m] = e;
        lsum += e;
    }
#pragma unroll
    for (int o = 16; o; o >>= 1) lsum += __shfl_xor_sync(0xffffffffu, lsum, o);
    if (lane == 0) reds[warp] = lsum;
    __syncthreads();
    float tot = 0.f;
#pragma unroll
    for (int w = 0; w < 8; w++) tot += reds[w];
    float inv = 1.0f / tot;
    for (int m = tid; m < NPAD; m += 256)
        g_adjT[m * NPAD + n] = (m < NN) ? lg[m] * inv : 0.f;
}

// =====================================================================
// 3) FUSED layer kernel — bf16 3-split mainloop, DOUBLE-BUFFERED smem
//    (one __syncthreads per 16-k tile); tf32 epilogue unchanged.
// =====================================================================
__global__ __launch_bounds__(256) void k_agg_token_tc(
    const float* __restrict__ W, const float* __restrict__ bvec,
    const float* __restrict__ gvec, const float* __restrict__ bevec,
    int layer)
{
    extern __shared__ float sm[];
    uint32_t* pool = (uint32_t*)sm;         // 2 buffers x 4352
    float* US  = sm;                        // [64][136] alias post-mainloop
    float* WH  = sm + 8704;                 // [64][65]
    float* WL  = sm + 12864;
    float* sb  = sm + 17024;
    float* sg  = sm + 17088;
    float* sbe = sm + 17152;

    int tid = threadIdx.x;
    int m0 = blockIdx.x * 128, n0 = blockIdx.y * 128;
    int wid = tid >> 5, lane = tid & 31;
    int g = lane >> 2, tig = lane & 3;
    int wm = (wid & 1) * 64, wn = (wid >> 1) * 32;

    for (int q = tid; q < 4096; q += 256) {
        int e = q >> 6, d = q & 63;
        float h, l;
        split_tf32(W[q], h, l);
        WH[d * 65 + e] = h; WL[d * 65 + e] = l;
    }
    if (tid < 64) { sb[tid] = bvec[tid]; sg[tid] = gvec[tid]; sbe[tid] = bevec[tid]; }

    int a_r = tid >> 1,  a_kc = (tid & 1) * 8;
    int b_k2 = tid >> 5;                 // 0..7
    int b_c  = (tid & 31) * 4;           // 0..124

    float acc[4][4][4];
#pragma unroll
    for (int mt = 0; mt < 4; mt++)
#pragma unroll
        for (int nt = 0; nt < 4; nt++)
#pragma unroll
            for (int r = 0; r < 4; r++) acc[mt][nt][r] = 0.f;

    const float* A  = g_adjT;
    const float* Bm = layer ? g_Y : g_X;

    float4 aR0 = *(const float4*)&A[(m0 + a_r) * NPAD + a_kc];
    float4 aR1 = *(const float4*)&A[(m0 + a_r) * NPAD + a_kc + 4];
    float4 bR0 = *(const float4*)&Bm[(size_t)(2 * b_k2) * GDCOL + n0 + b_c];
    float4 bR1 = *(const float4*)&Bm[(size_t)(2 * b_k2 + 1) * GDCOL + n0 + b_c];

    __syncthreads();   // W/LN smem writes complete before pool writes

    // pack tile 0 into buffer 0
    {
        uint32_t* PAh = pool;
        uint32_t* PAl = pool + 1088;
        uint32_t* PBh = pool + 2176;
        uint32_t* PBl = pool + 3264;
        uint32_t ph, pl;
        int ab = (a_kc >> 1);
        split2_bf16(aR0.x, aR0.y, ph, pl); PAh[(ab + 0) * 136 + a_r] = ph; PAl[(ab + 0) * 136 + a_r] = pl;
        split2_bf16(aR0.z, aR0.w, ph, pl); PAh[(ab + 1) * 136 + a_r] = ph; PAl[(ab + 1) * 136 + a_r] = pl;
        split2_bf16(aR1.x, aR1.y, ph, pl); PAh[(ab + 2) * 136 + a_r] = ph; PAl[(ab + 2) * 136 + a_r] = pl;
        split2_bf16(aR1.z, aR1.w, ph, pl); PAh[(ab + 3) * 136 + a_r] = ph; PAl[(ab + 3) * 136 + a_r] = pl;
        split2_bf16(bR0.x, bR1.x, ph, pl); PBh[b_k2 * 136 + b_c + 0] = ph; PBl[b_k2 * 136 + b_c + 0] = pl;
        split2_bf16(bR0.y, bR1.y, ph, pl); PBh[b_k2 * 136 + b_c + 1] = ph; PBl[b_k2 * 136 + b_c + 1] = pl;
        split2_bf16(bR0.z, bR1.z, ph, pl); PBh[b_k2 * 136 + b_c + 2] = ph; PBl[b_k2 * 136 + b_c + 2] = pl;
        split2_bf16(bR0.w, bR1.w, ph, pl); PBh[b_k2 * 136 + b_c + 3] = ph; PBl[b_k2 * 136 + b_c + 3] = pl;
    }
    __syncthreads();

    for (int kt = 0; kt < 32; kt++) {
        bool more = (kt + 1 < 32);
        uint32_t* Pc = pool + (kt & 1) * 4352;
        uint32_t* Pn = pool + ((kt + 1) & 1) * 4352;

        if (more) {
            int k0 = (kt + 1) * 16;
            aR0 = *(const float4*)&A[(m0 + a_r) * NPAD + k0 + a_kc];
            aR1 = *(const float4*)&A[(m0 + a_r) * NPAD + k0 + a_kc + 4];
            bR0 = *(const float4*)&Bm[(size_t)(k0 + 2 * b_k2) * GDCOL + n0 + b_c];
            bR1 = *(const float4*)&Bm[(size_t)(k0 + 2 * b_k2 + 1) * GDCOL + n0 + b_c];
        }

        // mma on current buffer
        {
            uint32_t* PAh = Pc;
            uint32_t* PAl = Pc + 1088;
            uint32_t* PBh = Pc + 2176;
            uint32_t* PBl = Pc + 3264;
            uint32_t ah[4][4], al[4][4];
#pragma unroll
            for (int mt = 0; mt < 4; mt++) {
                int mrow = wm + mt * 16 + g;
                ah[mt][0] = PAh[tig * 136 + mrow];
                ah[mt][1] = PAh[tig * 136 + mrow + 8];
                ah[mt][2] = PAh[(tig + 4) * 136 + mrow];
                ah[mt][3] = PAh[(tig + 4) * 136 + mrow + 8];
                al[mt][0] = PAl[tig * 136 + mrow];
                al[mt][1] = PAl[tig * 136 + mrow + 8];
                al[mt][2] = PAl[(tig + 4) * 136 + mrow];
                al[mt][3] = PAl[(tig + 4) * 136 + mrow + 8];
            }
            uint32_t bh[4][2], bl[4][2];
#pragma unroll
            for (int nt = 0; nt < 4; nt++) {
                int ncol = wn + nt * 8 + g;
                bh[nt][0] = PBh[tig * 136 + ncol];
                bh[nt][1] = PBh[(tig + 4) * 136 + ncol];
                bl[nt][0] = PBl[tig * 136 + ncol];
                bl[nt][1] = PBl[(tig + 4) * 136 + ncol];
            }
#pragma unroll
            for (int mt = 0; mt < 4; mt++)
#pragma unroll
                for (int nt = 0; nt < 4; nt++) {
                    mma_bf16(acc[mt][nt], ah[mt], bh[nt]);
                    mma_bf16(acc[mt][nt], ah[mt], bl[nt]);
                    mma_bf16(acc[mt][nt], al[mt], bh[nt]);
                }
        }

        // pack next tile into other buffer (no hazard: distinct buffer)
        if (more) {
            uint32_t* PAh = Pn;
            uint32_t* PAl = Pn + 1088;
            uint32_t* PBh = Pn + 2176;
            uint32_t* PBl = Pn + 3264;
            uint32_t ph, pl;
            int ab = (a_kc >> 1);
            split2_bf16(aR0.x, aR0.y, ph, pl); PAh[(ab + 0) * 136 + a_r] = ph; PAl[(ab + 0) * 136 + a_r] = pl;
            split2_bf16(aR0.z, aR0.w, ph, pl); PAh[(ab + 1) * 136 + a_r] = ph; PAl[(ab + 1) * 136 + a_r] = pl;
            split2_bf16(aR1.x, aR1.y, ph, pl); PAh[(ab + 2) * 136 + a_r] = ph; PAl[(ab + 2) * 136 + a_r] = pl;
            split2_bf16(aR1.z, aR1.w, ph, pl); PAh[(ab + 3) * 136 + a_r] = ph; PAl[(ab + 3) * 136 + a_r] = pl;
            split2_bf16(bR0.x, bR1.x, ph, pl); PBh[b_k2 * 136 + b_c + 0] = ph; PBl[b_k2 * 136 + b_c + 0] = pl;
            split2_bf16(bR0.y, bR1.y, ph, pl); PBh[b_k2 * 136 + b_c + 1] = ph; PBl[b_k2 * 136 + b_c + 1] = pl;
            split2_bf16(bR0.z, bR1.z, ph, pl); PBh[b_k2 * 136 + b_c + 2] = ph; PBl[b_k2 * 136 + b_c + 2] = pl;
            split2_bf16(bR0.w, bR1.w, ph, pl); PBh[b_k2 * 136 + b_c + 3] = ph; PBl[b_k2 * 136 + b_c + 3] = pl;
        }
        __syncthreads();
    }

    // ------------- fused epilogue: two 64-row phases (unchanged) -------------
    for (int p = 0; p < 2; p++) {
        if ((wid & 1) == p) {
#pragma unroll
            for (int mt = 0; mt < 4; mt++) {
#pragma unroll
                for (int nt = 0; nt < 4; nt++) {
                    int lr = mt * 16 + g;
                    int lcol = wn + nt * 8 + tig * 2;
                    int cg = lcol >> 6, d = lcol & 63;
                    int grow = m0 + p * 64 + lr;
                    size_t gi0 = (size_t)grow * GDCOL + n0 + lcol;
                    size_t gi1 = (size_t)(grow + 8) * GDCOL + n0 + lcol;
                    float2 x0 = *(const float2*)&Bm[gi0];
                    float2 x1 = *(const float2*)&Bm[gi1];
                    *(float2*)&US[lr * 136 + cg * 68 + d] =
                        make_float2(acc[mt][nt][0] + x0.x, acc[mt][nt][1] + x0.y);
                    *(float2*)&US[(lr + 8) * 136 + cg * 68 + d] =
                        make_float2(acc[mt][nt][2] + x1.x, acc[mt][nt][3] + x1.y);
                }
            }
        }
        __syncthreads();

        {
            int base0 = ((wid << 3) + (g >> 1)) * 136 + (g & 1) * 68;
            int base1 = base0 + 4 * 136;

            float araw[8][4];
#pragma unroll
            for (int kk = 0; kk < 8; kk++) {
                araw[kk][0] = US[base0 + kk * 8 + tig];
                araw[kk][1] = US[base1 + kk * 8 + tig];
                araw[kk][2] = US[base0 + kk * 8 + tig + 4];
                araw[kk][3] = US[base1 + kk * 8 + tig + 4];
            }

            float tacc[8][4];
#pragma unroll
            for (int nt = 0; nt < 8; nt++)
#pragma unroll
                for (int r = 0; r < 4; r++) tacc[nt][r] = 0.f;

#pragma unroll
            for (int kk = 0; kk < 8; kk++) {
                uint32_t ah[4], al[4];
#pragma unroll
                for (int r = 0; r < 4; r++) {
                    float h, l;
                    split_tf32(araw[kk][r], h, l);
                    ah[r] = __float_as_uint(h); al[r] = __float_as_uint(l);
                }
                int k0 = (kk * 8 + tig) * 65, k1 = (kk * 8 + tig + 4) * 65;
#pragma unroll
                for (int nt = 0; nt < 8; nt++) {
                    int e = nt * 8 + g;
                    uint32_t bh[2], bl[2];
                    bh[0] = __float_as_uint(WH[k0 + e]);
                    bh[1] = __float_as_uint(WH[k1 + e]);
                    bl[0] = __float_as_uint(WL[k0 + e]);
                    bl[1] = __float_as_uint(WL[k1 + e]);
                    mma_tf32(tacc[nt], ah, bh);
                    mma_tf32(tacc[nt], ah, bl);
                    mma_tf32(tacc[nt], al, bh);
                }
            }

#pragma unroll
            for (int nt = 0; nt < 8; nt++) {
                float bbx = sb[nt * 8 + 2 * tig], bby = sb[nt * 8 + 2 * tig + 1];
                tacc[nt][0] = gelu_f(tacc[nt][0] + bbx);
                tacc[nt][1] = gelu_f(tacc[nt][1] + bby);
                tacc[nt][2] = gelu_f(tacc[nt][2] + bbx);
                tacc[nt][3] = gelu_f(tacc[nt][3] + bby);
            }

            float s0 = 0.f, s1 = 0.f;
#pragma unroll
            for (int nt = 0; nt < 8; nt++) { s0 += tacc[nt][0] + tacc[nt][1]; s1 += tacc[nt][2] + tacc[nt][3]; }
            s0 += __shfl_xor_sync(0xffffffffu, s0, 1); s0 += __shfl_xor_sync(0xffffffffu, s0, 2);
            s1 += __shfl_xor_sync(0xffffffffu, s1, 1); s1 += __shfl_xor_sync(0xffffffffu, s1, 2);
            float mu0 = s0 * (1.0f / 64.0f), mu1 = s1 * (1.0f / 64.0f);
            float v0 = 0.f, v1 = 0.f;
#pragma unroll
            for (int nt = 0; nt < 8; nt++) {
                float d0 = tacc[nt][0] - mu0, d1 = tacc[nt][1] - mu0;
                float d2 = tacc[nt][2] - mu1, d3 = tacc[nt][3] - mu1;
                v0 += d0 * d0 + d1 * d1; v1 += d2 * d2 + d3 * d3;
            }
            v0 += __shfl_xor_sync(0xffffffffu, v0, 1); v0 += __shfl_xor_sync(0xffffffffu, v0, 2);
            v1 += __shfl_xor_sync(0xffffffffu, v1, 1); v1 += __shfl_xor_sync(0xffffffffu, v1, 2);
            float inv0 = rsqrtf(v0 * (1.0f / 64.0f) + 1e-5f);
            float inv1 = rsqrtf(v1 * (1.0f / 64.0f) + 1e-5f);

            int grow0 = m0 + p * 64 + (wid << 3) + (g >> 1);
            int grow1 = grow0 + 4;
            int bs = (n0 >> 6) + (g & 1);

            size_t ob0, ob1;
            float* dst;
            if (layer == 0) {
                dst = g_Y;
                ob0 = (size_t)grow0 * GDCOL + (size_t)bs * 64;
                ob1 = (size_t)grow1 * GDCOL + (size_t)bs * 64;
            } else {
                dst = g_flat;
                ob0 = (size_t)bs * KIN + (size_t)grow0 * 64;
                ob1 = (size_t)bs * KIN + (size_t)grow1 * 64;
            }
            if (grow0 < NN) {
#pragma unroll
                for (int nt = 0; nt < 8; nt++) {
                    int c = nt * 8 + 2 * tig;
                    *(float2*)&dst[ob0 + c] = make_float2(
                        (tacc[nt][0] - mu0) * inv0 * sg[c] + sbe[c],
                        (tacc[nt][1] - mu0) * inv0 * sg[c + 1] + sbe[c + 1]);
                }
            }
            if (grow1 < NN) {
#pragma unroll
                for (int nt = 0; nt < 8; nt++) {
                    int c = nt * 8 + 2 * tig;
                    *(float2*)&dst[ob1 + c] = make_float2(
                        (tacc[nt][2] - mu1) * inv1 * sg[c] + sbe[c],
                        (tacc[nt][3] - mu1) * inv1 * sg[c + 1] + sbe[c + 1]);
                }
            }
        }
        __syncthreads();
    }
}

// =====================================================================
// 5) GRU input projection — bf16 3-split, DOUBLE-BUFFERED, split-K.
// =====================================================================
__global__ __launch_bounds__(256) void k_xp_tc(
    const float* __restrict__ W, int T, int Mtot, int sel)
{
    __shared__ uint32_t PAh[2][8][72], PAl[2][8][72];
    __shared__ uint32_t PBh[2][8][72], PBl[2][8][72];
    float* part = (sel == 0) ? g_part_l : (sel == 1) ? g_part_m : g_part_s;

    int tid = threadIdx.x;
    int m0 = blockIdx.x * 64;
    int n0 = blockIdx.y * 64;
    int z  = blockIdx.z;
    int kbase = z * KCH_L;

    int wid = tid >> 5, lane = tid & 31;
    int g = lane >> 2, tig = lane & 3;
    int wm = (wid & 3) * 16, wn = (wid >> 2) * 32;

    int a_r = tid >> 2, a_k = (tid & 3) * 4;
    int b_g = tid >> 2, b_k = (tid & 3) * 4;

    int r = m0 + a_r;
    bool a_valid = (r < Mtot);
    const float* aptr = g_flat;
    if (a_valid) {
        int bb = r / T, tt = r - bb * T;
        int frow = bb * S_ + (S_ - T) + tt;
        aptr = g_flat + (size_t)frow * KIN;
    }
    const float* bptr = W + (size_t)(n0 + b_g) * KIN;

    float acc[4][4];
#pragma unroll
    for (int nt = 0; nt < 4; nt++)
#pragma unroll
        for (int c = 0; c < 4; c++) acc[nt][c] = 0.f;

    const int NT = KCH_L / 16;    // 80
    float4 aReg = a_valid ? *(const float4*)(aptr + kbase + a_k) : make_float4(0.f, 0.f, 0.f, 0.f);
    float4 bReg = *(const float4*)(bptr + kbase + b_k);

    // pack tile 0 into buffer 0
    {
        uint32_t ph, pl;
        int ak2 = a_k >> 1, bk2 = b_k >> 1;
        split2_bf16(aReg.x, aReg.y, ph, pl); PAh[0][ak2 + 0][a_r] = ph; PAl[0][ak2 + 0][a_r] = pl;
        split2_bf16(aReg.z, aReg.w, ph, pl); PAh[0][ak2 + 1][a_r] = ph; PAl[0][ak2 + 1][a_r] = pl;
        split2_bf16(bReg.x, bReg.y, ph, pl); PBh[0][bk2 + 0][b_g] = ph; PBl[0][bk2 + 0][b_g] = pl;
        split2_bf16(bReg.z, bReg.w, ph, pl); PBh[0][bk2 + 1][b_g] = ph; PBl[0][bk2 + 1][b_g] = pl;
    }
    __syncthreads();

    for (int kt = 0; kt < NT; kt++) {
        bool more = (kt + 1 < NT);
        int cur = kt & 1, nxt = cur ^ 1;

        if (more) {
            int k0 = kbase + (kt + 1) * 16;
            aReg = a_valid ? *(const float4*)(aptr + k0 + a_k) : make_float4(0.f, 0.f, 0.f, 0.f);
            bReg = *(const float4*)(bptr + k0 + b_k);
        }

        {
            uint32_t ah[4], al[4];
            int mrow = wm + g;
            ah[0] = PAh[cur][tig][mrow];     ah[1] = PAh[cur][tig][mrow + 8];
            ah[2] = PAh[cur][tig + 4][mrow]; ah[3] = PAh[cur][tig + 4][mrow + 8];
            al[0] = PAl[cur][tig][mrow];     al[1] = PAl[cur][tig][mrow + 8];
            al[2] = PAl[cur][tig + 4][mrow]; al[3] = PAl[cur][tig + 4][mrow + 8];
#pragma unroll
            for (int nt = 0; nt < 4; nt++) {
                int ncol = wn + nt * 8 + g;
                uint32_t bh[2], bl[2];
                bh[0] = PBh[cur][tig][ncol]; bh[1] = PBh[cur][tig + 4][ncol];
                bl[0] = PBl[cur][tig][ncol]; bl[1] = PBl[cur][tig + 4][ncol];
                mma_bf16(acc[nt], ah, bh);
                mma_bf16(acc[nt], ah, bl);
                mma_bf16(acc[nt], al, bh);
            }
        }

        if (more) {
            uint32_t ph, pl;
            int ak2 = a_k >> 1, bk2 = b_k >> 1;
            split2_bf16(aReg.x, aReg.y, ph, pl); PAh[nxt][ak2 + 0][a_r] = ph; PAl[nxt][ak2 + 0][a_r] = pl;
            split2_bf16(aReg.z, aReg.w, ph, pl); PAh[nxt][ak2 + 1][a_r] = ph; PAl[nxt][ak2 + 1][a_r] = pl;
            split2_bf16(bReg.x, bReg.y, ph, pl); PBh[nxt][bk2 + 0][b_g] = ph; PBl[nxt][bk2 + 0][b_g] = pl;
            split2_bf16(bReg.z, bReg.w, ph, pl); PBh[nxt][bk2 + 1][b_g] = ph; PBl[nxt][bk2 + 1][b_g] = pl;
        }
        __syncthreads();
    }

    int row0 = m0 + wm + g, row1 = row0 + 8;
#pragma unroll
    for (int nt = 0; nt < 4; nt++) {
        int gate = n0 + wn + nt * 8 + 2 * tig;
        if (row0 < Mtot)
            *(float2*)&part[((size_t)z * Mtot + row0) * I3D + gate] =
                make_float2(acc[nt][0], acc[nt][1]);
        if (row1 < Mtot)
            *(float2*)&part[((size_t)z * Mtot + row1) * I3D + gate] =
                make_float2(acc[nt][2], acc[nt][3]);
    }
}

__global__ void k_xp_reduce(const float* __restrict__ bih, int Mtot, int sel)
{
    const float* part = (sel == 0) ? g_part_l : (sel == 1) ? g_part_m : g_part_s;
    float* out = (sel == 0) ? g_xp_l : (sel == 1) ? g_xp_m : g_xp_s;
    int i = blockIdx.x * 256 + threadIdx.x;
    int tot = Mtot * I3D;
    if (i >= tot) return;
    int g = i % I3D;
    float s = bih[g];
    for (int z = 0; z < SPLITK; z++) s += part[(size_t)z * tot + i];
    out[i] = s;
}

// =====================================================================
// 6) GRU recurrence — unchanged
// =====================================================================
__global__ __launch_bounds__(192) void k_gru(
    const float* __restrict__ Whh_s, const float* __restrict__ bhh_s,
    const float* __restrict__ Whh_m, const float* __restrict__ bhh_m,
    const float* __restrict__ Whh_l, const float* __restrict__ bhh_l)
{
    int blk = blockIdx.x;
    int gru = blk >> 2;
    int b = blk & 3;
    int T = (gru == 0) ? 10 : (gru == 1) ? 20 : 256;
    const float* xp  = (gru == 0) ? g_xp_s : (gru == 1) ? g_xp_m : g_xp_l;
    const float* Whh = (gru == 0) ? Whh_s : (gru == 1) ? Whh_m : Whh_l;
    const float* bhh = (gru == 0) ? bhh_s : (gru == 1) ? bhh_m : bhh_l;
    int g = threadIdx.x;

    float w[64];
#pragma unroll
    for (int d = 0; d < 64; d += 4) {
        float4 v = *(const float4*)&Whh[g * 64 + d];
        w[d] = v.x; w[d + 1] = v.y; w[d + 2] = v.z; w[d + 3] = v.w;
    }
    float bh = bhh[g];

    __shared__ float h_sh[64], r_sh[64], z_sh[64], n_sh[64];
    if (g < 64) h_sh[g] = 0.f;
    __syncthreads();

    const float* xpb = xp + (size_t)b * T * I3D;
    for (int t = 0; t < T; t++) {
        float a0 = 0.f, a1 = 0.f, a2 = 0.f, a3 = 0.f;
#pragma unroll
        for (int d = 0; d < 64; d += 4) {
            a0 += w[d]     * h_sh[d];
            a1 += w[d + 1] * h_sh[d + 1];
            a2 += w[d + 2] * h_sh[d + 2];
            a3 += w[d + 3] * h_sh[d + 3];
        }
        float gh = bh + ((a0 + a1) + (a2 + a3));
        float xv = xpb[t * I3D + g];
        if (g < 64) {
            r_sh[g] = sigm_f(xv + gh);
        } else if (g < 128) {
            z_sh[g - 64] = sigm_f(xv + gh);
        }
        __syncthreads();
        if (g >= 128) {
            n_sh[g - 128] = tanhf(xv + r_sh[g - 128] * gh);
        }
        __syncthreads();
        if (g < 64) {
            float zz = z_sh[g], nn = n_sh[g];
            h_sh[g] = (1.f - zz) * nn + zz * h_sh[g];
        }
        __syncthreads();
    }
    if (g < 64) g_hcat[b * I3D + gru * 64 + g] = h_sh[g];
}

// =====================================================================
// 7) head — unchanged
// =====================================================================
__global__ __launch_bounds__(256) void k_head(
    const float* __restrict__ W1, const float* __restrict__ b1,
    const float* __restrict__ W2, const float* __restrict__ b2,
    float* __restrict__ out)
{
    __shared__ float hc[4 * I3D];
    __shared__ float h1[4 * 64];
    int t = threadIdx.x;
    for (int i = t; i < 4 * I3D; i += 256) hc[i] = g_hcat[i];
    __syncthreads();
    {
        int b = t >> 6, e = t & 63;
        float a = b1[e];
#pragma unroll 8
        for (int gg = 0; gg < I3D; gg++) a += hc[b * I3D + gg] * W1[e * I3D + gg];
        h1[b * 64 + e] = gelu_f(a);
    }
    __syncthreads();
    for (int q = t; q < 4 * NN; q += 256) {
        int b = q / NN, n = q - b * NN;
        float a = b2[n];
#pragma unroll 8
        for (int e = 0; e < 64; e++) a += h1[b * 64 + e] * W2[n * 64 + e];
        out[b * NN + n] = a;
    }
}

// =====================================================================
// launcher
// =====================================================================
extern "C" void kernel_launch(void* const* d_in, const int* in_sizes, int n_in,
                              void* d_out, int out_size)
{
    const float* x     = (const float*)d_in[0];
    const float* ipW   = (const float*)d_in[1];
    const float* ipb   = (const float*)d_in[2];
    const float* fe    = (const float*)d_in[3];
    const float* te    = (const float*)d_in[4];
    const float* glW   = (const float*)d_in[5];
    const float* glb   = (const float*)d_in[6];
    const float* glg   = (const float*)d_in[7];
    const float* glbe  = (const float*)d_in[8];
    const float* Wih_s = (const float*)d_in[9];
    const float* Whh_s = (const float*)d_in[10];
    const float* bih_s = (const float*)d_in[11];
    const float* bhh_s = (const float*)d_in[12];
    const float* Wih_m = (const float*)d_in[13];
    const float* Whh_m = (const float*)d_in[14];
    const float* bih_m = (const float*)d_in[15];
    const float* bhh_m = (const float*)d_in[16];
    const float* Wih_l = (const float*)d_in[17];
    const float* Whh_l = (const float*)d_in[18];
    const float* bih_l = (const float*)d_in[19];
    const float* bhh_l = (const float*)d_in[20];
    const float* dhW1  = (const float*)d_in[21];
    const float* dhb1  = (const float*)d_in[22];
    const float* dhW2  = (const float*)d_in[23];
    const float* dhb2  = (const float*)d_in[24];
    float* out = (float*)d_out;

    const int FUSED_SMEM = 17216 * 4;   // 68864 bytes
    cudaFuncSetAttribute(k_agg_token_tc,
                         cudaFuncAttributeMaxDynamicSharedMemorySize, FUSED_SMEM);

    k_input_proj<<<4000, 256>>>(x, ipW, ipb);
    k_adj<<<NN, 256>>>(fe, te);

    // layer 0: src g_X -> dst g_Y
    k_agg_token_tc<<<dim3(4, GDCOL / 128), 256, FUSED_SMEM>>>(glW, glb, glg, glbe, 0);
    // layer 1: src g_Y -> dst g_flat (scatter)
    k_agg_token_tc<<<dim3(4, GDCOL / 128), 256, FUSED_SMEM>>>(glW + 4096, glb + 64, glg + 64, glbe + 64, 1);

    // GRU input projections (split-K, bf16 tensor cores)
    k_xp_tc<<<dim3(16, 3, SPLITK), 256>>>(Wih_l, 256, 1024, 0);
    k_xp_tc<<<dim3(2, 3, SPLITK), 256>>>(Wih_m, 20, 80, 1);
    k_xp_tc<<<dim3(1, 3, SPLITK), 256>>>(Wih_s, 10, 40, 2);
    k_xp_reduce<<<(1024 * I3D + 255) / 256, 256>>>(bih_l, 1024, 0);
    k_xp_reduce<<<(80 * I3D + 255) / 256, 256>>>(bih_m, 80, 1);
    k_xp_reduce<<<(40 * I3D + 255) / 256, 256>>>(bih_s, 40, 2);

    k_gru<<<12, 192>>>(Whh_s, bhh_s, Whh_m, bhh_m, Whh_l, bhh_l);
    k_head<<<1, 256>>>(dhW1, dhb1, dhW2, dhb2, out);
}

// round 15
// speedup vs baseline: 1.6435x; 1.1609x over previous
#include <cuda_runtime.h>
#include <cuda_bf16.h>
#include <math.h>
#include <stdint.h>

// ---------------- problem constants ----------------
#define B_    4
#define S_    256
#define BS_   1024          // B*S
#define NN    500           // nodes
#define NPAD  512
#define FF    32
#define DD    64
#define GDCOL 65536         // BS_*DD
#define I3D   192
#define KIN   32000
#define SPLITK 25
#define KCH_L  1280         // 32000/25

// ---------------- device scratch (static zero-init; pads never written) ----------------
__device__ __align__(16) float g_X[(size_t)NPAD * BS_ * DD];
__device__ __align__(16) float g_Y[(size_t)NPAD * BS_ * DD];
__device__ __align__(16) float g_flat[(size_t)BS_ * KIN];
__device__ __align__(16) float g_adjT[NPAD * NPAD];
__device__ __align__(16) float g_part_l[SPLITK * BS_ * I3D];
__device__ __align__(16) float g_part_m[SPLITK * 80 * I3D];
__device__ __align__(16) float g_part_s[SPLITK * 40 * I3D];
__device__ __align__(16) float g_xp_l[BS_ * I3D];
__device__ __align__(16) float g_xp_m[80 * I3D];
__device__ __align__(16) float g_xp_s[40 * I3D];
__device__ __align__(16) float g_hcat[4 * I3D];

__device__ __forceinline__ float gelu_f(float x) {
    return 0.5f * x * (1.0f + erff(x * 0.7071067811865476f));
}
__device__ __forceinline__ float sigm_f(float x) {
    return 1.0f / (1.0f + expf(-x));
}

// ---- tf32 helpers (epilogue token transform) ----
__device__ __forceinline__ uint32_t to_tf32(float v) {
    uint32_t r;
    asm("cvt.rna.tf32.f32 %0, %1;" : "=r"(r) : "f"(v));
    return r;
}
__device__ __forceinline__ void split_tf32(float v, float& hi, float& lo) {
    uint32_t h = to_tf32(v);
    hi = __uint_as_float(h);
    lo = __uint_as_float(to_tf32(v - hi));
}
__device__ __forceinline__ void mma_tf32(float* c, const uint32_t* a, const uint32_t* b) {
    asm volatile(
        "mma.sync.aligned.m16n8k8.row.col.f32.tf32.tf32.f32 "
        "{%0,%1,%2,%3}, {%4,%5,%6,%7}, {%8,%9}, {%0,%1,%2,%3};"
        : "+f"(c[0]), "+f"(c[1]), "+f"(c[2]), "+f"(c[3])
        : "r"(a[0]), "r"(a[1]), "r"(a[2]), "r"(a[3]), "r"(b[0]), "r"(b[1]));
}

// ---- bf16 3-split helpers (mainloops) ----
__device__ __forceinline__ void mma_bf16(float* c, const uint32_t* a, const uint32_t* b) {
    asm volatile(
        "mma.sync.aligned.m16n8k16.row.col.f32.bf16.bf16.f32 "
        "{%0,%1,%2,%3}, {%4,%5,%6,%7}, {%8,%9}, {%0,%1,%2,%3};"
        : "+f"(c[0]), "+f"(c[1]), "+f"(c[2]), "+f"(c[3])
        : "r"(a[0]), "r"(a[1]), "r"(a[2]), "r"(a[3]), "r"(b[0]), "r"(b[1]));
}
__device__ __forceinline__ void split2_bf16(float v0, float v1, uint32_t& ph, uint32_t& pl) {
    __nv_bfloat16 h0 = __float2bfloat16(v0), h1 = __float2bfloat16(v1);
    ph = ((uint32_t)__bfloat16_as_ushort(h1) << 16) | (uint32_t)__bfloat16_as_ushort(h0);
    float f0 = __bfloat162float(h0), f1 = __bfloat162float(h1);
    __nv_bfloat16 l0 = __float2bfloat16(v0 - f0), l1 = __float2bfloat16(v1 - f1);
    pl = ((uint32_t)__bfloat16_as_ushort(l1) << 16) | (uint32_t)__bfloat16_as_ushort(l0);
}

// =====================================================================
// 1) input projection
// =====================================================================
__global__ __launch_bounds__(256) void k_input_proj(
    const float* __restrict__ x, const float* __restrict__ ipW, const float* __restrict__ ipb)
{
    __shared__ float Wt[FF][DD];
    __shared__ float sb[DD];
    int tid = threadIdx.x;
    for (int q = tid; q < FF * DD; q += 256) {
        int d = q >> 5, f = q & 31;
        Wt[f][d] = ipW[q];
    }
    if (tid < DD) sb[tid] = ipb[tid];
    __syncthreads();
    int warp = tid >> 5, lane = tid & 31;
    for (int it = 0; it < 16; it++) {
        int row = (blockIdx.x * 16 + it) * 8 + warp;
        float xv = x[(size_t)row * FF + lane];
        float a0 = sb[lane], a1 = sb[lane + 32];
#pragma unroll
        for (int f = 0; f < FF; f++) {
            float xf = __shfl_sync(0xffffffffu, xv, f);
            a0 += xf * Wt[f][lane];
            a1 += xf * Wt[f][lane + 32];
        }
        int bs = row / NN, n = row - bs * NN;
        size_t base = ((size_t)n * BS_ + bs) * DD;
        g_X[base + lane]      = gelu_f(a0);
        g_X[base + lane + 32] = gelu_f(a1);
    }
}

// =====================================================================
// 2) adjacency
// =====================================================================
__global__ __launch_bounds__(256) void k_adj(
    const float* __restrict__ fe, const float* __restrict__ te)
{
    __shared__ float fl[32];
    __shared__ float lg[NN];
    __shared__ float redm[8], reds[8];
    int n = blockIdx.x, tid = threadIdx.x;
    int lane = tid & 31, warp = tid >> 5;
    if (tid < 32) fl[tid] = fe[n * 32 + tid];
    __syncthreads();

    float lmax = -1e30f;
    for (int m = tid; m < NN; m += 256) {
        float s = 0.f;
#pragma unroll
        for (int f = 0; f < 32; f++) s += fl[f] * te[m * 32 + f];
        s *= 2.0f;
        lg[m] = s;
        lmax = fmaxf(lmax, s);
    }
#pragma unroll
    for (int o = 16; o; o >>= 1) lmax = fmaxf(lmax, __shfl_xor_sync(0xffffffffu, lmax, o));
    if (lane == 0) redm[warp] = lmax;
    __syncthreads();
    float mx = redm[0];
#pragma unroll
    for (int w = 1; w < 8; w++) mx = fmaxf(mx, redm[w]);

    float lsum = 0.f;
    for (int m = tid; m < NN; m += 256) {
        float e = expf(lg[m] - mx);
        lg[m] = e;
        lsum += e;
    }
#pragma unroll
    for (int o = 16; o; o >>= 1) lsum += __shfl_xor_sync(0xffffffffu, lsum, o);
    if (lane == 0) reds[warp] = lsum;
    __syncthreads();
    float tot = 0.f;
#pragma unroll
    for (int w = 0; w < 8; w++) tot += reds[w];
    float inv = 1.0f / tot;
    for (int m = tid; m < NPAD; m += 256)
        g_adjT[m * NPAD + n] = (m < NN) ? lg[m] * inv : 0.f;
}

// =====================================================================
// 3) FUSED layer kernel — bf16 3-split, double-buffered, 2 CTAs/SM.
//    No register prefetch: pack stage issues its own LDGs (the second
//    resident CTA hides the load latency). __launch_bounds__(256, 2).
// =====================================================================
__global__ __launch_bounds__(256, 2) void k_agg_token_tc(
    const float* __restrict__ W, const float* __restrict__ bvec,
    const float* __restrict__ gvec, const float* __restrict__ bevec,
    int layer)
{
    extern __shared__ float sm[];
    uint32_t* pool = (uint32_t*)sm;         // 2 buffers x 4352
    float* US  = sm;                        // [64][136] alias post-mainloop
    float* WH  = sm + 8704;                 // [64][65]
    float* WL  = sm + 12864;
    float* sb  = sm + 17024;
    float* sg  = sm + 17088;
    float* sbe = sm + 17152;

    int tid = threadIdx.x;
    int m0 = blockIdx.x * 128, n0 = blockIdx.y * 128;
    int wid = tid >> 5, lane = tid & 31;
    int g = lane >> 2, tig = lane & 3;
    int wm = (wid & 1) * 64, wn = (wid >> 1) * 32;

    for (int q = tid; q < 4096; q += 256) {
        int e = q >> 6, d = q & 63;
        float h, l;
        split_tf32(W[q], h, l);
        WH[d * 65 + e] = h; WL[d * 65 + e] = l;
    }
    if (tid < 64) { sb[tid] = bvec[tid]; sg[tid] = gvec[tid]; sbe[tid] = bevec[tid]; }

    int a_r = tid >> 1,  a_kc = (tid & 1) * 8;
    int b_k2 = tid >> 5;                 // 0..7
    int b_c  = (tid & 31) * 4;           // 0..124

    float acc[4][4][4];
#pragma unroll
    for (int mt = 0; mt < 4; mt++)
#pragma unroll
        for (int nt = 0; nt < 4; nt++)
#pragma unroll
            for (int r = 0; r < 4; r++) acc[mt][nt][r] = 0.f;

    const float* A  = g_adjT;
    const float* Bm = layer ? g_Y : g_X;

    __syncthreads();   // W/LN smem writes complete before pool writes

    // pack tile 0 into buffer 0 (loads global directly)
    {
        uint32_t* PAh = pool;
        uint32_t* PAl = pool + 1088;
        uint32_t* PBh = pool + 2176;
        uint32_t* PBl = pool + 3264;
        float4 aR0 = *(const float4*)&A[(m0 + a_r) * NPAD + a_kc];
        float4 aR1 = *(const float4*)&A[(m0 + a_r) * NPAD + a_kc + 4];
        float4 bR0 = *(const float4*)&Bm[(size_t)(2 * b_k2) * GDCOL + n0 + b_c];
        float4 bR1 = *(const float4*)&Bm[(size_t)(2 * b_k2 + 1) * GDCOL + n0 + b_c];
        uint32_t ph, pl;
        int ab = (a_kc >> 1);
        split2_bf16(aR0.x, aR0.y, ph, pl); PAh[(ab + 0) * 136 + a_r] = ph; PAl[(ab + 0) * 136 + a_r] = pl;
        split2_bf16(aR0.z, aR0.w, ph, pl); PAh[(ab + 1) * 136 + a_r] = ph; PAl[(ab + 1) * 136 + a_r] = pl;
        split2_bf16(aR1.x, aR1.y, ph, pl); PAh[(ab + 2) * 136 + a_r] = ph; PAl[(ab + 2) * 136 + a_r] = pl;
        split2_bf16(aR1.z, aR1.w, ph, pl); PAh[(ab + 3) * 136 + a_r] = ph; PAl[(ab + 3) * 136 + a_r] = pl;
        split2_bf16(bR0.x, bR1.x, ph, pl); PBh[b_k2 * 136 + b_c + 0] = ph; PBl[b_k2 * 136 + b_c + 0] = pl;
        split2_bf16(bR0.y, bR1.y, ph, pl); PBh[b_k2 * 136 + b_c + 1] = ph; PBl[b_k2 * 136 + b_c + 1] = pl;
        split2_bf16(bR0.z, bR1.z, ph, pl); PBh[b_k2 * 136 + b_c + 2] = ph; PBl[b_k2 * 136 + b_c + 2] = pl;
        split2_bf16(bR0.w, bR1.w, ph, pl); PBh[b_k2 * 136 + b_c + 3] = ph; PBl[b_k2 * 136 + b_c + 3] = pl;
    }
    __syncthreads();

    for (int kt = 0; kt < 32; kt++) {
        bool more = (kt + 1 < 32);
        uint32_t* Pc = pool + (kt & 1) * 4352;
        uint32_t* Pn = pool + ((kt + 1) & 1) * 4352;

        // mma on current buffer
        {
            uint32_t* PAh = Pc;
            uint32_t* PAl = Pc + 1088;
            uint32_t* PBh = Pc + 2176;
            uint32_t* PBl = Pc + 3264;
            uint32_t ah[4][4], al[4][4];
#pragma unroll
            for (int mt = 0; mt < 4; mt++) {
                int mrow = wm + mt * 16 + g;
                ah[mt][0] = PAh[tig * 136 + mrow];
                ah[mt][1] = PAh[tig * 136 + mrow + 8];
                ah[mt][2] = PAh[(tig + 4) * 136 + mrow];
                ah[mt][3] = PAh[(tig + 4) * 136 + mrow + 8];
                al[mt][0] = PAl[tig * 136 + mrow];
                al[mt][1] = PAl[tig * 136 + mrow + 8];
                al[mt][2] = PAl[(tig + 4) * 136 + mrow];
                al[mt][3] = PAl[(tig + 4) * 136 + mrow + 8];
            }
            uint32_t bh[4][2], bl[4][2];
#pragma unroll
            for (int nt = 0; nt < 4; nt++) {
                int ncol = wn + nt * 8 + g;
                bh[nt][0] = PBh[tig * 136 + ncol];
                bh[nt][1] = PBh[(tig + 4) * 136 + ncol];
                bl[nt][0] = PBl[tig * 136 + ncol];
                bl[nt][1] = PBl[(tig + 4) * 136 + ncol];
            }
#pragma unroll
            for (int mt = 0; mt < 4; mt++)
#pragma unroll
                for (int nt = 0; nt < 4; nt++) {
                    mma_bf16(acc[mt][nt], ah[mt], bh[nt]);
                    mma_bf16(acc[mt][nt], ah[mt], bl[nt]);
                    mma_bf16(acc[mt][nt], al[mt], bh[nt]);
                }
        }

        // pack next tile into other buffer (own LDGs; other CTA hides latency)
        if (more) {
            int k0 = (kt + 1) * 16;
            uint32_t* PAh = Pn;
            uint32_t* PAl = Pn + 1088;
            uint32_t* PBh = Pn + 2176;
            uint32_t* PBl = Pn + 3264;
            float4 aR0 = *(const float4*)&A[(m0 + a_r) * NPAD + k0 + a_kc];
            float4 aR1 = *(const float4*)&A[(m0 + a_r) * NPAD + k0 + a_kc + 4];
            float4 bR0 = *(const float4*)&Bm[(size_t)(k0 + 2 * b_k2) * GDCOL + n0 + b_c];
            float4 bR1 = *(const float4*)&Bm[(size_t)(k0 + 2 * b_k2 + 1) * GDCOL + n0 + b_c];
            uint32_t ph, pl;
            int ab = (a_kc >> 1);
            split2_bf16(aR0.x, aR0.y, ph, pl); PAh[(ab + 0) * 136 + a_r] = ph; PAl[(ab + 0) * 136 + a_r] = pl;
            split2_bf16(aR0.z, aR0.w, ph, pl); PAh[(ab + 1) * 136 + a_r] = ph; PAl[(ab + 1) * 136 + a_r] = pl;
            split2_bf16(aR1.x, aR1.y, ph, pl); PAh[(ab + 2) * 136 + a_r] = ph; PAl[(ab + 2) * 136 + a_r] = pl;
            split2_bf16(aR1.z, aR1.w, ph, pl); PAh[(ab + 3) * 136 + a_r] = ph; PAl[(ab + 3) * 136 + a_r] = pl;
            split2_bf16(bR0.x, bR1.x, ph, pl); PBh[b_k2 * 136 + b_c + 0] = ph; PBl[b_k2 * 136 + b_c + 0] = pl;
            split2_bf16(bR0.y, bR1.y, ph, pl); PBh[b_k2 * 136 + b_c + 1] = ph; PBl[b_k2 * 136 + b_c + 1] = pl;
            split2_bf16(bR0.z, bR1.z, ph, pl); PBh[b_k2 * 136 + b_c + 2] = ph; PBl[b_k2 * 136 + b_c + 2] = pl;
            split2_bf16(bR0.w, bR1.w, ph, pl); PBh[b_k2 * 136 + b_c + 3] = ph; PBl[b_k2 * 136 + b_c + 3] = pl;
        }
        __syncthreads();
    }

    // ------------- fused epilogue: two 64-row phases (unchanged) -------------
    for (int p = 0; p < 2; p++) {
        if ((wid & 1) == p) {
#pragma unroll
            for (int mt = 0; mt < 4; mt++) {
#pragma unroll
                for (int nt = 0; nt < 4; nt++) {
                    int lr = mt * 16 + g;
                    int lcol = wn + nt * 8 + tig * 2;
                    int cg = lcol >> 6, d = lcol & 63;
                    int grow = m0 + p * 64 + lr;
                    size_t gi0 = (size_t)grow * GDCOL + n0 + lcol;
                    size_t gi1 = (size_t)(grow + 8) * GDCOL + n0 + lcol;
                    float2 x0 = *(const float2*)&Bm[gi0];
                    float2 x1 = *(const float2*)&Bm[gi1];
                    *(float2*)&US[lr * 136 + cg * 68 + d] =
                        make_float2(acc[mt][nt][0] + x0.x, acc[mt][nt][1] + x0.y);
                    *(float2*)&US[(lr + 8) * 136 + cg * 68 + d] =
                        make_float2(acc[mt][nt][2] + x1.x, acc[mt][nt][3] + x1.y);
                }
            }
        }
        __syncthreads();

        {
            int base0 = ((wid << 3) + (g >> 1)) * 136 + (g & 1) * 68;
            int base1 = base0 + 4 * 136;

            float araw[8][4];
#pragma unroll
            for (int kk = 0; kk < 8; kk++) {
                araw[kk][0] = US[base0 + kk * 8 + tig];
                araw[kk][1] = US[base1 + kk * 8 + tig];
                araw[kk][2] = US[base0 + kk * 8 + tig + 4];
                araw[kk][3] = US[base1 + kk * 8 + tig + 4];
            }

            float tacc[8][4];
#pragma unroll
            for (int nt = 0; nt < 8; nt++)
#pragma unroll
                for (int r = 0; r < 4; r++) tacc[nt][r] = 0.f;

#pragma unroll
            for (int kk = 0; kk < 8; kk++) {
                uint32_t ah[4], al[4];
#pragma unroll
                for (int r = 0; r < 4; r++) {
                    float h, l;
                    split_tf32(araw[kk][r], h, l);
                    ah[r] = __float_as_uint(h); al[r] = __float_as_uint(l);
                }
                int k0 = (kk * 8 + tig) * 65, k1 = (kk * 8 + tig + 4) * 65;
#pragma unroll
                for (int nt = 0; nt < 8; nt++) {
                    int e = nt * 8 + g;
                    uint32_t bh[2], bl[2];
                    bh[0] = __float_as_uint(WH[k0 + e]);
                    bh[1] = __float_as_uint(WH[k1 + e]);
                    bl[0] = __float_as_uint(WL[k0 + e]);
                    bl[1] = __float_as_uint(WL[k1 + e]);
                    mma_tf32(tacc[nt], ah, bh);
                    mma_tf32(tacc[nt], ah, bl);
                    mma_tf32(tacc[nt], al, bh);
                }
            }

#pragma unroll
            for (int nt = 0; nt < 8; nt++) {
                float bbx = sb[nt * 8 + 2 * tig], bby = sb[nt * 8 + 2 * tig + 1];
                tacc[nt][0] = gelu_f(tacc[nt][0] + bbx);
                tacc[nt][1] = gelu_f(tacc[nt][1] + bby);
                tacc[nt][2] = gelu_f(tacc[nt][2] + bbx);
                tacc[nt][3] = gelu_f(tacc[nt][3] + bby);
            }

            float s0 = 0.f, s1 = 0.f;
#pragma unroll
            for (int nt = 0; nt < 8; nt++) { s0 += tacc[nt][0] + tacc[nt][1]; s1 += tacc[nt][2] + tacc[nt][3]; }
            s0 += __shfl_xor_sync(0xffffffffu, s0, 1); s0 += __shfl_xor_sync(0xffffffffu, s0, 2);
            s1 += __shfl_xor_sync(0xffffffffu, s1, 1); s1 += __shfl_xor_sync(0xffffffffu, s1, 2);
            float mu0 = s0 * (1.0f / 64.0f), mu1 = s1 * (1.0f / 64.0f);
            float v0 = 0.f, v1 = 0.f;
#pragma unroll
            for (int nt = 0; nt < 8; nt++) {
                float d0 = tacc[nt][0] - mu0, d1 = tacc[nt][1] - mu0;
                float d2 = tacc[nt][2] - mu1, d3 = tacc[nt][3] - mu1;
                v0 += d0 * d0 + d1 * d1; v1 += d2 * d2 + d3 * d3;
            }
            v0 += __shfl_xor_sync(0xffffffffu, v0, 1); v0 += __shfl_xor_sync(0xffffffffu, v0, 2);
            v1 += __shfl_xor_sync(0xffffffffu, v1, 1); v1 += __shfl_xor_sync(0xffffffffu, v1, 2);
            float inv0 = rsqrtf(v0 * (1.0f / 64.0f) + 1e-5f);
            float inv1 = rsqrtf(v1 * (1.0f / 64.0f) + 1e-5f);

            int grow0 = m0 + p * 64 + (wid << 3) + (g >> 1);
            int grow1 = grow0 + 4;
            int bs = (n0 >> 6) + (g & 1);

            size_t ob0, ob1;
            float* dst;
            if (layer == 0) {
                dst = g_Y;
                ob0 = (size_t)grow0 * GDCOL + (size_t)bs * 64;
                ob1 = (size_t)grow1 * GDCOL + (size_t)bs * 64;
            } else {
                dst = g_flat;
                ob0 = (size_t)bs * KIN + (size_t)grow0 * 64;
                ob1 = (size_t)bs * KIN + (size_t)grow1 * 64;
            }
            if (grow0 < NN) {
#pragma unroll
                for (int nt = 0; nt < 8; nt++) {
                    int c = nt * 8 + 2 * tig;
                    *(float2*)&dst[ob0 + c] = make_float2(
                        (tacc[nt][0] - mu0) * inv0 * sg[c] + sbe[c],
                        (tacc[nt][1] - mu0) * inv0 * sg[c + 1] + sbe[c + 1]);
                }
            }
            if (grow1 < NN) {
#pragma unroll
                for (int nt = 0; nt < 8; nt++) {
                    int c = nt * 8 + 2 * tig;
                    *(float2*)&dst[ob1 + c] = make_float2(
                        (tacc[nt][2] - mu1) * inv1 * sg[c] + sbe[c],
                        (tacc[nt][3] - mu1) * inv1 * sg[c + 1] + sbe[c + 1]);
                }
            }
        }
        __syncthreads();
    }
}

// =====================================================================
// 5) GRU input projection — bf16 3-split, double-buffered, split-K.
// =====================================================================
__global__ __launch_bounds__(256) void k_xp_tc(
    const float* __restrict__ W, int T, int Mtot, int sel)
{
    __shared__ uint32_t PAh[2][8][72], PAl[2][8][72];
    __shared__ uint32_t PBh[2][8][72], PBl[2][8][72];
    float* part = (sel == 0) ? g_part_l : (sel == 1) ? g_part_m : g_part_s;

    int tid = threadIdx.x;
    int m0 = blockIdx.x * 64;
    int n0 = blockIdx.y * 64;
    int z  = blockIdx.z;
    int kbase = z * KCH_L;

    int wid = tid >> 5, lane = tid & 31;
    int g = lane >> 2, tig = lane & 3;
    int wm = (wid & 3) * 16, wn = (wid >> 2) * 32;

    int a_r = tid >> 2, a_k = (tid & 3) * 4;
    int b_g = tid >> 2, b_k = (tid & 3) * 4;

    int r = m0 + a_r;
    bool a_valid = (r < Mtot);
    const float* aptr = g_flat;
    if (a_valid) {
        int bb = r / T, tt = r - bb * T;
        int frow = bb * S_ + (S_ - T) + tt;
        aptr = g_flat + (size_t)frow * KIN;
    }
    const float* bptr = W + (size_t)(n0 + b_g) * KIN;

    float acc[4][4];
#pragma unroll
    for (int nt = 0; nt < 4; nt++)
#pragma unroll
        for (int c = 0; c < 4; c++) acc[nt][c] = 0.f;

    const int NT = KCH_L / 16;    // 80
    float4 aReg = a_valid ? *(const float4*)(aptr + kbase + a_k) : make_float4(0.f, 0.f, 0.f, 0.f);
    float4 bReg = *(const float4*)(bptr + kbase + b_k);

    // pack tile 0 into buffer 0
    {
        uint32_t ph, pl;
        int ak2 = a_k >> 1, bk2 = b_k >> 1;
        split2_bf16(aReg.x, aReg.y, ph, pl); PAh[0][ak2 + 0][a_r] = ph; PAl[0][ak2 + 0][a_r] = pl;
        split2_bf16(aReg.z, aReg.w, ph, pl); PAh[0][ak2 + 1][a_r] = ph; PAl[0][ak2 + 1][a_r] = pl;
        split2_bf16(bReg.x, bReg.y, ph, pl); PBh[0][bk2 + 0][b_g] = ph; PBl[0][bk2 + 0][b_g] = pl;
        split2_bf16(bReg.z, bReg.w, ph, pl); PBh[0][bk2 + 1][b_g] = ph; PBl[0][bk2 + 1][b_g] = pl;
    }
    __syncthreads();

    for (int kt = 0; kt < NT; kt++) {
        bool more = (kt + 1 < NT);
        int cur = kt & 1, nxt = cur ^ 1;

        if (more) {
            int k0 = kbase + (kt + 1) * 16;
            aReg = a_valid ? *(const float4*)(aptr + k0 + a_k) : make_float4(0.f, 0.f, 0.f, 0.f);
            bReg = *(const float4*)(bptr + k0 + b_k);
        }

        {
            uint32_t ah[4], al[4];
            int mrow = wm + g;
            ah[0] = PAh[cur][tig][mrow];     ah[1] = PAh[cur][tig][mrow + 8];
            ah[2] = PAh[cur][tig + 4][mrow]; ah[3] = PAh[cur][tig + 4][mrow + 8];
            al[0] = PAl[cur][tig][mrow];     al[1] = PAl[cur][tig][mrow + 8];
            al[2] = PAl[cur][tig + 4][mrow]; al[3] = PAl[cur][tig + 4][mrow + 8];
#pragma unroll
            for (int nt = 0; nt < 4; nt++) {
                int ncol = wn + nt * 8 + g;
                uint32_t bh[2], bl[2];
                bh[0] = PBh[cur][tig][ncol]; bh[1] = PBh[cur][tig + 4][ncol];
                bl[0] = PBl[cur][tig][ncol]; bl[1] = PBl[cur][tig + 4][ncol];
                mma_bf16(acc[nt], ah, bh);
                mma_bf16(acc[nt], ah, bl);
                mma_bf16(acc[nt], al, bh);
            }
        }

        if (more) {
            uint32_t ph, pl;
            int ak2 = a_k >> 1, bk2 = b_k >> 1;
            split2_bf16(aReg.x, aReg.y, ph, pl); PAh[nxt][ak2 + 0][a_r] = ph; PAl[nxt][ak2 + 0][a_r] = pl;
            split2_bf16(aReg.z, aReg.w, ph, pl); PAh[nxt][ak2 + 1][a_r] = ph; PAl[nxt][ak2 + 1][a_r] = pl;
            split2_bf16(bReg.x, bReg.y, ph, pl); PBh[nxt][bk2 + 0][b_g] = ph; PBl[nxt][bk2 + 0][b_g] = pl;
            split2_bf16(bReg.z, bReg.w, ph, pl); PBh[nxt][bk2 + 1][b_g] = ph; PBl[nxt][bk2 + 1][b_g] = pl;
        }
        __syncthreads();
    }

    int row0 = m0 + wm + g, row1 = row0 + 8;
#pragma unroll
    for (int nt = 0; nt < 4; nt++) {
        int gate = n0 + wn + nt * 8 + 2 * tig;
        if (row0 < Mtot)
            *(float2*)&part[((size_t)z * Mtot + row0) * I3D + gate] =
                make_float2(acc[nt][0], acc[nt][1]);
        if (row1 < Mtot)
            *(float2*)&part[((size_t)z * Mtot + row1) * I3D + gate] =
                make_float2(acc[nt][2], acc[nt][3]);
    }
}

__global__ void k_xp_reduce(const float* __restrict__ bih, int Mtot, int sel)
{
    const float* part = (sel == 0) ? g_part_l : (sel == 1) ? g_part_m : g_part_s;
    float* out = (sel == 0) ? g_xp_l : (sel == 1) ? g_xp_m : g_xp_s;
    int i = blockIdx.x * 256 + threadIdx.x;
    int tot = Mtot * I3D;
    if (i >= tot) return;
    int g = i % I3D;
    float s = bih[g];
    for (int z = 0; z < SPLITK; z++) s += part[(size_t)z * tot + i];
    out[i] = s;
}

// =====================================================================
// 6) GRU recurrence — unchanged
// =====================================================================
__global__ __launch_bounds__(192) void k_gru(
    const float* __restrict__ Whh_s, const float* __restrict__ bhh_s,
    const float* __restrict__ Whh_m, const float* __restrict__ bhh_m,
    const float* __restrict__ Whh_l, const float* __restrict__ bhh_l)
{
    int blk = blockIdx.x;
    int gru = blk >> 2;
    int b = blk & 3;
    int T = (gru == 0) ? 10 : (gru == 1) ? 20 : 256;
    const float* xp  = (gru == 0) ? g_xp_s : (gru == 1) ? g_xp_m : g_xp_l;
    const float* Whh = (gru == 0) ? Whh_s : (gru == 1) ? Whh_m : Whh_l;
    const float* bhh = (gru == 0) ? bhh_s : (gru == 1) ? bhh_m : bhh_l;
    int g = threadIdx.x;

    float w[64];
#pragma unroll
    for (int d = 0; d < 64; d += 4) {
        float4 v = *(const float4*)&Whh[g * 64 + d];
        w[d] = v.x; w[d + 1] = v.y; w[d + 2] = v.z; w[d + 3] = v.w;
    }
    float bh = bhh[g];

    __shared__ float h_sh[64], r_sh[64], z_sh[64], n_sh[64];
    if (g < 64) h_sh[g] = 0.f;
    __syncthreads();

    const float* xpb = xp + (size_t)b * T * I3D;
    for (int t = 0; t < T; t++) {
        float a0 = 0.f, a1 = 0.f, a2 = 0.f, a3 = 0.f;
#pragma unroll
        for (int d = 0; d < 64; d += 4) {
            a0 += w[d]     * h_sh[d];
            a1 += w[d + 1] * h_sh[d + 1];
            a2 += w[d + 2] * h_sh[d + 2];
            a3 += w[d + 3] * h_sh[d + 3];
        }
        float gh = bh + ((a0 + a1) + (a2 + a3));
        float xv = xpb[t * I3D + g];
        if (g < 64) {
            r_sh[g] = sigm_f(xv + gh);
        } else if (g < 128) {
            z_sh[g - 64] = sigm_f(xv + gh);
        }
        __syncthreads();
        if (g >= 128) {
            n_sh[g - 128] = tanhf(xv + r_sh[g - 128] * gh);
        }
        __syncthreads();
        if (g < 64) {
            float zz = z_sh[g], nn = n_sh[g];
            h_sh[g] = (1.f - zz) * nn + zz * h_sh[g];
        }
        __syncthreads();
    }
    if (g < 64) g_hcat[b * I3D + gru * 64 + g] = h_sh[g];
}

// =====================================================================
// 7) head — unchanged
// =====================================================================
__global__ __launch_bounds__(256) void k_head(
    const float* __restrict__ W1, const float* __restrict__ b1,
    const float* __restrict__ W2, const float* __restrict__ b2,
    float* __restrict__ out)
{
    __shared__ float hc[4 * I3D];
    __shared__ float h1[4 * 64];
    int t = threadIdx.x;
    for (int i = t; i < 4 * I3D; i += 256) hc[i] = g_hcat[i];
    __syncthreads();
    {
        int b = t >> 6, e = t & 63;
        float a = b1[e];
#pragma unroll 8
        for (int gg = 0; gg < I3D; gg++) a += hc[b * I3D + gg] * W1[e * I3D + gg];
        h1[b * 64 + e] = gelu_f(a);
    }
    __syncthreads();
    for (int q = t; q < 4 * NN; q += 256) {
        int b = q / NN, n = q - b * NN;
        float a = b2[n];
#pragma unroll 8
        for (int e = 0; e < 64; e++) a += h1[b * 64 + e] * W2[n * 64 + e];
        out[b * NN + n] = a;
    }
}

// =====================================================================
// launcher
// =====================================================================
extern "C" void kernel_launch(void* const* d_in, const int* in_sizes, int n_in,
                              void* d_out, int out_size)
{
    const float* x     = (const float*)d_in[0];
    const float* ipW   = (const float*)d_in[1];
    const float* ipb   = (const float*)d_in[2];
    const float* fe    = (const float*)d_in[3];
    const float* te    = (const float*)d_in[4];
    const float* glW   = (const float*)d_in[5];
    const float* glb   = (const float*)d_in[6];
    const float* glg   = (const float*)d_in[7];
    const float* glbe  = (const float*)d_in[8];
    const float* Wih_s = (const float*)d_in[9];
    const float* Whh_s = (const float*)d_in[10];
    const float* bih_s = (const float*)d_in[11];
    const float* bhh_s = (const float*)d_in[12];
    const float* Wih_m = (const float*)d_in[13];
    const float* Whh_m = (const float*)d_in[14];
    const float* bih_m = (const float*)d_in[15];
    const float* bhh_m = (const float*)d_in[16];
    const float* Wih_l = (const float*)d_in[17];
    const float* Whh_l = (const float*)d_in[18];
    const float* bih_l = (const float*)d_in[19];
    const float* bhh_l = (const float*)d_in[20];
    const float* dhW1  = (const float*)d_in[21];
    const float* dhb1  = (const float*)d_in[22];
    const float* dhW2  = (const float*)d_in[23];
    const float* dhb2  = (const float*)d_in[24];
    float* out = (float*)d_out;

    const int FUSED_SMEM = 17216 * 4;   // 68864 bytes
    cudaFuncSetAttribute(k_agg_token_tc,
                         cudaFuncAttributeMaxDynamicSharedMemorySize, FUSED_SMEM);

    k_input_proj<<<4000, 256>>>(x, ipW, ipb);
    k_adj<<<NN, 256>>>(fe, te);

    // layer 0: src g_X -> dst g_Y
    k_agg_token_tc<<<dim3(4, GDCOL / 128), 256, FUSED_SMEM>>>(glW, glb, glg, glbe, 0);
    // layer 1: src g_Y -> dst g_flat (scatter)
    k_agg_token_tc<<<dim3(4, GDCOL / 128), 256, FUSED_SMEM>>>(glW + 4096, glb + 64, glg + 64, glbe + 64, 1);

    // GRU input projections (split-K, bf16 tensor cores)
    k_xp_tc<<<dim3(16, 3, SPLITK), 256>>>(Wih_l, 256, 1024, 0);
    k_xp_tc<<<dim3(2, 3, SPLITK), 256>>>(Wih_m, 20, 80, 1);
    k_xp_tc<<<dim3(1, 3, SPLITK), 256>>>(Wih_s, 10, 40, 2);
    k_xp_reduce<<<(1024 * I3D + 255) / 256, 256>>>(bih_l, 1024, 0);
    k_xp_reduce<<<(80 * I3D + 255) / 256, 256>>>(bih_m, 80, 1);
    k_xp_reduce<<<(40 * I3D + 255) / 256, 256>>>(bih_s, 40, 2);

    k_gru<<<12, 192>>>(Whh_s, bhh_s, Whh_m, bhh_m, Whh_l, bhh_l);
    k_head<<<1, 256>>>(dhW1, dhb1, dhW2, dhb2, out);
}

// round 17
// speedup vs baseline: 1.7526x; 1.0664x over previous
#include <cuda_runtime.h>
#include <cuda_bf16.h>
#include <math.h>
#include <stdint.h>

// ---------------- problem constants ----------------
#define B_    4
#define S_    256
#define BS_   1024
#define NN    500
#define NPAD  512
#define FF    32
#define DD    64
#define GDCOL 65536         // BS_*DD
#define I3D   192
#define KIN   32000
#define SPLITK 25
#define KCH_L  1280

// ---------------- device scratch (static zero-init; pads never written) ----------------
__device__ __align__(16) float g_X[(size_t)NPAD * BS_ * DD];
__device__ __align__(16) float g_Y[(size_t)NPAD * BS_ * DD];
__device__ __align__(16) float g_flat[(size_t)BS_ * KIN];
__device__ __align__(16) float g_adjT[NPAD * NPAD];
__device__ __align__(16) uint32_t g_adjTp_h[256 * NPAD];     // [kpair][m]
__device__ __align__(16) uint32_t g_adjTp_l[256 * NPAD];
__device__ __align__(16) uint32_t g_Xp_h[(size_t)256 * GDCOL];  // [kpair][col]
__device__ __align__(16) uint32_t g_Xp_l[(size_t)256 * GDCOL];
__device__ __align__(16) uint32_t g_Yp_h[(size_t)256 * GDCOL];
__device__ __align__(16) uint32_t g_Yp_l[(size_t)256 * GDCOL];
__device__ __align__(16) float g_part_l[SPLITK * BS_ * I3D];
__device__ __align__(16) float g_part_m[SPLITK * 80 * I3D];
__device__ __align__(16) float g_part_s[SPLITK * 40 * I3D];
__device__ __align__(16) float g_xp_l[BS_ * I3D];
__device__ __align__(16) float g_xp_m[80 * I3D];
__device__ __align__(16) float g_xp_s[40 * I3D];
__device__ __align__(16) float g_hcat[4 * I3D];

__device__ __forceinline__ float gelu_f(float x) {
    return 0.5f * x * (1.0f + erff(x * 0.7071067811865476f));
}
__device__ __forceinline__ float sigm_f(float x) {
    return 1.0f / (1.0f + expf(-x));
}

// ---- tf32 helpers (epilogue token transform) ----
__device__ __forceinline__ uint32_t to_tf32(float v) {
    uint32_t r;
    asm("cvt.rna.tf32.f32 %0, %1;" : "=r"(r) : "f"(v));
    return r;
}
__device__ __forceinline__ void split_tf32(float v, float& hi, float& lo) {
    uint32_t h = to_tf32(v);
    hi = __uint_as_float(h);
    lo = __uint_as_float(to_tf32(v - hi));
}
__device__ __forceinline__ void mma_tf32(float* c, const uint32_t* a, const uint32_t* b) {
    asm volatile(
        "mma.sync.aligned.m16n8k8.row.col.f32.tf32.tf32.f32 "
        "{%0,%1,%2,%3}, {%4,%5,%6,%7}, {%8,%9}, {%0,%1,%2,%3};"
        : "+f"(c[0]), "+f"(c[1]), "+f"(c[2]), "+f"(c[3])
        : "r"(a[0]), "r"(a[1]), "r"(a[2]), "r"(a[3]), "r"(b[0]), "r"(b[1]));
}

// ---- bf16 3-split helpers ----
__device__ __forceinline__ void mma_bf16(float* c, const uint32_t* a, const uint32_t* b) {
    asm volatile(
        "mma.sync.aligned.m16n8k16.row.col.f32.bf16.bf16.f32 "
        "{%0,%1,%2,%3}, {%4,%5,%6,%7}, {%8,%9}, {%0,%1,%2,%3};"
        : "+f"(c[0]), "+f"(c[1]), "+f"(c[2]), "+f"(c[3])
        : "r"(a[0]), "r"(a[1]), "r"(a[2]), "r"(a[3]), "r"(b[0]), "r"(b[1]));
}
// pack (v0 -> low 16 = even-k, v1 -> high 16 = odd-k): bf16 hi + bf16 residual
__device__ __forceinline__ void split2_bf16(float v0, float v1, uint32_t& ph, uint32_t& pl) {
    __nv_bfloat16 h0 = __float2bfloat16(v0), h1 = __float2bfloat16(v1);
    ph = ((uint32_t)__bfloat16_as_ushort(h1) << 16) | (uint32_t)__bfloat16_as_ushort(h0);
    float f0 = __bfloat162float(h0), f1 = __bfloat162float(h1);
    __nv_bfloat16 l0 = __float2bfloat16(v0 - f0), l1 = __float2bfloat16(v1 - f1);
    pl = ((uint32_t)__bfloat16_as_ushort(l1) << 16) | (uint32_t)__bfloat16_as_ushort(l0);
}

// =====================================================================
// 1) input projection — warp per NODE-PAIR (rows 2j, 2j+1, same bs):
//    writes f32 g_X rows AND packed bf16 g_Xp pair-rows.
// =====================================================================
__global__ __launch_bounds__(256) void k_input_proj(
    const float* __restrict__ x, const float* __restrict__ ipW, const float* __restrict__ ipb)
{
    __shared__ float Wt[FF][DD];
    __shared__ float sb[DD];
    int tid = threadIdx.x;
    for (int q = tid; q < FF * DD; q += 256) {
        int d = q >> 5, f = q & 31;
        Wt[f][d] = ipW[q];
    }
    if (tid < DD) sb[tid] = ipb[tid];
    __syncthreads();
    int warp = tid >> 5, lane = tid & 31;
    for (int it = 0; it < 16; it++) {
        int pair = (blockIdx.x * 16 + it) * 8 + warp;   // < 256000 (1024 bs x 250 j)
        int bs = pair / 250, j = pair - bs * 250;
        size_t r0 = (size_t)bs * 500 + 2 * j;
        float xv0 = x[r0 * FF + lane];
        float xv1 = x[(r0 + 1) * FF + lane];
        float a0 = sb[lane], a1 = sb[lane + 32];
        float c0 = a0, c1 = a1;
#pragma unroll
        for (int f = 0; f < FF; f++) {
            float xf0 = __shfl_sync(0xffffffffu, xv0, f);
            float xf1 = __shfl_sync(0xffffffffu, xv1, f);
            a0 += xf0 * Wt[f][lane];
            a1 += xf0 * Wt[f][lane + 32];
            c0 += xf1 * Wt[f][lane];
            c1 += xf1 * Wt[f][lane + 32];
        }
        a0 = gelu_f(a0); a1 = gelu_f(a1);
        c0 = gelu_f(c0); c1 = gelu_f(c1);
        size_t b0 = (size_t)(2 * j) * GDCOL + bs * 64;
        g_X[b0 + lane]               = a0;
        g_X[b0 + lane + 32]          = a1;
        g_X[b0 + GDCOL + lane]       = c0;
        g_X[b0 + GDCOL + lane + 32]  = c1;
        size_t pb = (size_t)j * GDCOL + bs * 64;
        uint32_t ph, pl;
        split2_bf16(a0, c0, ph, pl);
        g_Xp_h[pb + lane] = ph; g_Xp_l[pb + lane] = pl;
        split2_bf16(a1, c1, ph, pl);
        g_Xp_h[pb + lane + 32] = ph; g_Xp_l[pb + lane + 32] = pl;
    }
}

// =====================================================================
// 2) adjacency (unchanged)
// =====================================================================
__global__ __launch_bounds__(256) void k_adj(
    const float* __restrict__ fe, const float* __restrict__ te)
{
    __shared__ float fl[32];
    __shared__ float lg[NN];
    __shared__ float redm[8], reds[8];
    int n = blockIdx.x, tid = threadIdx.x;
    int lane = tid & 31, warp = tid >> 5;
    if (tid < 32) fl[tid] = fe[n * 32 + tid];
    __syncthreads();

    float lmax = -1e30f;
    for (int m = tid; m < NN; m += 256) {
        float s = 0.f;
#pragma unroll
        for (int f = 0; f < 32; f++) s += fl[f] * te[m * 32 + f];
        s *= 2.0f;
        lg[m] = s;
        lmax = fmaxf(lmax, s);
    }
#pragma unroll
    for (int o = 16; o; o >>= 1) lmax = fmaxf(lmax, __shfl_xor_sync(0xffffffffu, lmax, o));
    if (lane == 0) redm[warp] = lmax;
    __syncthreads();
    float mx = redm[0];
#pragma unroll
    for (int w = 1; w < 8; w++) mx = fmaxf(mx, redm[w]);

    float lsum = 0.f;
    for (int m = tid; m < NN; m += 256) {
        float e = expf(lg[m] - mx);
        lg[m] = e;
        lsum += e;
    }
#pragma unroll
    for (int o = 16; o; o >>= 1) lsum += __shfl_xor_sync(0xffffffffu, lsum, o);
    if (lane == 0) reds[warp] = lsum;
    __syncthreads();
    float tot = 0.f;
#pragma unroll
    for (int w = 0; w < 8; w++) tot += reds[w];
    float inv = 1.0f / tot;
    for (int m = tid; m < NPAD; m += 256)
        g_adjT[m * NPAD + n] = (m < NN) ? lg[m] * inv : 0.f;
}

// =====================================================================
// 2b) pack adjT into [kpair][m] bf16 hi/lo (once)
// =====================================================================
__global__ void k_packA()
{
    int i = blockIdx.x * 256 + threadIdx.x;   // 256*512 = 131072
    if (i >= 256 * NPAD) return;
    int j = i >> 9, m = i & (NPAD - 1);
    float v0 = g_adjT[m * NPAD + 2 * j];
    float v1 = g_adjT[m * NPAD + 2 * j + 1];
    uint32_t ph, pl;
    split2_bf16(v0, v1, ph, pl);
    g_adjTp_h[j * NPAD + m] = ph;
    g_adjTp_l[j * NPAD + m] = pl;
}

// =====================================================================
// 3) FUSED layer kernel — pre-packed operands: mainloop copy stage is
//    pure LDG.128 -> STS.128 (no cvt). Double-buffered, 2 CTAs/SM.
//    Layer 0 epilogue also emits packed g_Yp via shfl pair-exchange.
// =====================================================================
__global__ __launch_bounds__(256, 2) void k_agg_token_tc(
    const float* __restrict__ W, const float* __restrict__ bvec,
    const float* __restrict__ gvec, const float* __restrict__ bevec,
    int layer)
{
    extern __shared__ float sm[];
    uint32_t* pool = (uint32_t*)sm;         // 2 buffers x 4352
    float* US  = sm;                        // [64][136] alias post-mainloop
    float* WH  = sm + 8704;                 // [64][65]
    float* WL  = sm + 12864;
    float* sb  = sm + 17024;
    float* sg  = sm + 17088;
    float* sbe = sm + 17152;

    int tid = threadIdx.x;
    int m0 = blockIdx.x * 128, n0 = blockIdx.y * 128;
    int wid = tid >> 5, lane = tid & 31;
    int g = lane >> 2, tig = lane & 3;
    int wm = (wid & 1) * 64, wn = (wid >> 1) * 32;

    for (int q = tid; q < 4096; q += 256) {
        int e = q >> 6, d = q & 63;
        float h, l;
        split_tf32(W[q], h, l);
        WH[d * 65 + e] = h; WL[d * 65 + e] = l;
    }
    if (tid < 64) { sb[tid] = bvec[tid]; sg[tid] = gvec[tid]; sbe[tid] = bevec[tid]; }

    int ld_j = tid >> 5;            // 0..7
    int ld_c = (tid & 31) * 4;      // 0..124

    float acc[4][4][4];
#pragma unroll
    for (int mt = 0; mt < 4; mt++)
#pragma unroll
        for (int nt = 0; nt < 4; nt++)
#pragma unroll
            for (int r = 0; r < 4; r++) acc[mt][nt][r] = 0.f;

    const float* Bm = layer ? g_Y : g_X;
    const uint32_t* Bp_h = layer ? g_Yp_h : g_Xp_h;
    const uint32_t* Bp_l = layer ? g_Yp_l : g_Xp_l;

    __syncthreads();   // W/LN smem writes complete before pool writes

    // copy tile 0 into buffer 0
    {
        uint32_t* P = pool;
        size_t ai = (size_t)ld_j * NPAD + m0 + ld_c;
        size_t bi = (size_t)ld_j * GDCOL + n0 + ld_c;
        *(uint4*)&P[ld_j * 136 + ld_c]        = *(const uint4*)&g_adjTp_h[ai];
        *(uint4*)&P[1088 + ld_j * 136 + ld_c] = *(const uint4*)&g_adjTp_l[ai];
        *(uint4*)&P[2176 + ld_j * 136 + ld_c] = *(const uint4*)&Bp_h[bi];
        *(uint4*)&P[3264 + ld_j * 136 + ld_c] = *(const uint4*)&Bp_l[bi];
    }
    __syncthreads();

    for (int kt = 0; kt < 32; kt++) {
        bool more = (kt + 1 < 32);
        uint32_t* Pc = pool + (kt & 1) * 4352;
        uint32_t* Pn = pool + ((kt + 1) & 1) * 4352;

        // mma on current buffer
        {
            uint32_t* PAh = Pc;
            uint32_t* PAl = Pc + 1088;
            uint32_t* PBh = Pc + 2176;
            uint32_t* PBl = Pc + 3264;
            uint32_t ah[4][4], al[4][4];
#pragma unroll
            for (int mt = 0; mt < 4; mt++) {
                int mrow = wm + mt * 16 + g;
                ah[mt][0] = PAh[tig * 136 + mrow];
                ah[mt][1] = PAh[tig * 136 + mrow + 8];
                ah[mt][2] = PAh[(tig + 4) * 136 + mrow];
                ah[mt][3] = PAh[(tig + 4) * 136 + mrow + 8];
                al[mt][0] = PAl[tig * 136 + mrow];
                al[mt][1] = PAl[tig * 136 + mrow + 8];
                al[mt][2] = PAl[(tig + 4) * 136 + mrow];
                al[mt][3] = PAl[(tig + 4) * 136 + mrow + 8];
            }
            uint32_t bh[4][2], bl[4][2];
#pragma unroll
            for (int nt = 0; nt < 4; nt++) {
                int ncol = wn + nt * 8 + g;
                bh[nt][0] = PBh[tig * 136 + ncol];
                bh[nt][1] = PBh[(tig + 4) * 136 + ncol];
                bl[nt][0] = PBl[tig * 136 + ncol];
                bl[nt][1] = PBl[(tig + 4) * 136 + ncol];
            }
#pragma unroll
            for (int mt = 0; mt < 4; mt++)
#pragma unroll
                for (int nt = 0; nt < 4; nt++) {
                    mma_bf16(acc[mt][nt], ah[mt], bh[nt]);
                    mma_bf16(acc[mt][nt], ah[mt], bl[nt]);
                    mma_bf16(acc[mt][nt], al[mt], bh[nt]);
                }
        }

        // copy next tile into other buffer (pure LDG->STS)
        if (more) {
            int kp = (kt + 1) * 8 + ld_j;
            size_t ai = (size_t)kp * NPAD + m0 + ld_c;
            size_t bi = (size_t)kp * GDCOL + n0 + ld_c;
            *(uint4*)&Pn[ld_j * 136 + ld_c]        = *(const uint4*)&g_adjTp_h[ai];
            *(uint4*)&Pn[1088 + ld_j * 136 + ld_c] = *(const uint4*)&g_adjTp_l[ai];
            *(uint4*)&Pn[2176 + ld_j * 136 + ld_c] = *(const uint4*)&Bp_h[bi];
            *(uint4*)&Pn[3264 + ld_j * 136 + ld_c] = *(const uint4*)&Bp_l[bi];
        }
        __syncthreads();
    }

    // ------------- fused epilogue: two 64-row phases -------------
    for (int p = 0; p < 2; p++) {
        if ((wid & 1) == p) {
#pragma unroll
            for (int mt = 0; mt < 4; mt++) {
#pragma unroll
                for (int nt = 0; nt < 4; nt++) {
                    int lr = mt * 16 + g;
                    int lcol = wn + nt * 8 + tig * 2;
                    int cg = lcol >> 6, d = lcol & 63;
                    int grow = m0 + p * 64 + lr;
                    size_t gi0 = (size_t)grow * GDCOL + n0 + lcol;
                    size_t gi1 = (size_t)(grow + 8) * GDCOL + n0 + lcol;
                    float2 x0 = *(const float2*)&Bm[gi0];
                    float2 x1 = *(const float2*)&Bm[gi1];
                    *(float2*)&US[lr * 136 + cg * 68 + d] =
                        make_float2(acc[mt][nt][0] + x0.x, acc[mt][nt][1] + x0.y);
                    *(float2*)&US[(lr + 8) * 136 + cg * 68 + d] =
                        make_float2(acc[mt][nt][2] + x1.x, acc[mt][nt][3] + x1.y);
                }
            }
        }
        __syncthreads();

        {
            int base0 = ((wid << 3) + (g >> 1)) * 136 + (g & 1) * 68;
            int base1 = base0 + 4 * 136;

            float araw[8][4];
#pragma unroll
            for (int kk = 0; kk < 8; kk++) {
                araw[kk][0] = US[base0 + kk * 8 + tig];
                araw[kk][1] = US[base1 + kk * 8 + tig];
                araw[kk][2] = US[base0 + kk * 8 + tig + 4];
                araw[kk][3] = US[base1 + kk * 8 + tig + 4];
            }

            float tacc[8][4];
#pragma unroll
            for (int nt = 0; nt < 8; nt++)
#pragma unroll
                for (int r = 0; r < 4; r++) tacc[nt][r] = 0.f;

#pragma unroll
            for (int kk = 0; kk < 8; kk++) {
                uint32_t ah[4], al[4];
#pragma unroll
                for (int r = 0; r < 4; r++) {
                    float h, l;
                    split_tf32(araw[kk][r], h, l);
                    ah[r] = __float_as_uint(h); al[r] = __float_as_uint(l);
                }
                int k0 = (kk * 8 + tig) * 65, k1 = (kk * 8 + tig + 4) * 65;
#pragma unroll
                for (int nt = 0; nt < 8; nt++) {
                    int e = nt * 8 + g;
                    uint32_t bh[2], bl[2];
                    bh[0] = __float_as_uint(WH[k0 + e]);
                    bh[1] = __float_as_uint(WH[k1 + e]);
                    bl[0] = __float_as_uint(WL[k0 + e]);
                    bl[1] = __float_as_uint(WL[k1 + e]);
                    mma_tf32(tacc[nt], ah, bh);
                    mma_tf32(tacc[nt], ah, bl);
                    mma_tf32(tacc[nt], al, bh);
                }
            }

#pragma unroll
            for (int nt = 0; nt < 8; nt++) {
                float bbx = sb[nt * 8 + 2 * tig], bby = sb[nt * 8 + 2 * tig + 1];
                tacc[nt][0] = gelu_f(tacc[nt][0] + bbx);
                tacc[nt][1] = gelu_f(tacc[nt][1] + bby);
                tacc[nt][2] = gelu_f(tacc[nt][2] + bbx);
                tacc[nt][3] = gelu_f(tacc[nt][3] + bby);
            }

            float s0 = 0.f, s1 = 0.f;
#pragma unroll
            for (int nt = 0; nt < 8; nt++) { s0 += tacc[nt][0] + tacc[nt][1]; s1 += tacc[nt][2] + tacc[nt][3]; }
            s0 += __shfl_xor_sync(0xffffffffu, s0, 1); s0 += __shfl_xor_sync(0xffffffffu, s0, 2);
            s1 += __shfl_xor_sync(0xffffffffu, s1, 1); s1 += __shfl_xor_sync(0xffffffffu, s1, 2);
            float mu0 = s0 * (1.0f / 64.0f), mu1 = s1 * (1.0f / 64.0f);
            float v0 = 0.f, v1 = 0.f;
#pragma unroll
            for (int nt = 0; nt < 8; nt++) {
                float d0 = tacc[nt][0] - mu0, d1 = tacc[nt][1] - mu0;
                float d2 = tacc[nt][2] - mu1, d3 = tacc[nt][3] - mu1;
                v0 += d0 * d0 + d1 * d1; v1 += d2 * d2 + d3 * d3;
            }
            v0 += __shfl_xor_sync(0xffffffffu, v0, 1); v0 += __shfl_xor_sync(0xffffffffu, v0, 2);
            v1 += __shfl_xor_sync(0xffffffffu, v1, 1); v1 += __shfl_xor_sync(0xffffffffu, v1, 2);
            float inv0 = rsqrtf(v0 * (1.0f / 64.0f) + 1e-5f);
            float inv1 = rsqrtf(v1 * (1.0f / 64.0f) + 1e-5f);

            int grow0 = m0 + p * 64 + (wid << 3) + (g >> 1);
            int grow1 = grow0 + 4;
            int bs = (n0 >> 6) + (g & 1);

            size_t ob0, ob1;
            float* dst;
            if (layer == 0) {
                dst = g_Y;
                ob0 = (size_t)grow0 * GDCOL + (size_t)bs * 64;
                ob1 = (size_t)grow1 * GDCOL + (size_t)bs * 64;
            } else {
                dst = g_flat;
                ob0 = (size_t)bs * KIN + (size_t)grow0 * 64;
                ob1 = (size_t)bs * KIN + (size_t)grow1 * 64;
            }

#pragma unroll
            for (int nt = 0; nt < 8; nt++) {
                int c = nt * 8 + 2 * tig;
                float o0x = (tacc[nt][0] - mu0) * inv0 * sg[c]     + sbe[c];
                float o0y = (tacc[nt][1] - mu0) * inv0 * sg[c + 1] + sbe[c + 1];
                float o1x = (tacc[nt][2] - mu1) * inv1 * sg[c]     + sbe[c];
                float o1y = (tacc[nt][3] - mu1) * inv1 * sg[c + 1] + sbe[c + 1];
                if (grow0 < NN) *(float2*)&dst[ob0 + c] = make_float2(o0x, o0y);
                if (grow1 < NN) *(float2*)&dst[ob1 + c] = make_float2(o1x, o1y);
                if (layer == 0) {
                    // pair partner (row ^1) lives at lane^8; pack (even,odd)
                    float q0x = __shfl_xor_sync(0xffffffffu, o0x, 8);
                    float q0y = __shfl_xor_sync(0xffffffffu, o0y, 8);
                    float q1x = __shfl_xor_sync(0xffffffffu, o1x, 8);
                    float q1y = __shfl_xor_sync(0xffffffffu, o1y, 8);
                    if ((g & 2) == 0) {
                        uint32_t ph0, pl0, ph1, pl1;
                        if (grow0 < NN) {
                            split2_bf16(o0x, q0x, ph0, pl0);
                            split2_bf16(o0y, q0y, ph1, pl1);
                            size_t pi = (size_t)(grow0 >> 1) * GDCOL + (size_t)bs * 64 + c;
                            *(uint2*)&g_Yp_h[pi] = make_uint2(ph0, ph1);
                            *(uint2*)&g_Yp_l[pi] = make_uint2(pl0, pl1);
                        }
                        if (grow1 < NN) {   // FIX: independent guard — pad pairs stay zero
                            split2_bf16(o1x, q1x, ph0, pl0);
                            split2_bf16(o1y, q1y, ph1, pl1);
                            size_t pj = (size_t)(grow1 >> 1) * GDCOL + (size_t)bs * 64 + c;
                            *(uint2*)&g_Yp_h[pj] = make_uint2(ph0, ph1);
                            *(uint2*)&g_Yp_l[pj] = make_uint2(pl0, pl1);
                        }
                    }
                }
            }
        }
        __syncthreads();
    }
}

// =====================================================================
// 5) GRU input projection — bf16 3-split, double-buffered, split-K (unchanged)
// =====================================================================
__global__ __launch_bounds__(256) void k_xp_tc(
    const float* __restrict__ W, int T, int Mtot, int sel)
{
    __shared__ uint32_t PAh[2][8][72], PAl[2][8][72];
    __shared__ uint32_t PBh[2][8][72], PBl[2][8][72];
    float* part = (sel == 0) ? g_part_l : (sel == 1) ? g_part_m : g_part_s;

    int tid = threadIdx.x;
    int m0 = blockIdx.x * 64;
    int n0 = blockIdx.y * 64;
    int z  = blockIdx.z;
    int kbase = z * KCH_L;

    int wid = tid >> 5, lane = tid & 31;
    int g = lane >> 2, tig = lane & 3;
    int wm = (wid & 3) * 16, wn = (wid >> 2) * 32;

    int a_r = tid >> 2, a_k = (tid & 3) * 4;
    int b_g = tid >> 2, b_k = (tid & 3) * 4;

    int r = m0 + a_r;
    bool a_valid = (r < Mtot);
    const float* aptr = g_flat;
    if (a_valid) {
        int bb = r / T, tt = r - bb * T;
        int frow = bb * S_ + (S_ - T) + tt;
        aptr = g_flat + (size_t)frow * KIN;
    }
    const float* bptr = W + (size_t)(n0 + b_g) * KIN;

    float acc[4][4];
#pragma unroll
    for (int nt = 0; nt < 4; nt++)
#pragma unroll
        for (int c = 0; c < 4; c++) acc[nt][c] = 0.f;

    const int NT = KCH_L / 16;    // 80
    float4 aReg = a_valid ? *(const float4*)(aptr + kbase + a_k) : make_float4(0.f, 0.f, 0.f, 0.f);
    float4 bReg = *(const float4*)(bptr + kbase + b_k);

    {
        uint32_t ph, pl;
        int ak2 = a_k >> 1, bk2 = b_k >> 1;
        split2_bf16(aReg.x, aReg.y, ph, pl); PAh[0][ak2 + 0][a_r] = ph; PAl[0][ak2 + 0][a_r] = pl;
        split2_bf16(aReg.z, aReg.w, ph, pl); PAh[0][ak2 + 1][a_r] = ph; PAl[0][ak2 + 1][a_r] = pl;
        split2_bf16(bReg.x, bReg.y, ph, pl); PBh[0][bk2 + 0][b_g] = ph; PBl[0][bk2 + 0][b_g] = pl;
        split2_bf16(bReg.z, bReg.w, ph, pl); PBh[0][bk2 + 1][b_g] = ph; PBl[0][bk2 + 1][b_g] = pl;
    }
    __syncthreads();

    for (int kt = 0; kt < NT; kt++) {
        bool more = (kt + 1 < NT);
        int cur = kt & 1, nxt = cur ^ 1;

        if (more) {
            int k0 = kbase + (kt + 1) * 16;
            aReg = a_valid ? *(const float4*)(aptr + k0 + a_k) : make_float4(0.f, 0.f, 0.f, 0.f);
            bReg = *(const float4*)(bptr + k0 + b_k);
        }

        {
            uint32_t ah[4], al[4];
            int mrow = wm + g;
            ah[0] = PAh[cur][tig][mrow];     ah[1] = PAh[cur][tig][mrow + 8];
            ah[2] = PAh[cur][tig + 4][mrow]; ah[3] = PAh[cur][tig + 4][mrow + 8];
            al[0] = PAl[cur][tig][mrow];     al[1] = PAl[cur][tig][mrow + 8];
            al[2] = PAl[cur][tig + 4][mrow]; al[3] = PAl[cur][tig + 4][mrow + 8];
#pragma unroll
            for (int nt = 0; nt < 4; nt++) {
                int ncol = wn + nt * 8 + g;
                uint32_t bh[2], bl[2];
                bh[0] = PBh[cur][tig][ncol]; bh[1] = PBh[cur][tig + 4][ncol];
                bl[0] = PBl[cur][tig][ncol]; bl[1] = PBl[cur][tig + 4][ncol];
                mma_bf16(acc[nt], ah, bh);
                mma_bf16(acc[nt], ah, bl);
                mma_bf16(acc[nt], al, bh);
            }
        }

        if (more) {
            uint32_t ph, pl;
            int ak2 = a_k >> 1, bk2 = b_k >> 1;
            split2_bf16(aReg.x, aReg.y, ph, pl); PAh[nxt][ak2 + 0][a_r] = ph; PAl[nxt][ak2 + 0][a_r] = pl;
            split2_bf16(aReg.z, aReg.w, ph, pl); PAh[nxt][ak2 + 1][a_r] = ph; PAl[nxt][ak2 + 1][a_r] = pl;
            split2_bf16(bReg.x, bReg.y, ph, pl); PBh[nxt][bk2 + 0][b_g] = ph; PBl[nxt][bk2 + 0][b_g] = pl;
            split2_bf16(bReg.z, bReg.w, ph, pl); PBh[nxt][bk2 + 1][b_g] = ph; PBl[nxt][bk2 + 1][b_g] = pl;
        }
        __syncthreads();
    }

    int row0 = m0 + wm + g, row1 = row0 + 8;
#pragma unroll
    for (int nt = 0; nt < 4; nt++) {
        int gate = n0 + wn + nt * 8 + 2 * tig;
        if (row0 < Mtot)
            *(float2*)&part[((size_t)z * Mtot + row0) * I3D + gate] =
                make_float2(acc[nt][0], acc[nt][1]);
        if (row1 < Mtot)
            *(float2*)&part[((size_t)z * Mtot + row1) * I3D + gate] =
                make_float2(acc[nt][2], acc[nt][3]);
    }
}

__global__ void k_xp_reduce(const float* __restrict__ bih, int Mtot, int sel)
{
    const float* part = (sel == 0) ? g_part_l : (sel == 1) ? g_part_m : g_part_s;
    float* out = (sel == 0) ? g_xp_l : (sel == 1) ? g_xp_m : g_xp_s;
    int i = blockIdx.x * 256 + threadIdx.x;
    int tot = Mtot * I3D;
    if (i >= tot) return;
    int g = i % I3D;
    float s = bih[g];
    for (int z = 0; z < SPLITK; z++) s += part[(size_t)z * tot + i];
    out[i] = s;
}

// =====================================================================
// 6) GRU recurrence — unchanged
// =====================================================================
__global__ __launch_bounds__(192) void k_gru(
    const float* __restrict__ Whh_s, const float* __restrict__ bhh_s,
    const float* __restrict__ Whh_m, const float* __restrict__ bhh_m,
    const float* __restrict__ Whh_l, const float* __restrict__ bhh_l)
{
    int blk = blockIdx.x;
    int gru = blk >> 2;
    int b = blk & 3;
    int T = (gru == 0) ? 10 : (gru == 1) ? 20 : 256;
    const float* xp  = (gru == 0) ? g_xp_s : (gru == 1) ? g_xp_m : g_xp_l;
    const float* Whh = (gru == 0) ? Whh_s : (gru == 1) ? Whh_m : Whh_l;
    const float* bhh = (gru == 0) ? bhh_s : (gru == 1) ? bhh_m : bhh_l;
    int g = threadIdx.x;

    float w[64];
#pragma unroll
    for (int d = 0; d < 64; d += 4) {
        float4 v = *(const float4*)&Whh[g * 64 + d];
        w[d] = v.x; w[d + 1] = v.y; w[d + 2] = v.z; w[d + 3] = v.w;
    }
    float bh = bhh[g];

    __shared__ float h_sh[64], r_sh[64], z_sh[64], n_sh[64];
    if (g < 64) h_sh[g] = 0.f;
    __syncthreads();

    const float* xpb = xp + (size_t)b * T * I3D;
    for (int t = 0; t < T; t++) {
        float a0 = 0.f, a1 = 0.f, a2 = 0.f, a3 = 0.f;
#pragma unroll
        for (int d = 0; d < 64; d += 4) {
            a0 += w[d]     * h_sh[d];
            a1 += w[d + 1] * h_sh[d + 1];
            a2 += w[d + 2] * h_sh[d + 2];
            a3 += w[d + 3] * h_sh[d + 3];
        }
        float gh = bh + ((a0 + a1) + (a2 + a3));
        float xv = xpb[t * I3D + g];
        if (g < 64) {
            r_sh[g] = sigm_f(xv + gh);
        } else if (g < 128) {
            z_sh[g - 64] = sigm_f(xv + gh);
        }
        __syncthreads();
        if (g >= 128) {
            n_sh[g - 128] = tanhf(xv + r_sh[g - 128] * gh);
        }
        __syncthreads();
        if (g < 64) {
            float zz = z_sh[g], nn = n_sh[g];
            h_sh[g] = (1.f - zz) * nn + zz * h_sh[g];
        }
        __syncthreads();
    }
    if (g < 64) g_hcat[b * I3D + gru * 64 + g] = h_sh[g];
}

// =====================================================================
// 7) head — unchanged
// =====================================================================
__global__ __launch_bounds__(256) void k_head(
    const float* __restrict__ W1, const float* __restrict__ b1,
    const float* __restrict__ W2, const float* __restrict__ b2,
    float* __restrict__ out)
{
    __shared__ float hc[4 * I3D];
    __shared__ float h1[4 * 64];
    int t = threadIdx.x;
    for (int i = t; i < 4 * I3D; i += 256) hc[i] = g_hcat[i];
    __syncthreads();
    {
        int b = t >> 6, e = t & 63;
        float a = b1[e];
#pragma unroll 8
        for (int gg = 0; gg < I3D; gg++) a += hc[b * I3D + gg] * W1[e * I3D + gg];
        h1[b * 64 + e] = gelu_f(a);
    }
    __syncthreads();
    for (int q = t; q < 4 * NN; q += 256) {
        int b = q / NN, n = q - b * NN;
        float a = b2[n];
#pragma unroll 8
        for (int e = 0; e < 64; e++) a += h1[b * 64 + e] * W2[n * 64 + e];
        out[b * NN + n] = a;
    }
}

// =====================================================================
// launcher
// =====================================================================
extern "C" void kernel_launch(void* const* d_in, const int* in_sizes, int n_in,
                              void* d_out, int out_size)
{
    const float* x     = (const float*)d_in[0];
    const float* ipW   = (const float*)d_in[1];
    const float* ipb   = (const float*)d_in[2];
    const float* fe    = (const float*)d_in[3];
    const float* te    = (const float*)d_in[4];
    const float* glW   = (const float*)d_in[5];
    const float* glb   = (const float*)d_in[6];
    const float* glg   = (const float*)d_in[7];
    const float* glbe  = (const float*)d_in[8];
    const float* Wih_s = (const float*)d_in[9];
    const float* Whh_s = (const float*)d_in[10];
    const float* bih_s = (const float*)d_in[11];
    const float* bhh_s = (const float*)d_in[12];
    const float* Wih_m = (const float*)d_in[13];
    const float* Whh_m = (const float*)d_in[14];
    const float* bih_m = (const float*)d_in[15];
    const float* bhh_m = (const float*)d_in[16];
    const float* Wih_l = (const float*)d_in[17];
    const float* Whh_l = (const float*)d_in[18];
    const float* bih_l = (const float*)d_in[19];
    const float* bhh_l = (const float*)d_in[20];
    const float* dhW1  = (const float*)d_in[21];
    const float* dhb1  = (const float*)d_in[22];
    const float* dhW2  = (const float*)d_in[23];
    const float* dhb2  = (const float*)d_in[24];
    float* out = (float*)d_out;

    const int FUSED_SMEM = 17216 * 4;   // 68864 bytes
    cudaFuncSetAttribute(k_agg_token_tc,
                         cudaFuncAttributeMaxDynamicSharedMemorySize, FUSED_SMEM);

    k_input_proj<<<2000, 256>>>(x, ipW, ipb);
    k_adj<<<NN, 256>>>(fe, te);
    k_packA<<<512, 256>>>();

    // layer 0: src g_Xp -> dst g_Y + g_Yp
    k_agg_token_tc<<<dim3(4, GDCOL / 128), 256, FUSED_SMEM>>>(glW, glb, glg, glbe, 0);
    // layer 1: src g_Yp -> dst g_flat
    k_agg_token_tc<<<dim3(4, GDCOL / 128), 256, FUSED_SMEM>>>(glW + 4096, glb + 64, glg + 64, glbe + 64, 1);

    // GRU input projections (split-K, bf16 tensor cores)
    k_xp_tc<<<dim3(16, 3, SPLITK), 256>>>(Wih_l, 256, 1024, 0);
    k_xp_tc<<<dim3(2, 3, SPLITK), 256>>>(Wih_m, 20, 80, 1);
    k_xp_tc<<<dim3(1, 3, SPLITK), 256>>>(Wih_s, 10, 40, 2);
    k_xp_reduce<<<(1024 * I3D + 255) / 256, 256>>>(bih_l, 1024, 0);
    k_xp_reduce<<<(80 * I3D + 255) / 256, 256>>>(bih_m, 80, 1);
    k_xp_reduce<<<(40 * I3D + 255) / 256, 256>>>(bih_s, 40, 2);

    k_gru<<<12, 192>>>(Whh_s, bhh_s, Whh_m, bhh_m, Whh_l, bhh_l);
    k_head<<<1, 256>>>(dhW1, dhb1, dhW2, dhb2, out);
}